// round 1
// baseline (speedup 1.0000x reference)
#include <cuda_runtime.h>
#include <cuda_bf16.h>
#include <math.h>

// Problem constants
#define BB 2
#define NN 1569          // tokens incl cls
#define CC 768
#define HH 12
#define DD 64
#define PP 196
#define FF 8
#define SS 1568          // F*P
#define C3 2304          // 3*C
#define SCALE 0.125f

// ---------------- device scratch (no allocations allowed) ----------------
__device__ float g_qkv[(size_t)BB * NN * C3];          // (B*N, 3C)
__device__ float g_traj[(size_t)BB * SS * FF * CC];    // (B,S,F,C)
__device__ float g_xdiag[(size_t)BB * SS * CC];        // (B*S, C)
__device__ float g_q2[(size_t)BB * SS * CC];           // (B*S, C)
__device__ float g_k2[(size_t)BB * SS * FF * CC];      // (B*S*F, C)
__device__ float g_Y[(size_t)BB * NN * CC];            // (B*N, C) concat[cls,out]

// ---------------- generic tiled SGEMM: C = A(MxK) @ B(KxN) [+bias] --------
// BM=BN=64, BK=16, 256 threads, 4x4 per thread. N%64==0, K%16==0, M guarded.
__global__ void sgemm_kernel(const float* __restrict__ A, const float* __restrict__ B,
                             float* __restrict__ C, int M, int N, int K,
                             int lda, int ldb, int ldc,
                             const float* __restrict__ bias)
{
    __shared__ float As[16][68];
    __shared__ float Bs[16][64];
    const int tid = threadIdx.x;
    const int by = blockIdx.y * 64;
    const int bx = blockIdx.x * 64;
    const int tr = (tid / 16) * 4;
    const int tc = (tid % 16) * 4;

    const int arow = tid >> 2;         // 0..63
    const int acol = (tid & 3) * 4;    // 0,4,8,12
    const int brow = tid >> 4;         // 0..15
    const int bcol = (tid & 15) * 4;   // 0..60

    float acc[4][4] = {};

    for (int k0 = 0; k0 < K; k0 += 16) {
        float4 av = make_float4(0.f, 0.f, 0.f, 0.f);
        int gr = by + arow;
        if (gr < M) av = *(const float4*)(A + (size_t)gr * lda + k0 + acol);
        As[acol + 0][arow] = av.x;
        As[acol + 1][arow] = av.y;
        As[acol + 2][arow] = av.z;
        As[acol + 3][arow] = av.w;

        float4 bv = *(const float4*)(B + (size_t)(k0 + brow) * ldb + bx + bcol);
        *(float4*)&Bs[brow][bcol] = bv;
        __syncthreads();

        #pragma unroll
        for (int kk = 0; kk < 16; kk++) {
            float4 a4 = *(const float4*)&As[kk][tr];
            float4 b4 = *(const float4*)&Bs[kk][tc];
            acc[0][0] += a4.x * b4.x; acc[0][1] += a4.x * b4.y; acc[0][2] += a4.x * b4.z; acc[0][3] += a4.x * b4.w;
            acc[1][0] += a4.y * b4.x; acc[1][1] += a4.y * b4.y; acc[1][2] += a4.y * b4.z; acc[1][3] += a4.y * b4.w;
            acc[2][0] += a4.z * b4.x; acc[2][1] += a4.z * b4.y; acc[2][2] += a4.z * b4.z; acc[2][3] += a4.z * b4.w;
            acc[3][0] += a4.w * b4.x; acc[3][1] += a4.w * b4.y; acc[3][2] += a4.w * b4.z; acc[3][3] += a4.w * b4.w;
        }
        __syncthreads();
    }

    float4 bb = make_float4(0.f, 0.f, 0.f, 0.f);
    if (bias) bb = *(const float4*)(bias + bx + tc);
    #pragma unroll
    for (int i = 0; i < 4; i++) {
        int gr = by + tr + i;
        if (gr < M) {
            float4 o;
            o.x = acc[i][0] + bb.x;
            o.y = acc[i][1] + bb.y;
            o.z = acc[i][2] + bb.z;
            o.w = acc[i][3] + bb.w;
            *(float4*)(C + (size_t)gr * ldc + bx + tc) = o;
        }
    }
}

// ---------------- cls attention: 24 blocks (b,h) ----------------
__global__ void cls_attn_kernel(const float* __restrict__ qkv, float* __restrict__ Y)
{
    const int b = blockIdx.x / HH;
    const int h = blockIdx.x % HH;
    const int tid = threadIdx.x;

    __shared__ float qs[DD];
    __shared__ float sc[NN];
    __shared__ float red[256];
    __shared__ float part4[4][DD];

    if (tid < DD) qs[tid] = qkv[(size_t)(b * NN) * C3 + h * DD + tid];
    __syncthreads();

    for (int i = tid; i < NN; i += 256) {
        const float* kr = qkv + (size_t)(b * NN + i) * C3 + CC + h * DD;
        float dot = 0.f;
        for (int d = 0; d < DD; d += 4) {
            float4 k4 = *(const float4*)(kr + d);
            dot += qs[d] * k4.x + qs[d + 1] * k4.y + qs[d + 2] * k4.z + qs[d + 3] * k4.w;
        }
        sc[i] = dot * SCALE;
    }
    __syncthreads();

    float m = -1e30f;
    for (int i = tid; i < NN; i += 256) m = fmaxf(m, sc[i]);
    red[tid] = m; __syncthreads();
    for (int o = 128; o; o >>= 1) { if (tid < o) red[tid] = fmaxf(red[tid], red[tid + o]); __syncthreads(); }
    m = red[0];
    __syncthreads();

    float z = 0.f;
    for (int i = tid; i < NN; i += 256) { float e = __expf(sc[i] - m); sc[i] = e; z += e; }
    red[tid] = z; __syncthreads();
    for (int o = 128; o; o >>= 1) { if (tid < o) red[tid] += red[tid + o]; __syncthreads(); }
    float inv = 1.f / red[0];
    __syncthreads();

    int d = tid & 63, part = tid >> 6;
    float acc = 0.f;
    for (int i = part; i < NN; i += 4)
        acc += sc[i] * qkv[(size_t)(b * NN + i) * C3 + 2 * CC + h * DD + d];
    part4[part][d] = acc;
    __syncthreads();
    if (tid < DD)
        Y[(size_t)(b * NN) * CC + h * DD + tid] =
            (part4[0][tid] + part4[1][tid] + part4[2][tid] + part4[3][tid]) * inv;
}

// ---------------- space attention -> traj (B,S,F,C). grid = 24*196 -------
__global__ void space_attn_kernel(const float* __restrict__ qkv, float* __restrict__ traj)
{
    const int bh = blockIdx.x / PP;
    const int st = blockIdx.x % PP;
    const int b = bh / HH;
    const int h = bh % HH;
    const int s0 = st * 8;
    const int tid = threadIdx.x;

    __shared__ float qs[8][DD];
    __shared__ float sc[8][PP];
    __shared__ float part4[4][8][DD];

    for (int idx = tid; idx < 8 * DD; idx += 256) {
        int q = idx >> 6, d = idx & 63;
        qs[q][d] = qkv[(size_t)(b * NN + 1 + s0 + q) * C3 + h * DD + d];
    }
    __syncthreads();

    for (int f = 0; f < FF; f++) {
        if (tid < PP) {
            const float* kr = qkv + (size_t)(b * NN + 1 + f * PP + tid) * C3 + CC + h * DD;
            float acc[8] = {};
            #pragma unroll
            for (int d4 = 0; d4 < 16; d4++) {
                float4 k4 = *(const float4*)(kr + d4 * 4);
                #pragma unroll
                for (int q = 0; q < 8; q++) {
                    float4 q4 = *(const float4*)&qs[q][d4 * 4];
                    acc[q] += q4.x * k4.x + q4.y * k4.y + q4.z * k4.z + q4.w * k4.w;
                }
            }
            #pragma unroll
            for (int q = 0; q < 8; q++) sc[q][tid] = acc[q] * SCALE;
        }
        __syncthreads();

        // softmax: one warp per query
        {
            int q = tid >> 5, lane = tid & 31;
            float m = -1e30f;
            for (int n = lane; n < PP; n += 32) m = fmaxf(m, sc[q][n]);
            for (int o = 16; o; o >>= 1) m = fmaxf(m, __shfl_xor_sync(0xffffffffu, m, o));
            float z = 0.f;
            for (int n = lane; n < PP; n += 32) { float e = __expf(sc[q][n] - m); sc[q][n] = e; z += e; }
            for (int o = 16; o; o >>= 1) z += __shfl_xor_sync(0xffffffffu, z, o);
            float inv = 1.f / z;
            for (int n = lane; n < PP; n += 32) sc[q][n] *= inv;
        }
        __syncthreads();

        // P @ V
        int d = tid & 63, part = tid >> 6;
        float facc[8] = {};
        for (int n = part; n < PP; n += 4) {
            float v = qkv[(size_t)(b * NN + 1 + f * PP + n) * C3 + 2 * CC + h * DD + d];
            #pragma unroll
            for (int q = 0; q < 8; q++) facc[q] += sc[q][n] * v;
        }
        #pragma unroll
        for (int q = 0; q < 8; q++) part4[part][q][d] = facc[q];
        __syncthreads();

        for (int idx = tid; idx < 8 * DD; idx += 256) {
            int q = idx >> 6, d2 = idx & 63;
            float o = part4[0][q][d2] + part4[1][q][d2] + part4[2][q][d2] + part4[3][q][d2];
            traj[((size_t)(b * SS + s0 + q) * FF + f) * CC + h * DD + d2] = o;
        }
        __syncthreads();
    }
}

// ---------------- x_diag gather ----------------
__global__ void gather_xdiag_kernel(const float* __restrict__ traj, float* __restrict__ xd)
{
    size_t idx = (size_t)blockIdx.x * 256 + threadIdx.x;
    if (idx >= (size_t)BB * SS * CC) return;
    int c = idx % CC;
    int bs = idx / CC;
    int s = bs % SS;
    xd[idx] = traj[((size_t)bs * FF + (s / PP)) * CC + c];
}

// ---------------- frame attention + attn output + Y rows. grid = B*S -----
__global__ void frame_attn_kernel(const float* __restrict__ q2, const float* __restrict__ k2,
                                  const float* __restrict__ traj, float* __restrict__ Y,
                                  float* __restrict__ attn_out)
{
    const int bs = blockIdx.x;
    const int b = bs / SS;
    const int s = bs % SS;
    const int tid = threadIdx.x;
    __shared__ float a[HH][FF];

    if (tid < HH * FF) {
        int h = tid >> 3, f = tid & 7;
        const float* qr = q2 + (size_t)bs * CC + h * DD;
        const float* kr = k2 + ((size_t)bs * FF + f) * CC + h * DD;
        float dot = 0.f;
        for (int d = 0; d < DD; d += 4) {
            float4 a4 = *(const float4*)(qr + d);
            float4 b4 = *(const float4*)(kr + d);
            dot += a4.x * b4.x + a4.y * b4.y + a4.z * b4.z + a4.w * b4.w;
        }
        a[h][f] = dot * SCALE;
    }
    __syncthreads();
    if (tid < HH) {
        int h = tid;
        float m = -1e30f;
        #pragma unroll
        for (int f = 0; f < FF; f++) m = fmaxf(m, a[h][f]);
        float z = 0.f;
        #pragma unroll
        for (int f = 0; f < FF; f++) { float e = __expf(a[h][f] - m); a[h][f] = e; z += e; }
        float inv = 1.f / z;
        #pragma unroll
        for (int f = 0; f < FF; f++) a[h][f] *= inv;
    }
    __syncthreads();
    if (tid < HH * FF) {
        int h = tid >> 3, f = tid & 7;
        attn_out[(((size_t)b * HH + h) * SS + s) * FF + f] = a[h][f];
    }
    for (int c = tid; c < CC; c += 256) {
        int h = c >> 6;
        float o = 0.f;
        #pragma unroll
        for (int f = 0; f < FF; f++)
            o += a[h][f] * traj[((size_t)bs * FF + f) * CC + c];
        Y[(size_t)(b * NN + 1 + s) * CC + c] = o;
    }
}

// ---------------- launcher ----------------
extern "C" void kernel_launch(void* const* d_in, const int* in_sizes, int n_in,
                              void* d_out, int out_size)
{
    const float* x      = (const float*)d_in[0];
    const float* W_qkv  = (const float*)d_in[1];
    const float* W_pq   = (const float*)d_in[2];
    const float* W_pkv  = (const float*)d_in[3];
    const float* W_proj = (const float*)d_in[4];
    const float* b_proj = (const float*)d_in[5];
    (void)in_sizes; (void)n_in;

    float *qkv, *traj, *xdiag, *q2, *k2, *Y;
    cudaGetSymbolAddress((void**)&qkv,   g_qkv);
    cudaGetSymbolAddress((void**)&traj,  g_traj);
    cudaGetSymbolAddress((void**)&xdiag, g_xdiag);
    cudaGetSymbolAddress((void**)&q2,    g_q2);
    cudaGetSymbolAddress((void**)&k2,    g_k2);
    cudaGetSymbolAddress((void**)&Y,     g_Y);

    float* out_main = (float*)d_out;                                   // (B,N,C)
    float* out_attn = out_main + (size_t)BB * NN * CC;                 // (B,h,S,F)

    const int M1 = BB * NN;   // 3138

    // 1) qkv = x @ W_qkv
    {
        dim3 grid(C3 / 64, (M1 + 63) / 64);
        sgemm_kernel<<<grid, 256>>>(x, W_qkv, qkv, M1, C3, CC, CC, C3, C3, nullptr);
    }
    // 2) cls attention -> Y row 0 per batch
    cls_attn_kernel<<<BB * HH, 256>>>(qkv, Y);
    // 3) space attention -> traj
    space_attn_kernel<<<BB * HH * PP, 256>>>(qkv, traj);
    // 4) x_diag gather + q2 GEMM
    {
        size_t tot = (size_t)BB * SS * CC;
        gather_xdiag_kernel<<<(int)((tot + 255) / 256), 256>>>(traj, xdiag);
        dim3 grid(CC / 64, (BB * SS) / 64);
        sgemm_kernel<<<grid, 256>>>(xdiag, W_pq, q2, BB * SS, CC, CC, CC, CC, CC, nullptr);
    }
    // 5) k2 = traj @ W_pkv[:, :CC]   (v2 is dead in the reference)
    {
        int M = BB * SS * FF;  // 25088
        dim3 grid(CC / 64, M / 64);
        sgemm_kernel<<<grid, 256>>>(traj, W_pkv, k2, M, CC, CC, CC, 2 * CC, CC, nullptr);
    }
    // 6) frame attention -> attn output + Y rows 1..S
    frame_attn_kernel<<<BB * SS, 256>>>(q2, k2, traj, Y, out_attn);
    // 7) out = Y @ W_proj + b_proj
    {
        dim3 grid(CC / 64, (M1 + 63) / 64);
        sgemm_kernel<<<grid, 256>>>(Y, W_proj, out_main, M1, CC, CC, CC, CC, CC, b_proj);
    }
}

// round 2
// speedup vs baseline: 1.5571x; 1.5571x over previous
#include <cuda_runtime.h>
#include <cuda_bf16.h>
#include <math.h>
#include <stdint.h>

// Problem constants
#define BB 2
#define NN 1569          // tokens incl cls
#define CC 768
#define HH 12
#define DD 64
#define PP 196
#define FF 8
#define SS 1568          // F*P
#define C3 2304          // 3*C
#define SCALE 0.125f

// ---------------- device scratch (no allocations allowed) ----------------
__device__ float g_qkv[(size_t)BB * NN * C3];          // (B*N, 3C)
__device__ float g_traj[(size_t)BB * SS * FF * CC];    // (B,S,F,C)
__device__ float g_xdiag[(size_t)BB * SS * CC];        // (B*S, C)
__device__ float g_q2[(size_t)BB * SS * CC];           // (B*S, C)
__device__ float g_k2[(size_t)BB * SS * FF * CC];      // (B*S*F, C)
__device__ float g_Y[(size_t)BB * NN * CC];            // (B*N, C) concat[cls,out]

// ---------------- TF32 tensor-core GEMM ----------------
// C = A(MxK) @ B(KxN) [+bias].  BM=128, BN=64, BK=16, 256 threads (8 warps).
// Warp layout 4(M) x 2(N); warp tile 32x32 via 2x4 m16n8k8 fragments.
// Requires: N % 64 == 0, K % 16 == 0. M guarded.

#define GBM 128
#define GBN 64
#define GBK 16
#define AST 136   // As row stride: %32==8 -> conflict-free fragment LDS
#define BST 72    // Bs row stride: %32==8

__device__ __forceinline__ float to_tf32(float x) {
    uint32_t u;
    asm("cvt.rna.tf32.f32 %0, %1;" : "=r"(u) : "f"(x));
    return __uint_as_float(u);
}

__device__ __forceinline__ void mma_tf32(float (&c)[4], const uint32_t (&a)[4], const uint32_t (&b)[2]) {
    asm volatile(
        "mma.sync.aligned.m16n8k8.row.col.f32.tf32.tf32.f32 "
        "{%0,%1,%2,%3}, {%4,%5,%6,%7}, {%8,%9}, {%0,%1,%2,%3};"
        : "+f"(c[0]), "+f"(c[1]), "+f"(c[2]), "+f"(c[3])
        : "r"(a[0]), "r"(a[1]), "r"(a[2]), "r"(a[3]), "r"(b[0]), "r"(b[1]));
}

__global__ void tf32_gemm_kernel(const float* __restrict__ A, const float* __restrict__ B,
                                 float* __restrict__ C, int M, int N, int K,
                                 int lda, int ldb, int ldc,
                                 const float* __restrict__ bias)
{
    __shared__ float As[GBK][AST];   // k-major
    __shared__ float Bs[GBK][BST];   // k-major

    const int tid  = threadIdx.x;
    const int warp = tid >> 5;
    const int lane = tid & 31;
    const int g = lane >> 2;   // 0..7
    const int q = lane & 3;    // 0..3

    const int wm = warp & 3;           // 0..3 (M)
    const int wn = warp >> 2;          // 0..1 (N)
    const int warpM = wm * 32;
    const int warpN = wn * 32;

    const int by = blockIdx.y * GBM;
    const int bx = blockIdx.x * GBN;

    float acc[2][4][4];
    #pragma unroll
    for (int i = 0; i < 2; i++)
        #pragma unroll
        for (int j = 0; j < 4; j++)
            #pragma unroll
            for (int l = 0; l < 4; l++) acc[i][j][l] = 0.f;

    // A global-load mapping: idx -> row=idx>>2 (0..127), colgroup=(idx&3)*4
    const int a_row = tid >> 2;
    const int a_col = (tid & 3) << 2;
    // B: row = tid>>4 (0..15), col = (tid&15)*4
    const int b_row = tid >> 4;
    const int b_col = (tid & 15) << 2;

    for (int k0 = 0; k0 < K; k0 += GBK) {
        #pragma unroll
        for (int i = 0; i < 2; i++) {
            int row = a_row + i * 64;
            float4 av = make_float4(0.f, 0.f, 0.f, 0.f);
            int gr = by + row;
            if (gr < M) av = *(const float4*)(A + (size_t)gr * lda + k0 + a_col);
            As[a_col + 0][row] = to_tf32(av.x);
            As[a_col + 1][row] = to_tf32(av.y);
            As[a_col + 2][row] = to_tf32(av.z);
            As[a_col + 3][row] = to_tf32(av.w);
        }
        {
            float4 bv = *(const float4*)(B + (size_t)(k0 + b_row) * ldb + bx + b_col);
            Bs[b_row][b_col + 0] = to_tf32(bv.x);
            Bs[b_row][b_col + 1] = to_tf32(bv.y);
            Bs[b_row][b_col + 2] = to_tf32(bv.z);
            Bs[b_row][b_col + 3] = to_tf32(bv.w);
        }
        __syncthreads();

        #pragma unroll
        for (int kk = 0; kk < GBK; kk += 8) {
            uint32_t afr[2][4];
            #pragma unroll
            for (int mt = 0; mt < 2; mt++) {
                int r = warpM + mt * 16 + g;
                afr[mt][0] = __float_as_uint(As[kk + q][r]);
                afr[mt][1] = __float_as_uint(As[kk + q][r + 8]);
                afr[mt][2] = __float_as_uint(As[kk + q + 4][r]);
                afr[mt][3] = __float_as_uint(As[kk + q + 4][r + 8]);
            }
            uint32_t bfr[4][2];
            #pragma unroll
            for (int nt = 0; nt < 4; nt++) {
                int c = warpN + nt * 8 + g;
                bfr[nt][0] = __float_as_uint(Bs[kk + q][c]);
                bfr[nt][1] = __float_as_uint(Bs[kk + q + 4][c]);
            }
            #pragma unroll
            for (int mt = 0; mt < 2; mt++)
                #pragma unroll
                for (int nt = 0; nt < 4; nt++)
                    mma_tf32(acc[mt][nt], afr[mt], bfr[nt]);
        }
        __syncthreads();
    }

    // epilogue: c0: (g, 2q), c1: (g, 2q+1), c2: (g+8, 2q), c3: (g+8, 2q+1)
    #pragma unroll
    for (int mt = 0; mt < 2; mt++) {
        #pragma unroll
        for (int nt = 0; nt < 4; nt++) {
            int col = bx + warpN + nt * 8 + 2 * q;
            float bx0 = 0.f, bx1 = 0.f;
            if (bias) { bx0 = bias[col]; bx1 = bias[col + 1]; }
            int r0 = by + warpM + mt * 16 + g;
            if (r0 < M) {
                float2 o = make_float2(acc[mt][nt][0] + bx0, acc[mt][nt][1] + bx1);
                *(float2*)(C + (size_t)r0 * ldc + col) = o;
            }
            if (r0 + 8 < M) {
                float2 o = make_float2(acc[mt][nt][2] + bx0, acc[mt][nt][3] + bx1);
                *(float2*)(C + (size_t)(r0 + 8) * ldc + col) = o;
            }
        }
    }
}

// ---------------- cls attention: 24 blocks (b,h) ----------------
__global__ void cls_attn_kernel(const float* __restrict__ qkv, float* __restrict__ Y)
{
    const int b = blockIdx.x / HH;
    const int h = blockIdx.x % HH;
    const int tid = threadIdx.x;

    __shared__ float qs[DD];
    __shared__ float sc[NN];
    __shared__ float red[256];
    __shared__ float part4[4][DD];

    if (tid < DD) qs[tid] = qkv[(size_t)(b * NN) * C3 + h * DD + tid];
    __syncthreads();

    for (int i = tid; i < NN; i += 256) {
        const float* kr = qkv + (size_t)(b * NN + i) * C3 + CC + h * DD;
        float dot = 0.f;
        for (int d = 0; d < DD; d += 4) {
            float4 k4 = *(const float4*)(kr + d);
            dot += qs[d] * k4.x + qs[d + 1] * k4.y + qs[d + 2] * k4.z + qs[d + 3] * k4.w;
        }
        sc[i] = dot * SCALE;
    }
    __syncthreads();

    float m = -1e30f;
    for (int i = tid; i < NN; i += 256) m = fmaxf(m, sc[i]);
    red[tid] = m; __syncthreads();
    for (int o = 128; o; o >>= 1) { if (tid < o) red[tid] = fmaxf(red[tid], red[tid + o]); __syncthreads(); }
    m = red[0];
    __syncthreads();

    float z = 0.f;
    for (int i = tid; i < NN; i += 256) { float e = __expf(sc[i] - m); sc[i] = e; z += e; }
    red[tid] = z; __syncthreads();
    for (int o = 128; o; o >>= 1) { if (tid < o) red[tid] += red[tid + o]; __syncthreads(); }
    float inv = 1.f / red[0];
    __syncthreads();

    int d = tid & 63, part = tid >> 6;
    float acc = 0.f;
    for (int i = part; i < NN; i += 4)
        acc += sc[i] * qkv[(size_t)(b * NN + i) * C3 + 2 * CC + h * DD + d];
    part4[part][d] = acc;
    __syncthreads();
    if (tid < DD)
        Y[(size_t)(b * NN) * CC + h * DD + tid] =
            (part4[0][tid] + part4[1][tid] + part4[2][tid] + part4[3][tid]) * inv;
}

// ---------------- space attention -> traj. QTILE=16, grid = 24*98 -------
#define QT 16
__global__ void space_attn_kernel(const float* __restrict__ qkv, float* __restrict__ traj)
{
    const int nt = SS / QT;           // 98 tiles per (b,h)
    const int bh = blockIdx.x / nt;
    const int st = blockIdx.x % nt;
    const int b = bh / HH;
    const int h = bh % HH;
    const int s0 = st * QT;
    const int tid = threadIdx.x;
    const int warp = tid >> 5;
    const int lane = tid & 31;

    __shared__ float qs[QT][DD];
    __shared__ float sc[QT][PP];
    __shared__ float part4[4][QT][DD];

    for (int idx = tid; idx < QT * DD; idx += 256) {
        int qq = idx >> 6, d = idx & 63;
        qs[qq][d] = qkv[(size_t)(b * NN + 1 + s0 + qq) * C3 + h * DD + d];
    }
    __syncthreads();

    for (int f = 0; f < FF; f++) {
        if (tid < PP) {
            const float* kr = qkv + (size_t)(b * NN + 1 + f * PP + tid) * C3 + CC + h * DD;
            float acc[QT];
            #pragma unroll
            for (int qq = 0; qq < QT; qq++) acc[qq] = 0.f;
            #pragma unroll
            for (int d4 = 0; d4 < 16; d4++) {
                float4 k4 = *(const float4*)(kr + d4 * 4);
                #pragma unroll
                for (int qq = 0; qq < QT; qq++) {
                    float4 q4 = *(const float4*)&qs[qq][d4 * 4];
                    acc[qq] += q4.x * k4.x + q4.y * k4.y + q4.z * k4.z + q4.w * k4.w;
                }
            }
            #pragma unroll
            for (int qq = 0; qq < QT; qq++) sc[qq][tid] = acc[qq] * SCALE;
        }
        __syncthreads();

        // softmax: 8 warps, each handles 2 queries
        for (int qq = warp; qq < QT; qq += 8) {
            float m = -1e30f;
            for (int n = lane; n < PP; n += 32) m = fmaxf(m, sc[qq][n]);
            for (int o = 16; o; o >>= 1) m = fmaxf(m, __shfl_xor_sync(0xffffffffu, m, o));
            float z = 0.f;
            for (int n = lane; n < PP; n += 32) { float e = __expf(sc[qq][n] - m); sc[qq][n] = e; z += e; }
            for (int o = 16; o; o >>= 1) z += __shfl_xor_sync(0xffffffffu, z, o);
            float inv = 1.f / z;
            for (int n = lane; n < PP; n += 32) sc[qq][n] *= inv;
        }
        __syncthreads();

        // P @ V
        int d = tid & 63, part = tid >> 6;
        float facc[QT];
        #pragma unroll
        for (int qq = 0; qq < QT; qq++) facc[qq] = 0.f;
        for (int n = part; n < PP; n += 4) {
            float v = qkv[(size_t)(b * NN + 1 + f * PP + n) * C3 + 2 * CC + h * DD + d];
            #pragma unroll
            for (int qq = 0; qq < QT; qq++) facc[qq] += sc[qq][n] * v;
        }
        #pragma unroll
        for (int qq = 0; qq < QT; qq++) part4[part][qq][d] = facc[qq];
        __syncthreads();

        for (int idx = tid; idx < QT * DD; idx += 256) {
            int qq = idx >> 6, d2 = idx & 63;
            float o = part4[0][qq][d2] + part4[1][qq][d2] + part4[2][qq][d2] + part4[3][qq][d2];
            traj[((size_t)(b * SS + s0 + qq) * FF + f) * CC + h * DD + d2] = o;
        }
        __syncthreads();
    }
}

// ---------------- x_diag gather ----------------
__global__ void gather_xdiag_kernel(const float* __restrict__ traj, float* __restrict__ xd)
{
    size_t idx = (size_t)blockIdx.x * 256 + threadIdx.x;
    if (idx >= (size_t)BB * SS * CC) return;
    int c = idx % CC;
    int bs = idx / CC;
    int s = bs % SS;
    xd[idx] = traj[((size_t)bs * FF + (s / PP)) * CC + c];
}

// ---------------- frame attention + attn output + Y rows. grid = B*S -----
__global__ void frame_attn_kernel(const float* __restrict__ q2, const float* __restrict__ k2,
                                  const float* __restrict__ traj, float* __restrict__ Y,
                                  float* __restrict__ attn_out)
{
    const int bs = blockIdx.x;
    const int b = bs / SS;
    const int s = bs % SS;
    const int tid = threadIdx.x;
    __shared__ float a[HH][FF];

    if (tid < HH * FF) {
        int h = tid >> 3, f = tid & 7;
        const float* qr = q2 + (size_t)bs * CC + h * DD;
        const float* kr = k2 + ((size_t)bs * FF + f) * CC + h * DD;
        float dot = 0.f;
        for (int d = 0; d < DD; d += 4) {
            float4 a4 = *(const float4*)(qr + d);
            float4 b4 = *(const float4*)(kr + d);
            dot += a4.x * b4.x + a4.y * b4.y + a4.z * b4.z + a4.w * b4.w;
        }
        a[h][f] = dot * SCALE;
    }
    __syncthreads();
    if (tid < HH) {
        int h = tid;
        float m = -1e30f;
        #pragma unroll
        for (int f = 0; f < FF; f++) m = fmaxf(m, a[h][f]);
        float z = 0.f;
        #pragma unroll
        for (int f = 0; f < FF; f++) { float e = __expf(a[h][f] - m); a[h][f] = e; z += e; }
        float inv = 1.f / z;
        #pragma unroll
        for (int f = 0; f < FF; f++) a[h][f] *= inv;
    }
    __syncthreads();
    if (tid < HH * FF) {
        int h = tid >> 3, f = tid & 7;
        attn_out[(((size_t)b * HH + h) * SS + s) * FF + f] = a[h][f];
    }
    for (int c = tid; c < CC; c += 256) {
        int h = c >> 6;
        float o = 0.f;
        #pragma unroll
        for (int f = 0; f < FF; f++)
            o += a[h][f] * traj[((size_t)bs * FF + f) * CC + c];
        Y[(size_t)(b * NN + 1 + s) * CC + c] = o;
    }
}

// ---------------- launcher ----------------
extern "C" void kernel_launch(void* const* d_in, const int* in_sizes, int n_in,
                              void* d_out, int out_size)
{
    const float* x      = (const float*)d_in[0];
    const float* W_qkv  = (const float*)d_in[1];
    const float* W_pq   = (const float*)d_in[2];
    const float* W_pkv  = (const float*)d_in[3];
    const float* W_proj = (const float*)d_in[4];
    const float* b_proj = (const float*)d_in[5];
    (void)in_sizes; (void)n_in;

    float *qkv, *traj, *xdiag, *q2, *k2, *Y;
    cudaGetSymbolAddress((void**)&qkv,   g_qkv);
    cudaGetSymbolAddress((void**)&traj,  g_traj);
    cudaGetSymbolAddress((void**)&xdiag, g_xdiag);
    cudaGetSymbolAddress((void**)&q2,    g_q2);
    cudaGetSymbolAddress((void**)&k2,    g_k2);
    cudaGetSymbolAddress((void**)&Y,     g_Y);

    float* out_main = (float*)d_out;                                   // (B,N,C)
    float* out_attn = out_main + (size_t)BB * NN * CC;                 // (B,h,S,F)

    const int M1 = BB * NN;   // 3138

    // 1) qkv = x @ W_qkv
    {
        dim3 grid(C3 / GBN, (M1 + GBM - 1) / GBM);
        tf32_gemm_kernel<<<grid, 256>>>(x, W_qkv, qkv, M1, C3, CC, CC, C3, C3, nullptr);
    }
    // 2) cls attention -> Y row 0 per batch
    cls_attn_kernel<<<BB * HH, 256>>>(qkv, Y);
    // 3) space attention -> traj
    space_attn_kernel<<<BB * HH * (SS / QT), 256>>>(qkv, traj);
    // 4) x_diag gather + q2 GEMM
    {
        size_t tot = (size_t)BB * SS * CC;
        gather_xdiag_kernel<<<(int)((tot + 255) / 256), 256>>>(traj, xdiag);
        dim3 grid(CC / GBN, (BB * SS + GBM - 1) / GBM);
        tf32_gemm_kernel<<<grid, 256>>>(xdiag, W_pq, q2, BB * SS, CC, CC, CC, CC, CC, nullptr);
    }
    // 5) k2 = traj @ W_pkv[:, :CC]   (v2 is dead in the reference)
    {
        int M = BB * SS * FF;  // 25088
        dim3 grid(CC / GBN, (M + GBM - 1) / GBM);
        tf32_gemm_kernel<<<grid, 256>>>(traj, W_pkv, k2, M, CC, CC, CC, 2 * CC, CC, nullptr);
    }
    // 6) frame attention -> attn output + Y rows 1..S
    frame_attn_kernel<<<BB * SS, 256>>>(q2, k2, traj, Y, out_attn);
    // 7) out = Y @ W_proj + b_proj
    {
        dim3 grid(CC / GBN, (M1 + GBM - 1) / GBM);
        tf32_gemm_kernel<<<grid, 256>>>(Y, W_proj, out_main, M1, CC, CC, CC, CC, CC, b_proj);
    }
}

// round 4
// speedup vs baseline: 2.3982x; 1.5402x over previous
#include <cuda_runtime.h>
#include <cuda_bf16.h>
#include <math.h>
#include <stdint.h>

// Problem constants
#define BB 2
#define NN 1569          // tokens incl cls
#define CC 768
#define HH 12
#define DD 64
#define PP 196
#define FF 8
#define SS 1568          // F*P
#define C3 2304          // 3*C
#define SCALE 0.125f

// ---------------- device scratch (no allocations allowed) ----------------
__device__ float g_qkv[(size_t)BB * NN * C3];          // (B*N, 3C)
__device__ float g_traj[(size_t)BB * SS * FF * CC];    // (B,S,F,C)
__device__ float g_xdiag[(size_t)BB * SS * CC];        // (B*S, C)
__device__ float g_q2[(size_t)BB * SS * CC];           // (B*S, C)
__device__ float g_k2[(size_t)BB * SS * FF * CC];      // (B*S*F, C)
__device__ float g_Y[(size_t)BB * NN * CC];            // (B*N, C) concat[cls,out]

__device__ __forceinline__ float to_tf32(float x) {
    uint32_t u;
    asm("cvt.rna.tf32.f32 %0, %1;" : "=r"(u) : "f"(x));
    return __uint_as_float(u);
}

__device__ __forceinline__ void mma_tf32(float (&c)[4], const uint32_t (&a)[4], const uint32_t (&b)[2]) {
    asm volatile(
        "mma.sync.aligned.m16n8k8.row.col.f32.tf32.tf32.f32 "
        "{%0,%1,%2,%3}, {%4,%5,%6,%7}, {%8,%9}, {%0,%1,%2,%3};"
        : "+f"(c[0]), "+f"(c[1]), "+f"(c[2]), "+f"(c[3])
        : "r"(a[0]), "r"(a[1]), "r"(a[2]), "r"(a[3]), "r"(b[0]), "r"(b[1]));
}

// ---------------- TF32 tensor-core GEMM, double-buffered ----------------
// C = A(MxK) @ B(KxN) [+bias].  BM=128, BN=64, BK=16, 256 threads (8 warps).
#define GBM 128
#define GBN 64
#define GBK 16
#define AST 136
#define BST 72

__global__ void tf32_gemm_kernel(const float* __restrict__ A, const float* __restrict__ B,
                                 float* __restrict__ C, int M, int N, int K,
                                 int lda, int ldb, int ldc,
                                 const float* __restrict__ bias)
{
    __shared__ float As[2][GBK][AST];   // k-major
    __shared__ float Bs[2][GBK][BST];   // k-major

    const int tid  = threadIdx.x;
    const int warp = tid >> 5;
    const int lane = tid & 31;
    const int g = lane >> 2;
    const int q = lane & 3;

    const int wm = warp & 3;
    const int wn = warp >> 2;
    const int warpM = wm * 32;
    const int warpN = wn * 32;

    const int by = blockIdx.y * GBM;
    const int bx = blockIdx.x * GBN;

    float acc[2][4][4];
    #pragma unroll
    for (int i = 0; i < 2; i++)
        #pragma unroll
        for (int j = 0; j < 4; j++)
            #pragma unroll
            for (int l = 0; l < 4; l++) acc[i][j][l] = 0.f;

    const int a_row = tid >> 2;
    const int a_col = (tid & 3) << 2;
    const int b_row = tid >> 4;
    const int b_col = (tid & 15) << 2;

    float4 avP[2], bvP;
    // prologue: load tile 0
    #pragma unroll
    for (int i = 0; i < 2; i++) {
        int gr = by + a_row + i * 64;
        avP[i] = make_float4(0.f, 0.f, 0.f, 0.f);
        if (gr < M) avP[i] = *(const float4*)(A + (size_t)gr * lda + a_col);
    }
    bvP = *(const float4*)(B + (size_t)b_row * ldb + bx + b_col);
    {
        #pragma unroll
        for (int i = 0; i < 2; i++) {
            int row = a_row + i * 64;
            As[0][a_col + 0][row] = to_tf32(avP[i].x);
            As[0][a_col + 1][row] = to_tf32(avP[i].y);
            As[0][a_col + 2][row] = to_tf32(avP[i].z);
            As[0][a_col + 3][row] = to_tf32(avP[i].w);
        }
        Bs[0][b_row][b_col + 0] = to_tf32(bvP.x);
        Bs[0][b_row][b_col + 1] = to_tf32(bvP.y);
        Bs[0][b_row][b_col + 2] = to_tf32(bvP.z);
        Bs[0][b_row][b_col + 3] = to_tf32(bvP.w);
    }
    __syncthreads();

    int cur = 0;
    for (int k0 = 0; k0 < K; k0 += GBK) {
        const bool has_next = (k0 + GBK < K);
        if (has_next) {
            #pragma unroll
            for (int i = 0; i < 2; i++) {
                int gr = by + a_row + i * 64;
                avP[i] = make_float4(0.f, 0.f, 0.f, 0.f);
                if (gr < M) avP[i] = *(const float4*)(A + (size_t)gr * lda + k0 + GBK + a_col);
            }
            bvP = *(const float4*)(B + (size_t)(k0 + GBK + b_row) * ldb + bx + b_col);
        }

        #pragma unroll
        for (int kk = 0; kk < GBK; kk += 8) {
            uint32_t afr[2][4];
            #pragma unroll
            for (int mt = 0; mt < 2; mt++) {
                int r = warpM + mt * 16 + g;
                afr[mt][0] = __float_as_uint(As[cur][kk + q][r]);
                afr[mt][1] = __float_as_uint(As[cur][kk + q][r + 8]);
                afr[mt][2] = __float_as_uint(As[cur][kk + q + 4][r]);
                afr[mt][3] = __float_as_uint(As[cur][kk + q + 4][r + 8]);
            }
            uint32_t bfr[4][2];
            #pragma unroll
            for (int nt = 0; nt < 4; nt++) {
                int c = warpN + nt * 8 + g;
                bfr[nt][0] = __float_as_uint(Bs[cur][kk + q][c]);
                bfr[nt][1] = __float_as_uint(Bs[cur][kk + q + 4][c]);
            }
            #pragma unroll
            for (int mt = 0; mt < 2; mt++)
                #pragma unroll
                for (int nt = 0; nt < 4; nt++)
                    mma_tf32(acc[mt][nt], afr[mt], bfr[nt]);
        }

        if (has_next) {
            int nb = cur ^ 1;
            #pragma unroll
            for (int i = 0; i < 2; i++) {
                int row = a_row + i * 64;
                As[nb][a_col + 0][row] = to_tf32(avP[i].x);
                As[nb][a_col + 1][row] = to_tf32(avP[i].y);
                As[nb][a_col + 2][row] = to_tf32(avP[i].z);
                As[nb][a_col + 3][row] = to_tf32(avP[i].w);
            }
            Bs[nb][b_row][b_col + 0] = to_tf32(bvP.x);
            Bs[nb][b_row][b_col + 1] = to_tf32(bvP.y);
            Bs[nb][b_row][b_col + 2] = to_tf32(bvP.z);
            Bs[nb][b_row][b_col + 3] = to_tf32(bvP.w);
        }
        __syncthreads();
        cur ^= 1;
    }

    #pragma unroll
    for (int mt = 0; mt < 2; mt++) {
        #pragma unroll
        for (int nt = 0; nt < 4; nt++) {
            int col = bx + warpN + nt * 8 + 2 * q;
            float bx0 = 0.f, bx1 = 0.f;
            if (bias) { bx0 = bias[col]; bx1 = bias[col + 1]; }
            int r0 = by + warpM + mt * 16 + g;
            if (r0 < M) {
                float2 o = make_float2(acc[mt][nt][0] + bx0, acc[mt][nt][1] + bx1);
                *(float2*)(C + (size_t)r0 * ldc + col) = o;
            }
            if (r0 + 8 < M) {
                float2 o = make_float2(acc[mt][nt][2] + bx0, acc[mt][nt][3] + bx1);
                *(float2*)(C + (size_t)(r0 + 8) * ldc + col) = o;
            }
        }
    }
}

// ---------------- cls attention: 24 blocks (b,h) ----------------
__global__ void cls_attn_kernel(const float* __restrict__ qkv, float* __restrict__ Y)
{
    const int b = blockIdx.x / HH;
    const int h = blockIdx.x % HH;
    const int tid = threadIdx.x;

    __shared__ float qs[DD];
    __shared__ float sc[NN];
    __shared__ float red[256];
    __shared__ float part4[4][DD];

    if (tid < DD) qs[tid] = qkv[(size_t)(b * NN) * C3 + h * DD + tid];
    __syncthreads();

    for (int i = tid; i < NN; i += 256) {
        const float* kr = qkv + (size_t)(b * NN + i) * C3 + CC + h * DD;
        float dot = 0.f;
        for (int d = 0; d < DD; d += 4) {
            float4 k4 = *(const float4*)(kr + d);
            dot += qs[d] * k4.x + qs[d + 1] * k4.y + qs[d + 2] * k4.z + qs[d + 3] * k4.w;
        }
        sc[i] = dot * SCALE;
    }
    __syncthreads();

    float m = -1e30f;
    for (int i = tid; i < NN; i += 256) m = fmaxf(m, sc[i]);
    red[tid] = m; __syncthreads();
    for (int o = 128; o; o >>= 1) { if (tid < o) red[tid] = fmaxf(red[tid], red[tid + o]); __syncthreads(); }
    m = red[0];
    __syncthreads();

    float z = 0.f;
    for (int i = tid; i < NN; i += 256) { float e = __expf(sc[i] - m); sc[i] = e; z += e; }
    red[tid] = z; __syncthreads();
    for (int o = 128; o; o >>= 1) { if (tid < o) red[tid] += red[tid + o]; __syncthreads(); }
    float inv = 1.f / red[0];
    __syncthreads();

    int d = tid & 63, part = tid >> 6;
    float acc = 0.f;
    for (int i = part; i < NN; i += 4)
        acc += sc[i] * qkv[(size_t)(b * NN + i) * C3 + 2 * CC + h * DD + d];
    part4[part][d] = acc;
    __syncthreads();
    if (tid < DD)
        Y[(size_t)(b * NN) * CC + h * DD + tid] =
            (part4[0][tid] + part4[1][tid] + part4[2][tid] + part4[3][tid]) * inv;
}

// ---------------- tensor-core space attention -> traj -------------------
// QT=32 queries/block, grid = B*H*49. Dynamic smem ~160.5KB, 1 block/SM.
// Computes scores^T = K @ Q^T so K and V stay in natural layout.
#define SQT 32
#define KS_LD 76
#define VS_LD 72
#define SC_LD 40
#define QT_LD 40
#define KS_OFF 0
#define VS_OFF (208 * KS_LD)                    // 15808 floats
#define SC_OFF (VS_OFF + 200 * VS_LD)           // 30208
#define QT_OFF (SC_OFF + 208 * SC_LD)           // 38528
#define SPACE_SMEM_FLOATS (QT_OFF + 64 * QT_LD) // 41088
#define SPACE_SMEM_BYTES (SPACE_SMEM_FLOATS * 4)

__global__ void space_attn_kernel(const float* __restrict__ qkv, float* __restrict__ traj)
{
    extern __shared__ float smem[];
    float* Ks = smem + KS_OFF;   // [208][76]  K natural [n][d]
    float* Vs = smem + VS_OFF;   // [200][72]  V natural [n][d]
    float* Sc = smem + SC_OFF;   // [208][40]  scores^T [n][q]
    float* Qt = smem + QT_OFF;   // [64][40]   Q^T [d][q]

    const int nt_blocks = SS / SQT;    // 49
    const int bh = blockIdx.x / nt_blocks;
    const int st = blockIdx.x % nt_blocks;
    const int b = bh / HH;
    const int h = bh % HH;
    const int s0 = st * SQT;
    const int tid = threadIdx.x;
    const int warp = tid >> 5;
    const int lane = tid & 31;
    const int g = lane >> 2;
    const int q = lane & 3;

    // ---- load Q transposed: Qt[d][q] (tf32) ----
    for (int idx = tid; idx < SQT * 16; idx += 256) {
        int row = idx >> 4, d4 = (idx & 15) << 2;
        float4 qv = *(const float4*)(qkv + (size_t)(b * NN + 1 + s0 + row) * C3 + h * DD + d4);
        Qt[(d4 + 0) * QT_LD + row] = to_tf32(qv.x);
        Qt[(d4 + 1) * QT_LD + row] = to_tf32(qv.y);
        Qt[(d4 + 2) * QT_LD + row] = to_tf32(qv.z);
        Qt[(d4 + 3) * QT_LD + row] = to_tf32(qv.w);
    }

    for (int f = 0; f < FF; f++) {
        __syncthreads();   // prev frame PV done reading Sc/Vs

        // ---- load K,V frame (natural layout, tf32) ----
        const size_t frameRow = (size_t)(b * NN + 1 + f * PP);
        for (int idx = tid; idx < PP * 16; idx += 256) {
            int n = idx >> 4, d4 = (idx & 15) << 2;
            float4 kv = *(const float4*)(qkv + (frameRow + n) * C3 + CC + h * DD + d4);
            float* dst = &Ks[n * KS_LD + d4];
            dst[0] = to_tf32(kv.x); dst[1] = to_tf32(kv.y);
            dst[2] = to_tf32(kv.z); dst[3] = to_tf32(kv.w);
        }
        for (int idx = tid; idx < PP * 16; idx += 256) {
            int n = idx >> 4, d4 = (idx & 15) << 2;
            float4 vv = *(const float4*)(qkv + (frameRow + n) * C3 + 2 * CC + h * DD + d4);
            float* dst = &Vs[n * VS_LD + d4];
            dst[0] = to_tf32(vv.x); dst[1] = to_tf32(vv.y);
            dst[2] = to_tf32(vv.z); dst[3] = to_tf32(vv.w);
        }
        // zero V pad rows 196..199 (cols 0..63)
        {
            int n = 196 + (tid >> 6), d = tid & 63;
            Vs[n * VS_LD + d] = 0.f;
        }
        __syncthreads();

        // ---- QK: Sc^T(208x32) = K(208x64) @ Qt ----
        for (int mt = warp; mt < 13; mt += 8) {
            const int m0 = mt * 16;
            float acc[4][4];
            #pragma unroll
            for (int i = 0; i < 4; i++)
                #pragma unroll
                for (int j = 0; j < 4; j++) acc[i][j] = 0.f;
            #pragma unroll
            for (int kb = 0; kb < 8; kb++) {
                const int k0 = kb * 8;
                uint32_t a[4];
                a[0] = __float_as_uint(Ks[(m0 + g) * KS_LD + k0 + q]);
                a[1] = __float_as_uint(Ks[(m0 + 8 + g) * KS_LD + k0 + q]);
                a[2] = __float_as_uint(Ks[(m0 + g) * KS_LD + k0 + q + 4]);
                a[3] = __float_as_uint(Ks[(m0 + 8 + g) * KS_LD + k0 + q + 4]);
                #pragma unroll
                for (int nt = 0; nt < 4; nt++) {
                    uint32_t bfr[2];
                    bfr[0] = __float_as_uint(Qt[(k0 + q) * QT_LD + nt * 8 + g]);
                    bfr[1] = __float_as_uint(Qt[(k0 + q + 4) * QT_LD + nt * 8 + g]);
                    mma_tf32(acc[nt], a, bfr);
                }
            }
            #pragma unroll
            for (int nt = 0; nt < 4; nt++) {
                int c0 = nt * 8 + 2 * q;
                *(float2*)&Sc[(m0 + g) * SC_LD + c0] =
                    make_float2(acc[nt][0] * SCALE, acc[nt][1] * SCALE);
                *(float2*)&Sc[(m0 + 8 + g) * SC_LD + c0] =
                    make_float2(acc[nt][2] * SCALE, acc[nt][3] * SCALE);
            }
        }
        __syncthreads();

        // ---- softmax down columns (8 lanes per query column) ----
        {
            const int col = tid >> 3, r = tid & 7;
            float m = -1e30f;
            for (int n = r; n < PP; n += 8) m = fmaxf(m, Sc[n * SC_LD + col]);
            #pragma unroll
            for (int o = 4; o; o >>= 1) m = fmaxf(m, __shfl_xor_sync(0xffffffffu, m, o));
            float z = 0.f;
            for (int n = r; n < PP; n += 8) {
                float e = __expf(Sc[n * SC_LD + col] - m);
                Sc[n * SC_LD + col] = e;
                z += e;
            }
            #pragma unroll
            for (int o = 4; o; o >>= 1) z += __shfl_xor_sync(0xffffffffu, z, o);
            float inv = 1.f / z;
            for (int n = r; n < PP; n += 8)
                Sc[n * SC_LD + col] = to_tf32(Sc[n * SC_LD + col] * inv);
        }
        // zero P pad rows 196..199
        if (tid < 128) Sc[(196 + (tid >> 5)) * SC_LD + (tid & 31)] = 0.f;
        __syncthreads();

        // ---- PV: out(32x64) = P(32x200) @ V(200x64) ----
        {
            const int mt = warp & 1;       // m-tile (queries)
            const int ng = warp >> 1;      // owns d-tiles 2*ng, 2*ng+1
            const int m0 = mt * 16;
            float acc[2][4];
            #pragma unroll
            for (int j = 0; j < 2; j++)
                #pragma unroll
                for (int l = 0; l < 4; l++) acc[j][l] = 0.f;
            for (int kb = 0; kb < 25; kb++) {
                const int k0 = kb * 8;
                uint32_t a[4];
                a[0] = __float_as_uint(Sc[(k0 + q) * SC_LD + m0 + g]);
                a[1] = __float_as_uint(Sc[(k0 + q) * SC_LD + m0 + 8 + g]);
                a[2] = __float_as_uint(Sc[(k0 + q + 4) * SC_LD + m0 + g]);
                a[3] = __float_as_uint(Sc[(k0 + q + 4) * SC_LD + m0 + 8 + g]);
                #pragma unroll
                for (int j = 0; j < 2; j++) {
                    const int d0 = (ng * 2 + j) * 8;
                    uint32_t bfr[2];
                    bfr[0] = __float_as_uint(Vs[(k0 + q) * VS_LD + d0 + g]);
                    bfr[1] = __float_as_uint(Vs[(k0 + q + 4) * VS_LD + d0 + g]);
                    mma_tf32(acc[j], a, bfr);
                }
            }
            #pragma unroll
            for (int j = 0; j < 2; j++) {
                const int d0 = (ng * 2 + j) * 8;
                const int col = h * DD + d0 + 2 * q;
                const int row0 = s0 + m0 + g;
                *(float2*)(traj + ((size_t)(b * SS + row0) * FF + f) * CC + col) =
                    make_float2(acc[j][0], acc[j][1]);
                *(float2*)(traj + ((size_t)(b * SS + row0 + 8) * FF + f) * CC + col) =
                    make_float2(acc[j][2], acc[j][3]);
            }
        }
    }
}

// ---------------- x_diag gather ----------------
__global__ void gather_xdiag_kernel(const float* __restrict__ traj, float* __restrict__ xd)
{
    size_t idx = (size_t)blockIdx.x * 256 + threadIdx.x;
    if (idx >= (size_t)BB * SS * CC) return;
    int c = idx % CC;
    int bs = idx / CC;
    int s = bs % SS;
    xd[idx] = traj[((size_t)bs * FF + (s / PP)) * CC + c];
}

// ---------------- frame attention + attn output + Y rows. grid = B*S -----
__global__ void frame_attn_kernel(const float* __restrict__ q2, const float* __restrict__ k2,
                                  const float* __restrict__ traj, float* __restrict__ Y,
                                  float* __restrict__ attn_out)
{
    const int bs = blockIdx.x;
    const int b = bs / SS;
    const int s = bs % SS;
    const int tid = threadIdx.x;
    __shared__ float a[HH][FF];

    if (tid < HH * FF) {
        int h = tid >> 3, f = tid & 7;
        const float* qr = q2 + (size_t)bs * CC + h * DD;
        const float* kr = k2 + ((size_t)bs * FF + f) * CC + h * DD;
        float dot = 0.f;
        for (int d = 0; d < DD; d += 4) {
            float4 a4 = *(const float4*)(qr + d);
            float4 b4 = *(const float4*)(kr + d);
            dot += a4.x * b4.x + a4.y * b4.y + a4.z * b4.z + a4.w * b4.w;
        }
        a[h][f] = dot * SCALE;
    }
    __syncthreads();
    if (tid < HH) {
        int h = tid;
        float m = -1e30f;
        #pragma unroll
        for (int f = 0; f < FF; f++) m = fmaxf(m, a[h][f]);
        float z = 0.f;
        #pragma unroll
        for (int f = 0; f < FF; f++) { float e = __expf(a[h][f] - m); a[h][f] = e; z += e; }
        float inv = 1.f / z;
        #pragma unroll
        for (int f = 0; f < FF; f++) a[h][f] *= inv;
    }
    __syncthreads();
    if (tid < HH * FF) {
        int h = tid >> 3, f = tid & 7;
        attn_out[(((size_t)b * HH + h) * SS + s) * FF + f] = a[h][f];
    }
    for (int c = tid; c < CC; c += 256) {
        int h = c >> 6;
        float o = 0.f;
        #pragma unroll
        for (int f = 0; f < FF; f++)
            o += a[h][f] * traj[((size_t)bs * FF + f) * CC + c];
        Y[(size_t)(b * NN + 1 + s) * CC + c] = o;
    }
}

// ---------------- launcher ----------------
extern "C" void kernel_launch(void* const* d_in, const int* in_sizes, int n_in,
                              void* d_out, int out_size)
{
    const float* x      = (const float*)d_in[0];
    const float* W_qkv  = (const float*)d_in[1];
    const float* W_pq   = (const float*)d_in[2];
    const float* W_pkv  = (const float*)d_in[3];
    const float* W_proj = (const float*)d_in[4];
    const float* b_proj = (const float*)d_in[5];
    (void)in_sizes; (void)n_in;

    float *qkv, *traj, *xdiag, *q2, *k2, *Y;
    cudaGetSymbolAddress((void**)&qkv,   g_qkv);
    cudaGetSymbolAddress((void**)&traj,  g_traj);
    cudaGetSymbolAddress((void**)&xdiag, g_xdiag);
    cudaGetSymbolAddress((void**)&q2,    g_q2);
    cudaGetSymbolAddress((void**)&k2,    g_k2);
    cudaGetSymbolAddress((void**)&Y,     g_Y);

    float* out_main = (float*)d_out;                                   // (B,N,C)
    float* out_attn = out_main + (size_t)BB * NN * CC;                 // (B,h,S,F)

    static int smem_set = 0;
    if (!smem_set) {
        cudaFuncSetAttribute(space_attn_kernel,
                             cudaFuncAttributeMaxDynamicSharedMemorySize, SPACE_SMEM_BYTES);
        smem_set = 1;
    }

    const int M1 = BB * NN;   // 3138

    // 1) qkv = x @ W_qkv
    {
        dim3 grid(C3 / GBN, (M1 + GBM - 1) / GBM);
        tf32_gemm_kernel<<<grid, 256>>>(x, W_qkv, qkv, M1, C3, CC, CC, C3, C3, nullptr);
    }
    // 2) cls attention -> Y row 0 per batch
    cls_attn_kernel<<<BB * HH, 256>>>(qkv, Y);
    // 3) space attention -> traj (tensor cores)
    space_attn_kernel<<<BB * HH * (SS / SQT), 256, SPACE_SMEM_BYTES>>>(qkv, traj);
    // 4) x_diag gather + q2 GEMM
    {
        size_t tot = (size_t)BB * SS * CC;
        gather_xdiag_kernel<<<(int)((tot + 255) / 256), 256>>>(traj, xdiag);
        dim3 grid(CC / GBN, (BB * SS + GBM - 1) / GBM);
        tf32_gemm_kernel<<<grid, 256>>>(xdiag, W_pq, q2, BB * SS, CC, CC, CC, CC, CC, nullptr);
    }
    // 5) k2 = traj @ W_pkv[:, :CC]   (v2 is dead in the reference)
    {
        int M = BB * SS * FF;  // 25088
        dim3 grid(CC / GBN, (M + GBM - 1) / GBM);
        tf32_gemm_kernel<<<grid, 256>>>(traj, W_pkv, k2, M, CC, CC, CC, 2 * CC, CC, nullptr);
    }
    // 6) frame attention -> attn output + Y rows 1..S
    frame_attn_kernel<<<BB * SS, 256>>>(q2, k2, traj, Y, out_attn);
    // 7) out = Y @ W_proj + b_proj
    {
        dim3 grid(CC / GBN, (M1 + GBM - 1) / GBM);
        tf32_gemm_kernel<<<grid, 256>>>(Y, W_proj, out_main, M1, CC, CC, CC, CC, CC, b_proj);
    }
}

// round 5
// speedup vs baseline: 3.1500x; 1.3135x over previous
#include <cuda_runtime.h>
#include <cuda_bf16.h>
#include <math.h>
#include <stdint.h>

// Problem constants
#define BB 2
#define NN 1569          // tokens incl cls
#define CC 768
#define HH 12
#define DD 64
#define PP 196
#define FF 8
#define SS 1568          // F*P
#define C3 2304          // 3*C
#define W12 9216         // 12*768
#define SCALE 0.125f

// ---------------- device scratch (no allocations allowed) ----------------
__device__ float g_qkv[(size_t)BB * NN * C3];          // (B*N, 3C)
__device__ float g_traj[(size_t)BB * SS * FF * CC];    // (B,S,F,C)
__device__ float g_q2[(size_t)BB * SS * CC];           // (B*S, C)
__device__ float g_w[(size_t)BB * SS * W12];           // (B*S, H, C) fused k2 weights
__device__ float g_wT[(size_t)CC * CC];                // W_pkv[:, :CC] transposed: [hd][c]
__device__ float g_Y[(size_t)BB * NN * CC];            // (B*N, C) concat[cls,out]

__device__ __forceinline__ float to_tf32(float x) {
    uint32_t u;
    asm("cvt.rna.tf32.f32 %0, %1;" : "=r"(u) : "f"(x));
    return __uint_as_float(u);
}

__device__ __forceinline__ void mma_tf32(float (&c)[4], const uint32_t (&a)[4], const uint32_t (&b)[2]) {
    asm volatile(
        "mma.sync.aligned.m16n8k8.row.col.f32.tf32.tf32.f32 "
        "{%0,%1,%2,%3}, {%4,%5,%6,%7}, {%8,%9}, {%0,%1,%2,%3};"
        : "+f"(c[0]), "+f"(c[1]), "+f"(c[2]), "+f"(c[3])
        : "r"(a[0]), "r"(a[1]), "r"(a[2]), "r"(a[3]), "r"(b[0]), "r"(b[1]));
}

// ---------------- TF32 tensor-core GEMM, double-buffered ----------------
// C = A(MxK) @ B(KxN) [+bias].  BM=128, BN=64, BK=16, 256 threads (8 warps).
// gather!=0: A row r is read from A + (r*FF + (r%SS)/PP)*lda  (xdiag fusion).
// blockIdx.z batch: A += z*zAcol, B += z*zBoff, C += z*zCcol.
#define GBM 128
#define GBN 64
#define GBK 16
#define AST 136
#define BST 72

__device__ __forceinline__ size_t a_row_off(int gr, int lda, int gather) {
    if (gather) {
        int s = gr % SS;
        gr = gr * FF + s / PP;
    }
    return (size_t)gr * lda;
}

__global__ void tf32_gemm_kernel(const float* __restrict__ A, const float* __restrict__ B,
                                 float* __restrict__ C, int M, int N, int K,
                                 int lda, int ldb, int ldc,
                                 const float* __restrict__ bias, int gather,
                                 int zAcol, int zBoff, int zCcol)
{
    __shared__ float As[2][GBK][AST];   // k-major
    __shared__ float Bs[2][GBK][BST];   // k-major

    const int z = blockIdx.z;
    A += (size_t)z * zAcol;
    B += (size_t)z * zBoff;
    C += (size_t)z * zCcol;

    const int tid  = threadIdx.x;
    const int warp = tid >> 5;
    const int lane = tid & 31;
    const int g = lane >> 2;
    const int q = lane & 3;

    const int wm = warp & 3;
    const int wn = warp >> 2;
    const int warpM = wm * 32;
    const int warpN = wn * 32;

    const int by = blockIdx.y * GBM;
    const int bx = blockIdx.x * GBN;

    float acc[2][4][4];
    #pragma unroll
    for (int i = 0; i < 2; i++)
        #pragma unroll
        for (int j = 0; j < 4; j++)
            #pragma unroll
            for (int l = 0; l < 4; l++) acc[i][j][l] = 0.f;

    const int a_row = tid >> 2;
    const int a_col = (tid & 3) << 2;
    const int b_row = tid >> 4;
    const int b_col = (tid & 15) << 2;

    float4 avP[2], bvP;
    #pragma unroll
    for (int i = 0; i < 2; i++) {
        int gr = by + a_row + i * 64;
        avP[i] = make_float4(0.f, 0.f, 0.f, 0.f);
        if (gr < M) avP[i] = *(const float4*)(A + a_row_off(gr, lda, gather) + a_col);
    }
    bvP = *(const float4*)(B + (size_t)b_row * ldb + bx + b_col);
    {
        #pragma unroll
        for (int i = 0; i < 2; i++) {
            int row = a_row + i * 64;
            As[0][a_col + 0][row] = to_tf32(avP[i].x);
            As[0][a_col + 1][row] = to_tf32(avP[i].y);
            As[0][a_col + 2][row] = to_tf32(avP[i].z);
            As[0][a_col + 3][row] = to_tf32(avP[i].w);
        }
        Bs[0][b_row][b_col + 0] = to_tf32(bvP.x);
        Bs[0][b_row][b_col + 1] = to_tf32(bvP.y);
        Bs[0][b_row][b_col + 2] = to_tf32(bvP.z);
        Bs[0][b_row][b_col + 3] = to_tf32(bvP.w);
    }
    __syncthreads();

    int cur = 0;
    for (int k0 = 0; k0 < K; k0 += GBK) {
        const bool has_next = (k0 + GBK < K);
        if (has_next) {
            #pragma unroll
            for (int i = 0; i < 2; i++) {
                int gr = by + a_row + i * 64;
                avP[i] = make_float4(0.f, 0.f, 0.f, 0.f);
                if (gr < M) avP[i] = *(const float4*)(A + a_row_off(gr, lda, gather) + k0 + GBK + a_col);
            }
            bvP = *(const float4*)(B + (size_t)(k0 + GBK + b_row) * ldb + bx + b_col);
        }

        #pragma unroll
        for (int kk = 0; kk < GBK; kk += 8) {
            uint32_t afr[2][4];
            #pragma unroll
            for (int mt = 0; mt < 2; mt++) {
                int r = warpM + mt * 16 + g;
                afr[mt][0] = __float_as_uint(As[cur][kk + q][r]);
                afr[mt][1] = __float_as_uint(As[cur][kk + q][r + 8]);
                afr[mt][2] = __float_as_uint(As[cur][kk + q + 4][r]);
                afr[mt][3] = __float_as_uint(As[cur][kk + q + 4][r + 8]);
            }
            uint32_t bfr[4][2];
            #pragma unroll
            for (int nt = 0; nt < 4; nt++) {
                int c = warpN + nt * 8 + g;
                bfr[nt][0] = __float_as_uint(Bs[cur][kk + q][c]);
                bfr[nt][1] = __float_as_uint(Bs[cur][kk + q + 4][c]);
            }
            #pragma unroll
            for (int mt = 0; mt < 2; mt++)
                #pragma unroll
                for (int nt = 0; nt < 4; nt++)
                    mma_tf32(acc[mt][nt], afr[mt], bfr[nt]);
        }

        if (has_next) {
            int nb = cur ^ 1;
            #pragma unroll
            for (int i = 0; i < 2; i++) {
                int row = a_row + i * 64;
                As[nb][a_col + 0][row] = to_tf32(avP[i].x);
                As[nb][a_col + 1][row] = to_tf32(avP[i].y);
                As[nb][a_col + 2][row] = to_tf32(avP[i].z);
                As[nb][a_col + 3][row] = to_tf32(avP[i].w);
            }
            Bs[nb][b_row][b_col + 0] = to_tf32(bvP.x);
            Bs[nb][b_row][b_col + 1] = to_tf32(bvP.y);
            Bs[nb][b_row][b_col + 2] = to_tf32(bvP.z);
            Bs[nb][b_row][b_col + 3] = to_tf32(bvP.w);
        }
        __syncthreads();
        cur ^= 1;
    }

    #pragma unroll
    for (int mt = 0; mt < 2; mt++) {
        #pragma unroll
        for (int nt = 0; nt < 4; nt++) {
            int col = bx + warpN + nt * 8 + 2 * q;
            float bx0 = 0.f, bx1 = 0.f;
            if (bias) { bx0 = bias[col]; bx1 = bias[col + 1]; }
            int r0 = by + warpM + mt * 16 + g;
            if (r0 < M) {
                float2 o = make_float2(acc[mt][nt][0] + bx0, acc[mt][nt][1] + bx1);
                *(float2*)(C + (size_t)r0 * ldc + col) = o;
            }
            if (r0 + 8 < M) {
                float2 o = make_float2(acc[mt][nt][2] + bx0, acc[mt][nt][3] + bx1);
                *(float2*)(C + (size_t)(r0 + 8) * ldc + col) = o;
            }
        }
    }
}

// ---------------- W_pkv[:, :CC] transpose: wT[hd][c] = W_pkv[c][hd] ------
__global__ void transpose_wpkv_kernel(const float* __restrict__ W_pkv, float* __restrict__ wT)
{
    int idx = blockIdx.x * 256 + threadIdx.x;
    if (idx >= CC * CC) return;
    int hd = idx / CC, c = idx % CC;
    wT[(size_t)hd * CC + c] = W_pkv[(size_t)c * (2 * CC) + hd];
}

// ---------------- cls attention: 24 blocks (b,h) ----------------
__global__ void cls_attn_kernel(const float* __restrict__ qkv, float* __restrict__ Y)
{
    const int b = blockIdx.x / HH;
    const int h = blockIdx.x % HH;
    const int tid = threadIdx.x;

    __shared__ float qs[DD];
    __shared__ float sc[NN];
    __shared__ float red[256];
    __shared__ float part4[4][DD];

    if (tid < DD) qs[tid] = qkv[(size_t)(b * NN) * C3 + h * DD + tid];
    __syncthreads();

    for (int i = tid; i < NN; i += 256) {
        const float* kr = qkv + (size_t)(b * NN + i) * C3 + CC + h * DD;
        float dot = 0.f;
        for (int d = 0; d < DD; d += 4) {
            float4 k4 = *(const float4*)(kr + d);
            dot += qs[d] * k4.x + qs[d + 1] * k4.y + qs[d + 2] * k4.z + qs[d + 3] * k4.w;
        }
        sc[i] = dot * SCALE;
    }
    __syncthreads();

    float m = -1e30f;
    for (int i = tid; i < NN; i += 256) m = fmaxf(m, sc[i]);
    red[tid] = m; __syncthreads();
    for (int o = 128; o; o >>= 1) { if (tid < o) red[tid] = fmaxf(red[tid], red[tid + o]); __syncthreads(); }
    m = red[0];
    __syncthreads();

    float z = 0.f;
    for (int i = tid; i < NN; i += 256) { float e = __expf(sc[i] - m); sc[i] = e; z += e; }
    red[tid] = z; __syncthreads();
    for (int o = 128; o; o >>= 1) { if (tid < o) red[tid] += red[tid + o]; __syncthreads(); }
    float inv = 1.f / red[0];
    __syncthreads();

    int d = tid & 63, part = tid >> 6;
    float acc = 0.f;
    for (int i = part; i < NN; i += 4)
        acc += sc[i] * qkv[(size_t)(b * NN + i) * C3 + 2 * CC + h * DD + d];
    part4[part][d] = acc;
    __syncthreads();
    if (tid < DD)
        Y[(size_t)(b * NN) * CC + h * DD + tid] =
            (part4[0][tid] + part4[1][tid] + part4[2][tid] + part4[3][tid]) * inv;
}

// ---------------- tensor-core space attention -> traj -------------------
#define SQT 32
#define KS_LD 76
#define VS_LD 72
#define SC_LD 40
#define QT_LD 40
#define KS_OFF 0
#define VS_OFF (208 * KS_LD)
#define SC_OFF (VS_OFF + 200 * VS_LD)
#define QT_OFF (SC_OFF + 208 * SC_LD)
#define SPACE_SMEM_FLOATS (QT_OFF + 64 * QT_LD)
#define SPACE_SMEM_BYTES (SPACE_SMEM_FLOATS * 4)

__global__ void space_attn_kernel(const float* __restrict__ qkv, float* __restrict__ traj)
{
    extern __shared__ float smem[];
    float* Ks = smem + KS_OFF;
    float* Vs = smem + VS_OFF;
    float* Sc = smem + SC_OFF;
    float* Qt = smem + QT_OFF;

    const int nt_blocks = SS / SQT;    // 49
    const int bh = blockIdx.x / nt_blocks;
    const int st = blockIdx.x % nt_blocks;
    const int b = bh / HH;
    const int h = bh % HH;
    const int s0 = st * SQT;
    const int tid = threadIdx.x;
    const int warp = tid >> 5;
    const int lane = tid & 31;
    const int g = lane >> 2;
    const int q = lane & 3;

    for (int idx = tid; idx < SQT * 16; idx += 256) {
        int row = idx >> 4, d4 = (idx & 15) << 2;
        float4 qv = *(const float4*)(qkv + (size_t)(b * NN + 1 + s0 + row) * C3 + h * DD + d4);
        Qt[(d4 + 0) * QT_LD + row] = to_tf32(qv.x);
        Qt[(d4 + 1) * QT_LD + row] = to_tf32(qv.y);
        Qt[(d4 + 2) * QT_LD + row] = to_tf32(qv.z);
        Qt[(d4 + 3) * QT_LD + row] = to_tf32(qv.w);
    }

    for (int f = 0; f < FF; f++) {
        __syncthreads();

        const size_t frameRow = (size_t)(b * NN + 1 + f * PP);
        for (int idx = tid; idx < PP * 16; idx += 256) {
            int n = idx >> 4, d4 = (idx & 15) << 2;
            float4 kv = *(const float4*)(qkv + (frameRow + n) * C3 + CC + h * DD + d4);
            float* dst = &Ks[n * KS_LD + d4];
            dst[0] = to_tf32(kv.x); dst[1] = to_tf32(kv.y);
            dst[2] = to_tf32(kv.z); dst[3] = to_tf32(kv.w);
        }
        for (int idx = tid; idx < PP * 16; idx += 256) {
            int n = idx >> 4, d4 = (idx & 15) << 2;
            float4 vv = *(const float4*)(qkv + (frameRow + n) * C3 + 2 * CC + h * DD + d4);
            float* dst = &Vs[n * VS_LD + d4];
            dst[0] = to_tf32(vv.x); dst[1] = to_tf32(vv.y);
            dst[2] = to_tf32(vv.z); dst[3] = to_tf32(vv.w);
        }
        {
            int n = 196 + (tid >> 6), d = tid & 63;
            Vs[n * VS_LD + d] = 0.f;
        }
        __syncthreads();

        for (int mt = warp; mt < 13; mt += 8) {
            const int m0 = mt * 16;
            float acc[4][4];
            #pragma unroll
            for (int i = 0; i < 4; i++)
                #pragma unroll
                for (int j = 0; j < 4; j++) acc[i][j] = 0.f;
            #pragma unroll
            for (int kb = 0; kb < 8; kb++) {
                const int k0 = kb * 8;
                uint32_t a[4];
                a[0] = __float_as_uint(Ks[(m0 + g) * KS_LD + k0 + q]);
                a[1] = __float_as_uint(Ks[(m0 + 8 + g) * KS_LD + k0 + q]);
                a[2] = __float_as_uint(Ks[(m0 + g) * KS_LD + k0 + q + 4]);
                a[3] = __float_as_uint(Ks[(m0 + 8 + g) * KS_LD + k0 + q + 4]);
                #pragma unroll
                for (int nt = 0; nt < 4; nt++) {
                    uint32_t bfr[2];
                    bfr[0] = __float_as_uint(Qt[(k0 + q) * QT_LD + nt * 8 + g]);
                    bfr[1] = __float_as_uint(Qt[(k0 + q + 4) * QT_LD + nt * 8 + g]);
                    mma_tf32(acc[nt], a, bfr);
                }
            }
            #pragma unroll
            for (int nt = 0; nt < 4; nt++) {
                int c0 = nt * 8 + 2 * q;
                *(float2*)&Sc[(m0 + g) * SC_LD + c0] =
                    make_float2(acc[nt][0] * SCALE, acc[nt][1] * SCALE);
                *(float2*)&Sc[(m0 + 8 + g) * SC_LD + c0] =
                    make_float2(acc[nt][2] * SCALE, acc[nt][3] * SCALE);
            }
        }
        __syncthreads();

        {
            const int col = tid >> 3, r = tid & 7;
            float m = -1e30f;
            for (int n = r; n < PP; n += 8) m = fmaxf(m, Sc[n * SC_LD + col]);
            #pragma unroll
            for (int o = 4; o; o >>= 1) m = fmaxf(m, __shfl_xor_sync(0xffffffffu, m, o));
            float z = 0.f;
            for (int n = r; n < PP; n += 8) {
                float e = __expf(Sc[n * SC_LD + col] - m);
                Sc[n * SC_LD + col] = e;
                z += e;
            }
            #pragma unroll
            for (int o = 4; o; o >>= 1) z += __shfl_xor_sync(0xffffffffu, z, o);
            float inv = 1.f / z;
            for (int n = r; n < PP; n += 8)
                Sc[n * SC_LD + col] = to_tf32(Sc[n * SC_LD + col] * inv);
        }
        if (tid < 128) Sc[(196 + (tid >> 5)) * SC_LD + (tid & 31)] = 0.f;
        __syncthreads();

        {
            const int mt = warp & 1;
            const int ng = warp >> 1;
            const int m0 = mt * 16;
            float acc[2][4];
            #pragma unroll
            for (int j = 0; j < 2; j++)
                #pragma unroll
                for (int l = 0; l < 4; l++) acc[j][l] = 0.f;
            for (int kb = 0; kb < 25; kb++) {
                const int k0 = kb * 8;
                uint32_t a[4];
                a[0] = __float_as_uint(Sc[(k0 + q) * SC_LD + m0 + g]);
                a[1] = __float_as_uint(Sc[(k0 + q) * SC_LD + m0 + 8 + g]);
                a[2] = __float_as_uint(Sc[(k0 + q + 4) * SC_LD + m0 + g]);
                a[3] = __float_as_uint(Sc[(k0 + q + 4) * SC_LD + m0 + 8 + g]);
                #pragma unroll
                for (int j = 0; j < 2; j++) {
                    const int d0 = (ng * 2 + j) * 8;
                    uint32_t bfr[2];
                    bfr[0] = __float_as_uint(Vs[(k0 + q) * VS_LD + d0 + g]);
                    bfr[1] = __float_as_uint(Vs[(k0 + q + 4) * VS_LD + d0 + g]);
                    mma_tf32(acc[j], a, bfr);
                }
            }
            #pragma unroll
            for (int j = 0; j < 2; j++) {
                const int d0 = (ng * 2 + j) * 8;
                const int col = h * DD + d0 + 2 * q;
                const int row0 = s0 + m0 + g;
                *(float2*)(traj + ((size_t)(b * SS + row0) * FF + f) * CC + col) =
                    make_float2(acc[j][0], acc[j][1]);
                *(float2*)(traj + ((size_t)(b * SS + row0 + 8) * FF + f) * CC + col) =
                    make_float2(acc[j][2], acc[j][3]);
            }
        }
    }
}

// ---------------- frame attention (fused logits) ----------------
// grid = B*S, 384 threads (12 warps = 12 heads).
// logit[h,f] = SCALE * w[bs,h,:]·traj[bs,f,:] ; softmax over f;
// attn -> output, Y row = sum_f attn*traj.
__global__ void frame_attn_kernel(const float* __restrict__ w, const float* __restrict__ traj,
                                  float* __restrict__ Y, float* __restrict__ attn_out)
{
    const int bs = blockIdx.x;
    const int b = bs / SS;
    const int s = bs % SS;
    const int tid = threadIdx.x;
    const int h = tid >> 5;      // warp = head
    const int lane = tid & 31;

    __shared__ float ts[FF][CC];
    __shared__ float a_sm[HH][FF];

    for (int idx = tid; idx < FF * CC / 4; idx += 384) {
        int f = idx / 192, j = idx % 192;
        float4 v = *(const float4*)(traj + ((size_t)bs * FF + f) * CC + j * 4);
        *(float4*)&ts[f][j * 4] = v;
    }
    __syncthreads();

    // logits
    const float* wrow = w + (size_t)bs * W12 + h * CC;
    float wreg[24];
    #pragma unroll
    for (int j = 0; j < 24; j++) wreg[j] = wrow[lane + 32 * j];

    float lg[FF];
    #pragma unroll
    for (int f = 0; f < FF; f++) {
        float dsum = 0.f;
        #pragma unroll
        for (int j = 0; j < 24; j++) dsum += wreg[j] * ts[f][lane + 32 * j];
        #pragma unroll
        for (int o = 16; o; o >>= 1) dsum += __shfl_xor_sync(0xffffffffu, dsum, o);
        lg[f] = dsum * SCALE;
    }
    // softmax (all lanes redundantly)
    float m = -1e30f;
    #pragma unroll
    for (int f = 0; f < FF; f++) m = fmaxf(m, lg[f]);
    float z = 0.f;
    #pragma unroll
    for (int f = 0; f < FF; f++) { lg[f] = __expf(lg[f] - m); z += lg[f]; }
    float inv = 1.f / z;
    #pragma unroll
    for (int f = 0; f < FF; f++) lg[f] *= inv;

    if (lane < FF) {
        a_sm[h][lane] = lg[lane];
        attn_out[(((size_t)b * HH + h) * SS + s) * FF + lane] = lg[lane];
    }
    __syncthreads();

    // PV: 384 threads x 2 cols
    #pragma unroll
    for (int rep = 0; rep < 2; rep++) {
        int c = tid + rep * 384;
        int h2 = c >> 6;
        float o = 0.f;
        #pragma unroll
        for (int f = 0; f < FF; f++) o += a_sm[h2][f] * ts[f][c];
        Y[(size_t)(b * NN + 1 + s) * CC + c] = o;
    }
}

// ---------------- launcher ----------------
extern "C" void kernel_launch(void* const* d_in, const int* in_sizes, int n_in,
                              void* d_out, int out_size)
{
    const float* x      = (const float*)d_in[0];
    const float* W_qkv  = (const float*)d_in[1];
    const float* W_pq   = (const float*)d_in[2];
    const float* W_pkv  = (const float*)d_in[3];
    const float* W_proj = (const float*)d_in[4];
    const float* b_proj = (const float*)d_in[5];
    (void)in_sizes; (void)n_in;

    float *qkv, *traj, *q2, *w, *wT, *Y;
    cudaGetSymbolAddress((void**)&qkv,  g_qkv);
    cudaGetSymbolAddress((void**)&traj, g_traj);
    cudaGetSymbolAddress((void**)&q2,   g_q2);
    cudaGetSymbolAddress((void**)&w,    g_w);
    cudaGetSymbolAddress((void**)&wT,   g_wT);
    cudaGetSymbolAddress((void**)&Y,    g_Y);

    float* out_main = (float*)d_out;                                   // (B,N,C)
    float* out_attn = out_main + (size_t)BB * NN * CC;                 // (B,h,S,F)

    static int smem_set = 0;
    if (!smem_set) {
        cudaFuncSetAttribute(space_attn_kernel,
                             cudaFuncAttributeMaxDynamicSharedMemorySize, SPACE_SMEM_BYTES);
        smem_set = 1;
    }

    const int M1 = BB * NN;   // 3138
    const int M2 = BB * SS;   // 3136

    // 0) transpose of K-half of W_pkv (independent of activations)
    transpose_wpkv_kernel<<<(CC * CC + 255) / 256, 256>>>(W_pkv, wT);

    // 1) qkv = x @ W_qkv
    {
        dim3 grid(C3 / GBN, (M1 + GBM - 1) / GBM);
        tf32_gemm_kernel<<<grid, 256>>>(x, W_qkv, qkv, M1, C3, CC, CC, C3, C3,
                                        nullptr, 0, 0, 0, 0);
    }
    // 2) cls attention -> Y row 0 per batch
    cls_attn_kernel<<<BB * HH, 256>>>(qkv, Y);
    // 3) space attention -> traj (tensor cores)
    space_attn_kernel<<<BB * HH * (SS / SQT), 256, SPACE_SMEM_BYTES>>>(qkv, traj);
    // 4) q2 = xdiag @ W_pq with fused diagonal gather from traj
    {
        dim3 grid(CC / GBN, (M2 + GBM - 1) / GBM);
        tf32_gemm_kernel<<<grid, 256>>>(traj, W_pq, q2, M2, CC, CC, CC, CC, CC,
                                        nullptr, 1, 0, 0, 0);
    }
    // 5) w[bs,h,:] = q2[bs,h-block] @ W_pkv_h^T   (batched over z = head)
    {
        dim3 grid(CC / GBN, (M2 + GBM - 1) / GBM, HH);
        tf32_gemm_kernel<<<grid, 256>>>(q2, wT, w, M2, CC, DD, CC, CC, W12,
                                        nullptr, 0, DD, DD * CC, CC);
    }
    // 6) frame attention (fused logits) -> attn output + Y rows 1..S
    frame_attn_kernel<<<BB * SS, 384>>>(w, traj, Y, out_attn);
    // 7) out = Y @ W_proj + b_proj
    {
        dim3 grid(CC / GBN, (M1 + GBM - 1) / GBM);
        tf32_gemm_kernel<<<grid, 256>>>(Y, W_proj, out_main, M1, CC, CC, CC, CC, CC,
                                        b_proj, 0, 0, 0, 0);
    }
}

// round 8
// speedup vs baseline: 3.6756x; 1.1668x over previous
#include <cuda_runtime.h>
#include <cuda_bf16.h>
#include <math.h>
#include <stdint.h>

// Problem constants
#define BB 2
#define NN 1569          // tokens incl cls
#define CC 768
#define HH 12
#define DD 64
#define PP 196
#define FF 8
#define SS 1568          // F*P
#define C3 2304          // 3*C
#define W12 9216         // 12*768
#define SCALE 0.125f

// ---------------- device scratch (no allocations allowed) ----------------
__device__ float g_qkv[(size_t)BB * NN * C3];          // (B*N, 3C)
__device__ float g_traj[(size_t)BB * SS * FF * CC];    // (B,S,F,C)
__device__ float g_q2[(size_t)BB * SS * CC];           // (B*S, C)
__device__ float g_w[(size_t)BB * SS * W12];           // (B*S, H, C) fused k2 weights
__device__ float g_wT[(size_t)CC * CC];                // W_pkv[:, :CC] transposed: [hd][c]
__device__ float g_Y[(size_t)BB * NN * CC];            // (B*N, C) concat[cls,out]

__device__ __forceinline__ float to_tf32(float x) {
    uint32_t u;
    asm("cvt.rna.tf32.f32 %0, %1;" : "=r"(u) : "f"(x));
    return __uint_as_float(u);
}

__device__ __forceinline__ void mma_tf32(float (&c)[4], const uint32_t (&a)[4], const uint32_t (&b)[2]) {
    asm volatile(
        "mma.sync.aligned.m16n8k8.row.col.f32.tf32.tf32.f32 "
        "{%0,%1,%2,%3}, {%4,%5,%6,%7}, {%8,%9}, {%0,%1,%2,%3};"
        : "+f"(c[0]), "+f"(c[1]), "+f"(c[2]), "+f"(c[3])
        : "r"(a[0]), "r"(a[1]), "r"(a[2]), "r"(a[3]), "r"(b[0]), "r"(b[1]));
}

// ---------------- TF32 tensor-core GEMM, double-buffered ----------------
// C = A(MxK) @ B(KxN) [+bias].  BM=128, BN=64, BK=16, 256 threads (8 warps).
// gather!=0: A row r is read from A + (r*FF + (r%SS)/PP)*lda  (xdiag fusion).
// blockIdx.z batch: A += z*zAcol, B += z*zBoff, C += z*zCcol.
#define GBM 128
#define GBN 64
#define GBK 16
#define AST 136
#define BST 72

__device__ __forceinline__ size_t a_row_off(int gr, int lda, int gather) {
    if (gather) {
        int s = gr % SS;
        gr = gr * FF + s / PP;
    }
    return (size_t)gr * lda;
}

__global__ void tf32_gemm_kernel(const float* __restrict__ A, const float* __restrict__ B,
                                 float* __restrict__ C, int M, int N, int K,
                                 int lda, int ldb, int ldc,
                                 const float* __restrict__ bias, int gather,
                                 int zAcol, int zBoff, int zCcol)
{
    __shared__ float As[2][GBK][AST];   // k-major
    __shared__ float Bs[2][GBK][BST];   // k-major

    const int z = blockIdx.z;
    A += (size_t)z * zAcol;
    B += (size_t)z * zBoff;
    C += (size_t)z * zCcol;

    const int tid  = threadIdx.x;
    const int warp = tid >> 5;
    const int lane = tid & 31;
    const int g = lane >> 2;
    const int q = lane & 3;

    const int wm = warp & 3;
    const int wn = warp >> 2;
    const int warpM = wm * 32;
    const int warpN = wn * 32;

    const int by = blockIdx.y * GBM;
    const int bx = blockIdx.x * GBN;

    float acc[2][4][4];
    #pragma unroll
    for (int i = 0; i < 2; i++)
        #pragma unroll
        for (int j = 0; j < 4; j++)
            #pragma unroll
            for (int l = 0; l < 4; l++) acc[i][j][l] = 0.f;

    const int a_row = tid >> 2;
    const int a_col = (tid & 3) << 2;
    const int b_row = tid >> 4;
    const int b_col = (tid & 15) << 2;

    float4 avP[2], bvP;
    #pragma unroll
    for (int i = 0; i < 2; i++) {
        int gr = by + a_row + i * 64;
        avP[i] = make_float4(0.f, 0.f, 0.f, 0.f);
        if (gr < M) avP[i] = *(const float4*)(A + a_row_off(gr, lda, gather) + a_col);
    }
    bvP = *(const float4*)(B + (size_t)b_row * ldb + bx + b_col);
    {
        #pragma unroll
        for (int i = 0; i < 2; i++) {
            int row = a_row + i * 64;
            As[0][a_col + 0][row] = to_tf32(avP[i].x);
            As[0][a_col + 1][row] = to_tf32(avP[i].y);
            As[0][a_col + 2][row] = to_tf32(avP[i].z);
            As[0][a_col + 3][row] = to_tf32(avP[i].w);
        }
        Bs[0][b_row][b_col + 0] = to_tf32(bvP.x);
        Bs[0][b_row][b_col + 1] = to_tf32(bvP.y);
        Bs[0][b_row][b_col + 2] = to_tf32(bvP.z);
        Bs[0][b_row][b_col + 3] = to_tf32(bvP.w);
    }
    __syncthreads();

    int cur = 0;
    for (int k0 = 0; k0 < K; k0 += GBK) {
        const bool has_next = (k0 + GBK < K);
        if (has_next) {
            #pragma unroll
            for (int i = 0; i < 2; i++) {
                int gr = by + a_row + i * 64;
                avP[i] = make_float4(0.f, 0.f, 0.f, 0.f);
                if (gr < M) avP[i] = *(const float4*)(A + a_row_off(gr, lda, gather) + k0 + GBK + a_col);
            }
            bvP = *(const float4*)(B + (size_t)(k0 + GBK + b_row) * ldb + bx + b_col);
        }

        #pragma unroll
        for (int kk = 0; kk < GBK; kk += 8) {
            uint32_t afr[2][4];
            #pragma unroll
            for (int mt = 0; mt < 2; mt++) {
                int r = warpM + mt * 16 + g;
                afr[mt][0] = __float_as_uint(As[cur][kk + q][r]);
                afr[mt][1] = __float_as_uint(As[cur][kk + q][r + 8]);
                afr[mt][2] = __float_as_uint(As[cur][kk + q + 4][r]);
                afr[mt][3] = __float_as_uint(As[cur][kk + q + 4][r + 8]);
            }
            uint32_t bfr[4][2];
            #pragma unroll
            for (int nt = 0; nt < 4; nt++) {
                int c = warpN + nt * 8 + g;
                bfr[nt][0] = __float_as_uint(Bs[cur][kk + q][c]);
                bfr[nt][1] = __float_as_uint(Bs[cur][kk + q + 4][c]);
            }
            #pragma unroll
            for (int mt = 0; mt < 2; mt++)
                #pragma unroll
                for (int nt = 0; nt < 4; nt++)
                    mma_tf32(acc[mt][nt], afr[mt], bfr[nt]);
        }

        if (has_next) {
            int nb = cur ^ 1;
            #pragma unroll
            for (int i = 0; i < 2; i++) {
                int row = a_row + i * 64;
                As[nb][a_col + 0][row] = to_tf32(avP[i].x);
                As[nb][a_col + 1][row] = to_tf32(avP[i].y);
                As[nb][a_col + 2][row] = to_tf32(avP[i].z);
                As[nb][a_col + 3][row] = to_tf32(avP[i].w);
            }
            Bs[nb][b_row][b_col + 0] = to_tf32(bvP.x);
            Bs[nb][b_row][b_col + 1] = to_tf32(bvP.y);
            Bs[nb][b_row][b_col + 2] = to_tf32(bvP.z);
            Bs[nb][b_row][b_col + 3] = to_tf32(bvP.w);
        }
        __syncthreads();
        cur ^= 1;
    }

    #pragma unroll
    for (int mt = 0; mt < 2; mt++) {
        #pragma unroll
        for (int nt = 0; nt < 4; nt++) {
            int col = bx + warpN + nt * 8 + 2 * q;
            float bx0 = 0.f, bx1 = 0.f;
            if (bias) { bx0 = bias[col]; bx1 = bias[col + 1]; }
            int r0 = by + warpM + mt * 16 + g;
            if (r0 < M) {
                float2 o = make_float2(acc[mt][nt][0] + bx0, acc[mt][nt][1] + bx1);
                *(float2*)(C + (size_t)r0 * ldc + col) = o;
            }
            if (r0 + 8 < M) {
                float2 o = make_float2(acc[mt][nt][2] + bx0, acc[mt][nt][3] + bx1);
                *(float2*)(C + (size_t)(r0 + 8) * ldc + col) = o;
            }
        }
    }
}

// ---------------- W_pkv[:, :CC] transpose: wT[hd][c] = W_pkv[c][hd] ------
__global__ void transpose_wpkv_kernel(const float* __restrict__ W_pkv, float* __restrict__ wT)
{
    int idx = blockIdx.x * 256 + threadIdx.x;
    if (idx >= CC * CC) return;
    int hd = idx / CC, c = idx % CC;
    wT[(size_t)hd * CC + c] = W_pkv[(size_t)c * (2 * CC) + hd];
}

// ---------------- cls attention: 24 blocks (b,h) ----------------
__global__ void cls_attn_kernel(const float* __restrict__ qkv, float* __restrict__ Y)
{
    const int b = blockIdx.x / HH;
    const int h = blockIdx.x % HH;
    const int tid = threadIdx.x;

    __shared__ float qs[DD];
    __shared__ float sc[NN];
    __shared__ float red[256];
    __shared__ float part4[4][DD];

    if (tid < DD) qs[tid] = qkv[(size_t)(b * NN) * C3 + h * DD + tid];
    __syncthreads();

    for (int i = tid; i < NN; i += 256) {
        const float* kr = qkv + (size_t)(b * NN + i) * C3 + CC + h * DD;
        float dot = 0.f;
        for (int d = 0; d < DD; d += 4) {
            float4 k4 = *(const float4*)(kr + d);
            dot += qs[d] * k4.x + qs[d + 1] * k4.y + qs[d + 2] * k4.z + qs[d + 3] * k4.w;
        }
        sc[i] = dot * SCALE;
    }
    __syncthreads();

    float m = -1e30f;
    for (int i = tid; i < NN; i += 256) m = fmaxf(m, sc[i]);
    red[tid] = m; __syncthreads();
    for (int o = 128; o; o >>= 1) { if (tid < o) red[tid] = fmaxf(red[tid], red[tid + o]); __syncthreads(); }
    m = red[0];
    __syncthreads();

    float z = 0.f;
    for (int i = tid; i < NN; i += 256) { float e = __expf(sc[i] - m); sc[i] = e; z += e; }
    red[tid] = z; __syncthreads();
    for (int o = 128; o; o >>= 1) { if (tid < o) red[tid] += red[tid + o]; __syncthreads(); }
    float inv = 1.f / red[0];
    __syncthreads();

    int d = tid & 63, part = tid >> 6;
    float acc = 0.f;
    for (int i = part; i < NN; i += 4)
        acc += sc[i] * qkv[(size_t)(b * NN + i) * C3 + 2 * CC + h * DD + d];
    part4[part][d] = acc;
    __syncthreads();
    if (tid < DD)
        Y[(size_t)(b * NN) * CC + h * DD + tid] =
            (part4[0][tid] + part4[1][tid] + part4[2][tid] + part4[3][tid]) * inv;
}

// ---------------- tensor-core space attention -> traj -------------------
// SQT=32 queries/block, 256 threads (8 warps), grid = B*H*49.
// Single K/V buffer (~107KB smem total) -> 2 blocks/SM, 16 warps/SM.
// Computes scores^T = K @ Q^T so K and V stay in natural layout.
#define SQT 32
#define BUF_LD 76
#define SC_LD 40
#define QT_LD 40
#define BUF_OFF 0
#define SC_OFF (208 * BUF_LD)                     // 15808
#define QT_OFF (SC_OFF + 208 * SC_LD)             // 24128
#define SPACE_SMEM_FLOATS (QT_OFF + 64 * QT_LD)   // 26688
#define SPACE_SMEM_BYTES (SPACE_SMEM_FLOATS * 4)  // 106752

__global__ void space_attn_kernel(const float* __restrict__ qkv, float* __restrict__ traj)
{
    extern __shared__ float smem[];
    float* Buf = smem + BUF_OFF;  // [208][76] K then V, natural [n][d]
    float* Sc  = smem + SC_OFF;   // [208][40] scores^T [n][q]
    float* Qt  = smem + QT_OFF;   // [64][40]  Q^T [d][q]

    const int nt_blocks = SS / SQT;    // 49
    const int bh = blockIdx.x / nt_blocks;
    const int st = blockIdx.x % nt_blocks;
    const int b = bh / HH;
    const int h = bh % HH;
    const int s0 = st * SQT;
    const int tid = threadIdx.x;
    const int warp = tid >> 5;
    const int lane = tid & 31;
    const int g = lane >> 2;
    const int q = lane & 3;

    // ---- load Q transposed: Qt[d][q] (tf32) ----
    for (int idx = tid; idx < SQT * 16; idx += 256) {
        int row = idx >> 4, d4 = (idx & 15) << 2;
        float4 qv = *(const float4*)(qkv + (size_t)(b * NN + 1 + s0 + row) * C3 + h * DD + d4);
        Qt[(d4 + 0) * QT_LD + row] = to_tf32(qv.x);
        Qt[(d4 + 1) * QT_LD + row] = to_tf32(qv.y);
        Qt[(d4 + 2) * QT_LD + row] = to_tf32(qv.z);
        Qt[(d4 + 3) * QT_LD + row] = to_tf32(qv.w);
    }

    for (int f = 0; f < FF; f++) {
        __syncthreads();   // prev frame PV done reading Buf/Sc (covers Qt on first iter)

        // ---- load K frame into Buf (natural layout, tf32) ----
        const size_t frameRow = (size_t)(b * NN + 1 + f * PP);
        for (int idx = tid; idx < PP * 16; idx += 256) {
            int n = idx >> 4, d4 = (idx & 15) << 2;
            float4 kv = *(const float4*)(qkv + (frameRow + n) * C3 + CC + h * DD + d4);
            float* dst = &Buf[n * BUF_LD + d4];
            dst[0] = to_tf32(kv.x); dst[1] = to_tf32(kv.y);
            dst[2] = to_tf32(kv.z); dst[3] = to_tf32(kv.w);
        }
        __syncthreads();

        // ---- QK: Sc^T(208x32) = K(208x64) @ Qt ----
        for (int mt = warp; mt < 13; mt += 8) {
            const int m0 = mt * 16;
            float acc[4][4];
            #pragma unroll
            for (int i = 0; i < 4; i++)
                #pragma unroll
                for (int j = 0; j < 4; j++) acc[i][j] = 0.f;
            #pragma unroll
            for (int kb = 0; kb < 8; kb++) {
                const int k0 = kb * 8;
                uint32_t a[4];
                a[0] = __float_as_uint(Buf[(m0 + g) * BUF_LD + k0 + q]);
                a[1] = __float_as_uint(Buf[(m0 + 8 + g) * BUF_LD + k0 + q]);
                a[2] = __float_as_uint(Buf[(m0 + g) * BUF_LD + k0 + q + 4]);
                a[3] = __float_as_uint(Buf[(m0 + 8 + g) * BUF_LD + k0 + q + 4]);
                #pragma unroll
                for (int nt = 0; nt < 4; nt++) {
                    uint32_t bfr[2];
                    bfr[0] = __float_as_uint(Qt[(k0 + q) * QT_LD + nt * 8 + g]);
                    bfr[1] = __float_as_uint(Qt[(k0 + q + 4) * QT_LD + nt * 8 + g]);
                    mma_tf32(acc[nt], a, bfr);
                }
            }
            #pragma unroll
            for (int nt = 0; nt < 4; nt++) {
                int c0 = nt * 8 + 2 * q;
                *(float2*)&Sc[(m0 + g) * SC_LD + c0] =
                    make_float2(acc[nt][0] * SCALE, acc[nt][1] * SCALE);
                *(float2*)&Sc[(m0 + 8 + g) * SC_LD + c0] =
                    make_float2(acc[nt][2] * SCALE, acc[nt][3] * SCALE);
            }
        }
        __syncthreads();   // QK done reading Buf(K) & writing Sc

        // ---- load V frame over Buf; then softmax on Sc ----
        for (int idx = tid; idx < PP * 16; idx += 256) {
            int n = idx >> 4, d4 = (idx & 15) << 2;
            float4 vv = *(const float4*)(qkv + (frameRow + n) * C3 + 2 * CC + h * DD + d4);
            float* dst = &Buf[n * BUF_LD + d4];
            dst[0] = to_tf32(vv.x); dst[1] = to_tf32(vv.y);
            dst[2] = to_tf32(vv.z); dst[3] = to_tf32(vv.w);
        }
        // zero V pad rows 196..199 (cols 0..63)
        {
            int n = 196 + (tid >> 6), d = tid & 63;
            Buf[n * BUF_LD + d] = 0.f;
        }
        // softmax down columns (8 lanes per query column)
        {
            const int col = tid >> 3, r = tid & 7;
            float m = -1e30f;
            for (int n = r; n < PP; n += 8) m = fmaxf(m, Sc[n * SC_LD + col]);
            #pragma unroll
            for (int o = 4; o; o >>= 1) m = fmaxf(m, __shfl_xor_sync(0xffffffffu, m, o));
            float z = 0.f;
            for (int n = r; n < PP; n += 8) {
                float e = __expf(Sc[n * SC_LD + col] - m);
                Sc[n * SC_LD + col] = e;
                z += e;
            }
            #pragma unroll
            for (int o = 4; o; o >>= 1) z += __shfl_xor_sync(0xffffffffu, z, o);
            float inv = 1.f / z;
            for (int n = r; n < PP; n += 8)
                Sc[n * SC_LD + col] = to_tf32(Sc[n * SC_LD + col] * inv);
        }
        // zero P pad rows 196..199
        if (tid < 128) Sc[(196 + (tid >> 5)) * SC_LD + (tid & 31)] = 0.f;
        __syncthreads();

        // ---- PV: out(32x64) = P(32x200) @ V(200x64) ----
        {
            const int mt = warp & 1;       // query tile
            const int ng = warp >> 1;      // owns d-tiles 2*ng, 2*ng+1
            const int m0 = mt * 16;
            float acc[2][4];
            #pragma unroll
            for (int j = 0; j < 2; j++)
                #pragma unroll
                for (int l = 0; l < 4; l++) acc[j][l] = 0.f;
            for (int kb = 0; kb < 25; kb++) {
                const int k0 = kb * 8;
                uint32_t a[4];
                a[0] = __float_as_uint(Sc[(k0 + q) * SC_LD + m0 + g]);
                a[1] = __float_as_uint(Sc[(k0 + q) * SC_LD + m0 + 8 + g]);
                a[2] = __float_as_uint(Sc[(k0 + q + 4) * SC_LD + m0 + g]);
                a[3] = __float_as_uint(Sc[(k0 + q + 4) * SC_LD + m0 + 8 + g]);
                #pragma unroll
                for (int j = 0; j < 2; j++) {
                    const int d0 = (ng * 2 + j) * 8;
                    uint32_t bfr[2];
                    bfr[0] = __float_as_uint(Buf[(k0 + q) * BUF_LD + d0 + g]);
                    bfr[1] = __float_as_uint(Buf[(k0 + q + 4) * BUF_LD + d0 + g]);
                    mma_tf32(acc[j], a, bfr);
                }
            }
            #pragma unroll
            for (int j = 0; j < 2; j++) {
                const int d0 = (ng * 2 + j) * 8;
                const int col = h * DD + d0 + 2 * q;
                const int row0 = s0 + m0 + g;
                *(float2*)(traj + ((size_t)(b * SS + row0) * FF + f) * CC + col) =
                    make_float2(acc[j][0], acc[j][1]);
                *(float2*)(traj + ((size_t)(b * SS + row0 + 8) * FF + f) * CC + col) =
                    make_float2(acc[j][2], acc[j][3]);
            }
        }
    }
}

// ---------------- frame attention (fused logits) ----------------
// grid = B*S, 384 threads (12 warps = 12 heads).
__global__ void frame_attn_kernel(const float* __restrict__ w, const float* __restrict__ traj,
                                  float* __restrict__ Y, float* __restrict__ attn_out)
{
    const int bs = blockIdx.x;
    const int b = bs / SS;
    const int s = bs % SS;
    const int tid = threadIdx.x;
    const int h = tid >> 5;      // warp = head
    const int lane = tid & 31;

    __shared__ float ts[FF][CC];
    __shared__ float a_sm[HH][FF];

    for (int idx = tid; idx < FF * CC / 4; idx += 384) {
        int f = idx / 192, j = idx % 192;
        float4 v = *(const float4*)(traj + ((size_t)bs * FF + f) * CC + j * 4);
        *(float4*)&ts[f][j * 4] = v;
    }
    __syncthreads();

    const float* wrow = w + (size_t)bs * W12 + h * CC;
    float wreg[24];
    #pragma unroll
    for (int j = 0; j < 24; j++) wreg[j] = wrow[lane + 32 * j];

    float lg[FF];
    #pragma unroll
    for (int f = 0; f < FF; f++) {
        float dsum = 0.f;
        #pragma unroll
        for (int j = 0; j < 24; j++) dsum += wreg[j] * ts[f][lane + 32 * j];
        #pragma unroll
        for (int o = 16; o; o >>= 1) dsum += __shfl_xor_sync(0xffffffffu, dsum, o);
        lg[f] = dsum * SCALE;
    }
    float m = -1e30f;
    #pragma unroll
    for (int f = 0; f < FF; f++) m = fmaxf(m, lg[f]);
    float z = 0.f;
    #pragma unroll
    for (int f = 0; f < FF; f++) { lg[f] = __expf(lg[f] - m); z += lg[f]; }
    float inv = 1.f / z;
    #pragma unroll
    for (int f = 0; f < FF; f++) lg[f] *= inv;

    if (lane < FF) {
        a_sm[h][lane] = lg[lane];
        attn_out[(((size_t)b * HH + h) * SS + s) * FF + lane] = lg[lane];
    }
    __syncthreads();

    #pragma unroll
    for (int rep = 0; rep < 2; rep++) {
        int c = tid + rep * 384;
        int h2 = c >> 6;
        float o = 0.f;
        #pragma unroll
        for (int f = 0; f < FF; f++) o += a_sm[h2][f] * ts[f][c];
        Y[(size_t)(b * NN + 1 + s) * CC + c] = o;
    }
}

// ---------------- launcher ----------------
extern "C" void kernel_launch(void* const* d_in, const int* in_sizes, int n_in,
                              void* d_out, int out_size)
{
    const float* x      = (const float*)d_in[0];
    const float* W_qkv  = (const float*)d_in[1];
    const float* W_pq   = (const float*)d_in[2];
    const float* W_pkv  = (const float*)d_in[3];
    const float* W_proj = (const float*)d_in[4];
    const float* b_proj = (const float*)d_in[5];
    (void)in_sizes; (void)n_in;

    float *qkv, *traj, *q2, *w, *wT, *Y;
    cudaGetSymbolAddress((void**)&qkv,  g_qkv);
    cudaGetSymbolAddress((void**)&traj, g_traj);
    cudaGetSymbolAddress((void**)&q2,   g_q2);
    cudaGetSymbolAddress((void**)&w,    g_w);
    cudaGetSymbolAddress((void**)&wT,   g_wT);
    cudaGetSymbolAddress((void**)&Y,    g_Y);

    float* out_main = (float*)d_out;                                   // (B,N,C)
    float* out_attn = out_main + (size_t)BB * NN * CC;                 // (B,h,S,F)

    static int smem_set = 0;
    if (!smem_set) {
        cudaFuncSetAttribute(space_attn_kernel,
                             cudaFuncAttributeMaxDynamicSharedMemorySize, SPACE_SMEM_BYTES);
        smem_set = 1;
    }

    const int M1 = BB * NN;   // 3138
    const int M2 = BB * SS;   // 3136

    // 0) transpose of K-half of W_pkv (independent of activations)
    transpose_wpkv_kernel<<<(CC * CC + 255) / 256, 256>>>(W_pkv, wT);

    // 1) qkv = x @ W_qkv
    {
        dim3 grid(C3 / GBN, (M1 + GBM - 1) / GBM);
        tf32_gemm_kernel<<<grid, 256>>>(x, W_qkv, qkv, M1, C3, CC, CC, C3, C3,
                                        nullptr, 0, 0, 0, 0);
    }
    // 2) cls attention -> Y row 0 per batch
    cls_attn_kernel<<<BB * HH, 256>>>(qkv, Y);
    // 3) space attention -> traj (tensor cores, 2 blocks/SM)
    space_attn_kernel<<<BB * HH * (SS / SQT), 256, SPACE_SMEM_BYTES>>>(qkv, traj);
    // 4) q2 = xdiag @ W_pq with fused diagonal gather from traj
    {
        dim3 grid(CC / GBN, (M2 + GBM - 1) / GBM);
        tf32_gemm_kernel<<<grid, 256>>>(traj, W_pq, q2, M2, CC, CC, CC, CC, CC,
                                        nullptr, 1, 0, 0, 0);
    }
    // 5) w[bs,h,:] = q2[bs,h-block] @ W_pkv_h^T   (batched over z = head)
    {
        dim3 grid(CC / GBN, (M2 + GBM - 1) / GBM, HH);
        tf32_gemm_kernel<<<grid, 256>>>(q2, wT, w, M2, CC, DD, CC, CC, W12,
                                        nullptr, 0, DD, DD * CC, CC);
    }
    // 6) frame attention (fused logits) -> attn output + Y rows 1..S
    frame_attn_kernel<<<BB * SS, 384>>>(w, traj, Y, out_attn);
    // 7) out = Y @ W_proj + b_proj
    {
        dim3 grid(CC / GBN, (M1 + GBM - 1) / GBM);
        tf32_gemm_kernel<<<grid, 256>>>(Y, W_proj, out_main, M1, CC, CC, CC, CC, CC,
                                        b_proj, 0, 0, 0, 0);
    }
}

// round 9
// speedup vs baseline: 4.0350x; 1.0978x over previous
#include <cuda_runtime.h>
#include <cuda_bf16.h>
#include <math.h>
#include <stdint.h>

// Problem constants
#define BB 2
#define NN 1569          // tokens incl cls
#define CC 768
#define HH 12
#define DD 64
#define PP 196
#define FF 8
#define SS 1568          // F*P
#define C3 2304          // 3*C
#define W12 9216         // 12*768
#define SCALE 0.125f

// ---------------- device scratch (no allocations allowed) ----------------
__device__ float g_qkv[(size_t)BB * NN * C3];          // (B*N, 3C)
__device__ float g_traj[(size_t)BB * SS * FF * CC];    // (B,S,F,C)
__device__ float g_q2[(size_t)BB * SS * CC];           // (B*S, C)
__device__ float g_w[(size_t)BB * SS * W12];           // (B*S, H, C) fused k2 weights
__device__ float g_wT[(size_t)CC * CC];                // W_pkv[:, :CC] transposed: [hd][c]
__device__ float g_Y[(size_t)BB * NN * CC];            // (B*N, C) concat[cls,out]

__device__ __forceinline__ float to_tf32(float x) {
    uint32_t u;
    asm("cvt.rna.tf32.f32 %0, %1;" : "=r"(u) : "f"(x));
    return __uint_as_float(u);
}

__device__ __forceinline__ void mma_tf32(float (&c)[4], const uint32_t (&a)[4], const uint32_t (&b)[2]) {
    asm volatile(
        "mma.sync.aligned.m16n8k8.row.col.f32.tf32.tf32.f32 "
        "{%0,%1,%2,%3}, {%4,%5,%6,%7}, {%8,%9}, {%0,%1,%2,%3};"
        : "+f"(c[0]), "+f"(c[1]), "+f"(c[2]), "+f"(c[3])
        : "r"(a[0]), "r"(a[1]), "r"(a[2]), "r"(a[3]), "r"(b[0]), "r"(b[1]));
}

// ---------------- TF32 tensor-core GEMM, double-buffered ----------------
// C = A(MxK) @ B(KxN) [+bias].  BM=128, BN=128, BK=16, 256 threads (8 warps).
// Warp layout 4(M) x 2(N); warp tile 32x64 (2x8 m16n8k8 fragments).
// Requires: N % 128 == 0, K % 16 == 0. M guarded.
// gather!=0: A row r is read from A + (r*FF + (r%SS)/PP)*lda  (xdiag fusion).
// blockIdx.z batch: A += z*zAcol, B += z*zBoff, C += z*zCcol.
#define GBM 128
#define GBN 128
#define GBK 16
#define AST 136
#define BST 136

__device__ __forceinline__ size_t a_row_off(int gr, int lda, int gather) {
    if (gather) {
        int s = gr % SS;
        gr = gr * FF + s / PP;
    }
    return (size_t)gr * lda;
}

__global__ void tf32_gemm_kernel(const float* __restrict__ A, const float* __restrict__ B,
                                 float* __restrict__ C, int M, int N, int K,
                                 int lda, int ldb, int ldc,
                                 const float* __restrict__ bias, int gather,
                                 int zAcol, int zBoff, int zCcol)
{
    __shared__ float As[2][GBK][AST];   // k-major
    __shared__ float Bs[2][GBK][BST];   // k-major

    const int z = blockIdx.z;
    A += (size_t)z * zAcol;
    B += (size_t)z * zBoff;
    C += (size_t)z * zCcol;

    const int tid  = threadIdx.x;
    const int warp = tid >> 5;
    const int lane = tid & 31;
    const int g = lane >> 2;
    const int q = lane & 3;

    const int warpM = (warp & 3) * 32;
    const int warpN = (warp >> 2) * 64;

    const int by = blockIdx.y * GBM;
    const int bx = blockIdx.x * GBN;

    float acc[2][8][4];
    #pragma unroll
    for (int i = 0; i < 2; i++)
        #pragma unroll
        for (int j = 0; j < 8; j++)
            #pragma unroll
            for (int l = 0; l < 4; l++) acc[i][j][l] = 0.f;

    const int a_row = tid >> 2;
    const int a_col = (tid & 3) << 2;
    const int b_row = tid >> 4;
    const int b_col = (tid & 15) << 2;

    float4 avP[2], bvP[2];
    // prologue: load tile 0
    #pragma unroll
    for (int i = 0; i < 2; i++) {
        int gr = by + a_row + i * 64;
        avP[i] = make_float4(0.f, 0.f, 0.f, 0.f);
        if (gr < M) avP[i] = *(const float4*)(A + a_row_off(gr, lda, gather) + a_col);
    }
    #pragma unroll
    for (int j = 0; j < 2; j++)
        bvP[j] = *(const float4*)(B + (size_t)b_row * ldb + bx + b_col + j * 64);
    {
        #pragma unroll
        for (int i = 0; i < 2; i++) {
            int row = a_row + i * 64;
            As[0][a_col + 0][row] = to_tf32(avP[i].x);
            As[0][a_col + 1][row] = to_tf32(avP[i].y);
            As[0][a_col + 2][row] = to_tf32(avP[i].z);
            As[0][a_col + 3][row] = to_tf32(avP[i].w);
        }
        #pragma unroll
        for (int j = 0; j < 2; j++) {
            Bs[0][b_row][b_col + j * 64 + 0] = to_tf32(bvP[j].x);
            Bs[0][b_row][b_col + j * 64 + 1] = to_tf32(bvP[j].y);
            Bs[0][b_row][b_col + j * 64 + 2] = to_tf32(bvP[j].z);
            Bs[0][b_row][b_col + j * 64 + 3] = to_tf32(bvP[j].w);
        }
    }
    __syncthreads();

    int cur = 0;
    for (int k0 = 0; k0 < K; k0 += GBK) {
        const bool has_next = (k0 + GBK < K);
        if (has_next) {
            #pragma unroll
            for (int i = 0; i < 2; i++) {
                int gr = by + a_row + i * 64;
                avP[i] = make_float4(0.f, 0.f, 0.f, 0.f);
                if (gr < M) avP[i] = *(const float4*)(A + a_row_off(gr, lda, gather) + k0 + GBK + a_col);
            }
            #pragma unroll
            for (int j = 0; j < 2; j++)
                bvP[j] = *(const float4*)(B + (size_t)(k0 + GBK + b_row) * ldb + bx + b_col + j * 64);
        }

        #pragma unroll
        for (int kk = 0; kk < GBK; kk += 8) {
            uint32_t afr[2][4];
            #pragma unroll
            for (int mt = 0; mt < 2; mt++) {
                int r = warpM + mt * 16 + g;
                afr[mt][0] = __float_as_uint(As[cur][kk + q][r]);
                afr[mt][1] = __float_as_uint(As[cur][kk + q][r + 8]);
                afr[mt][2] = __float_as_uint(As[cur][kk + q + 4][r]);
                afr[mt][3] = __float_as_uint(As[cur][kk + q + 4][r + 8]);
            }
            uint32_t bfr[8][2];
            #pragma unroll
            for (int nt = 0; nt < 8; nt++) {
                int c = warpN + nt * 8 + g;
                bfr[nt][0] = __float_as_uint(Bs[cur][kk + q][c]);
                bfr[nt][1] = __float_as_uint(Bs[cur][kk + q + 4][c]);
            }
            #pragma unroll
            for (int mt = 0; mt < 2; mt++)
                #pragma unroll
                for (int nt = 0; nt < 8; nt++)
                    mma_tf32(acc[mt][nt], afr[mt], bfr[nt]);
        }

        if (has_next) {
            int nb = cur ^ 1;
            #pragma unroll
            for (int i = 0; i < 2; i++) {
                int row = a_row + i * 64;
                As[nb][a_col + 0][row] = to_tf32(avP[i].x);
                As[nb][a_col + 1][row] = to_tf32(avP[i].y);
                As[nb][a_col + 2][row] = to_tf32(avP[i].z);
                As[nb][a_col + 3][row] = to_tf32(avP[i].w);
            }
            #pragma unroll
            for (int j = 0; j < 2; j++) {
                Bs[nb][b_row][b_col + j * 64 + 0] = to_tf32(bvP[j].x);
                Bs[nb][b_row][b_col + j * 64 + 1] = to_tf32(bvP[j].y);
                Bs[nb][b_row][b_col + j * 64 + 2] = to_tf32(bvP[j].z);
                Bs[nb][b_row][b_col + j * 64 + 3] = to_tf32(bvP[j].w);
            }
        }
        __syncthreads();
        cur ^= 1;
    }

    #pragma unroll
    for (int mt = 0; mt < 2; mt++) {
        #pragma unroll
        for (int nt = 0; nt < 8; nt++) {
            int col = bx + warpN + nt * 8 + 2 * q;
            float bx0 = 0.f, bx1 = 0.f;
            if (bias) { bx0 = bias[col]; bx1 = bias[col + 1]; }
            int r0 = by + warpM + mt * 16 + g;
            if (r0 < M) {
                float2 o = make_float2(acc[mt][nt][0] + bx0, acc[mt][nt][1] + bx1);
                *(float2*)(C + (size_t)r0 * ldc + col) = o;
            }
            if (r0 + 8 < M) {
                float2 o = make_float2(acc[mt][nt][2] + bx0, acc[mt][nt][3] + bx1);
                *(float2*)(C + (size_t)(r0 + 8) * ldc + col) = o;
            }
        }
    }
}

// ---------------- W_pkv[:, :CC] transpose: wT[hd][c] = W_pkv[c][hd] ------
__global__ void transpose_wpkv_kernel(const float* __restrict__ W_pkv, float* __restrict__ wT)
{
    int idx = blockIdx.x * 256 + threadIdx.x;
    if (idx >= CC * CC) return;
    int hd = idx / CC, c = idx % CC;
    wT[(size_t)hd * CC + c] = W_pkv[(size_t)c * (2 * CC) + hd];
}

// ---------------- cls attention: 24 blocks (b,h) ----------------
__global__ void cls_attn_kernel(const float* __restrict__ qkv, float* __restrict__ Y)
{
    const int b = blockIdx.x / HH;
    const int h = blockIdx.x % HH;
    const int tid = threadIdx.x;

    __shared__ float qs[DD];
    __shared__ float sc[NN];
    __shared__ float red[256];
    __shared__ float part4[4][DD];

    if (tid < DD) qs[tid] = qkv[(size_t)(b * NN) * C3 + h * DD + tid];
    __syncthreads();

    for (int i = tid; i < NN; i += 256) {
        const float* kr = qkv + (size_t)(b * NN + i) * C3 + CC + h * DD;
        float dot = 0.f;
        for (int d = 0; d < DD; d += 4) {
            float4 k4 = *(const float4*)(kr + d);
            dot += qs[d] * k4.x + qs[d + 1] * k4.y + qs[d + 2] * k4.z + qs[d + 3] * k4.w;
        }
        sc[i] = dot * SCALE;
    }
    __syncthreads();

    float m = -1e30f;
    for (int i = tid; i < NN; i += 256) m = fmaxf(m, sc[i]);
    red[tid] = m; __syncthreads();
    for (int o = 128; o; o >>= 1) { if (tid < o) red[tid] = fmaxf(red[tid], red[tid + o]); __syncthreads(); }
    m = red[0];
    __syncthreads();

    float z = 0.f;
    for (int i = tid; i < NN; i += 256) { float e = __expf(sc[i] - m); sc[i] = e; z += e; }
    red[tid] = z; __syncthreads();
    for (int o = 128; o; o >>= 1) { if (tid < o) red[tid] += red[tid + o]; __syncthreads(); }
    float inv = 1.f / red[0];
    __syncthreads();

    int d = tid & 63, part = tid >> 6;
    float acc = 0.f;
    for (int i = part; i < NN; i += 4)
        acc += sc[i] * qkv[(size_t)(b * NN + i) * C3 + 2 * CC + h * DD + d];
    part4[part][d] = acc;
    __syncthreads();
    if (tid < DD)
        Y[(size_t)(b * NN) * CC + h * DD + tid] =
            (part4[0][tid] + part4[1][tid] + part4[2][tid] + part4[3][tid]) * inv;
}

// ---------------- tensor-core space attention -> traj -------------------
// SQT=32 queries/block, 256 threads (8 warps), grid = B*H*49.
// Single K/V buffer (~107KB smem total) -> 2 blocks/SM, 16 warps/SM.
// Computes scores^T = K @ Q^T so K and V stay in natural layout.
#define SQT 32
#define BUF_LD 76
#define SC_LD 40
#define QT_LD 40
#define BUF_OFF 0
#define SC_OFF (208 * BUF_LD)                     // 15808
#define QT_OFF (SC_OFF + 208 * SC_LD)             // 24128
#define SPACE_SMEM_FLOATS (QT_OFF + 64 * QT_LD)   // 26688
#define SPACE_SMEM_BYTES (SPACE_SMEM_FLOATS * 4)  // 106752

__global__ void space_attn_kernel(const float* __restrict__ qkv, float* __restrict__ traj)
{
    extern __shared__ float smem[];
    float* Buf = smem + BUF_OFF;  // [208][76] K then V, natural [n][d]
    float* Sc  = smem + SC_OFF;   // [208][40] scores^T [n][q]
    float* Qt  = smem + QT_OFF;   // [64][40]  Q^T [d][q]

    const int nt_blocks = SS / SQT;    // 49
    const int bh = blockIdx.x / nt_blocks;
    const int st = blockIdx.x % nt_blocks;
    const int b = bh / HH;
    const int h = bh % HH;
    const int s0 = st * SQT;
    const int tid = threadIdx.x;
    const int warp = tid >> 5;
    const int lane = tid & 31;
    const int g = lane >> 2;
    const int q = lane & 3;

    // ---- load Q transposed: Qt[d][q] (tf32) ----
    for (int idx = tid; idx < SQT * 16; idx += 256) {
        int row = idx >> 4, d4 = (idx & 15) << 2;
        float4 qv = *(const float4*)(qkv + (size_t)(b * NN + 1 + s0 + row) * C3 + h * DD + d4);
        Qt[(d4 + 0) * QT_LD + row] = to_tf32(qv.x);
        Qt[(d4 + 1) * QT_LD + row] = to_tf32(qv.y);
        Qt[(d4 + 2) * QT_LD + row] = to_tf32(qv.z);
        Qt[(d4 + 3) * QT_LD + row] = to_tf32(qv.w);
    }

    for (int f = 0; f < FF; f++) {
        __syncthreads();   // prev frame PV done reading Buf/Sc (covers Qt on first iter)

        // ---- load K frame into Buf (natural layout, tf32) ----
        const size_t frameRow = (size_t)(b * NN + 1 + f * PP);
        for (int idx = tid; idx < PP * 16; idx += 256) {
            int n = idx >> 4, d4 = (idx & 15) << 2;
            float4 kv = *(const float4*)(qkv + (frameRow + n) * C3 + CC + h * DD + d4);
            float* dst = &Buf[n * BUF_LD + d4];
            dst[0] = to_tf32(kv.x); dst[1] = to_tf32(kv.y);
            dst[2] = to_tf32(kv.z); dst[3] = to_tf32(kv.w);
        }
        __syncthreads();

        // ---- QK: Sc^T(208x32) = K(208x64) @ Qt ----
        // warp handles m-tiles {warp, warp+8}; b-frags hoisted over m-tiles.
        {
            const int mt0 = warp;            // 0..7, always valid (<13)
            const int mt1 = warp + 8;        // valid when < 13 (warps 0..4)
            const int m0 = mt0 * 16;
            const int m1 = mt1 * 16;
            const bool has1 = (mt1 < 13);
            float acc0[4][4], acc1[4][4];
            #pragma unroll
            for (int i = 0; i < 4; i++)
                #pragma unroll
                for (int j = 0; j < 4; j++) { acc0[i][j] = 0.f; acc1[i][j] = 0.f; }
            #pragma unroll
            for (int kb = 0; kb < 8; kb++) {
                const int k0 = kb * 8;
                uint32_t bfr[4][2];
                #pragma unroll
                for (int nt = 0; nt < 4; nt++) {
                    bfr[nt][0] = __float_as_uint(Qt[(k0 + q) * QT_LD + nt * 8 + g]);
                    bfr[nt][1] = __float_as_uint(Qt[(k0 + q + 4) * QT_LD + nt * 8 + g]);
                }
                uint32_t a[4];
                a[0] = __float_as_uint(Buf[(m0 + g) * BUF_LD + k0 + q]);
                a[1] = __float_as_uint(Buf[(m0 + 8 + g) * BUF_LD + k0 + q]);
                a[2] = __float_as_uint(Buf[(m0 + g) * BUF_LD + k0 + q + 4]);
                a[3] = __float_as_uint(Buf[(m0 + 8 + g) * BUF_LD + k0 + q + 4]);
                #pragma unroll
                for (int nt = 0; nt < 4; nt++) mma_tf32(acc0[nt], a, bfr[nt]);
                if (has1) {
                    uint32_t a1[4];
                    a1[0] = __float_as_uint(Buf[(m1 + g) * BUF_LD + k0 + q]);
                    a1[1] = __float_as_uint(Buf[(m1 + 8 + g) * BUF_LD + k0 + q]);
                    a1[2] = __float_as_uint(Buf[(m1 + g) * BUF_LD + k0 + q + 4]);
                    a1[3] = __float_as_uint(Buf[(m1 + 8 + g) * BUF_LD + k0 + q + 4]);
                    #pragma unroll
                    for (int nt = 0; nt < 4; nt++) mma_tf32(acc1[nt], a1, bfr[nt]);
                }
            }
            #pragma unroll
            for (int nt = 0; nt < 4; nt++) {
                int c0 = nt * 8 + 2 * q;
                *(float2*)&Sc[(m0 + g) * SC_LD + c0] =
                    make_float2(acc0[nt][0] * SCALE, acc0[nt][1] * SCALE);
                *(float2*)&Sc[(m0 + 8 + g) * SC_LD + c0] =
                    make_float2(acc0[nt][2] * SCALE, acc0[nt][3] * SCALE);
            }
            if (has1) {
                #pragma unroll
                for (int nt = 0; nt < 4; nt++) {
                    int c0 = nt * 8 + 2 * q;
                    *(float2*)&Sc[(m1 + g) * SC_LD + c0] =
                        make_float2(acc1[nt][0] * SCALE, acc1[nt][1] * SCALE);
                    *(float2*)&Sc[(m1 + 8 + g) * SC_LD + c0] =
                        make_float2(acc1[nt][2] * SCALE, acc1[nt][3] * SCALE);
                }
            }
        }
        __syncthreads();   // QK done reading Buf(K) & writing Sc

        // ---- load V frame over Buf; then softmax on Sc ----
        for (int idx = tid; idx < PP * 16; idx += 256) {
            int n = idx >> 4, d4 = (idx & 15) << 2;
            float4 vv = *(const float4*)(qkv + (frameRow + n) * C3 + 2 * CC + h * DD + d4);
            float* dst = &Buf[n * BUF_LD + d4];
            dst[0] = to_tf32(vv.x); dst[1] = to_tf32(vv.y);
            dst[2] = to_tf32(vv.z); dst[3] = to_tf32(vv.w);
        }
        // zero V pad rows 196..199 (cols 0..63)
        {
            int n = 196 + (tid >> 6), d = tid & 63;
            Buf[n * BUF_LD + d] = 0.f;
        }
        // softmax down columns (8 lanes per query column)
        {
            const int col = tid >> 3, r = tid & 7;
            float m = -1e30f;
            for (int n = r; n < PP; n += 8) m = fmaxf(m, Sc[n * SC_LD + col]);
            #pragma unroll
            for (int o = 4; o; o >>= 1) m = fmaxf(m, __shfl_xor_sync(0xffffffffu, m, o));
            float z = 0.f;
            for (int n = r; n < PP; n += 8) {
                float e = __expf(Sc[n * SC_LD + col] - m);
                Sc[n * SC_LD + col] = e;
                z += e;
            }
            #pragma unroll
            for (int o = 4; o; o >>= 1) z += __shfl_xor_sync(0xffffffffu, z, o);
            float inv = 1.f / z;
            for (int n = r; n < PP; n += 8)
                Sc[n * SC_LD + col] = to_tf32(Sc[n * SC_LD + col] * inv);
        }
        // zero P pad rows 196..199
        if (tid < 128) Sc[(196 + (tid >> 5)) * SC_LD + (tid & 31)] = 0.f;
        __syncthreads();

        // ---- PV: out(32x64) = P(32x200) @ V(200x64) ----
        {
            const int mt = warp & 1;       // query tile
            const int ng = warp >> 1;      // owns d-tiles 2*ng, 2*ng+1
            const int m0 = mt * 16;
            float acc[2][4];
            #pragma unroll
            for (int j = 0; j < 2; j++)
                #pragma unroll
                for (int l = 0; l < 4; l++) acc[j][l] = 0.f;
            for (int kb = 0; kb < 25; kb++) {
                const int k0 = kb * 8;
                uint32_t a[4];
                a[0] = __float_as_uint(Sc[(k0 + q) * SC_LD + m0 + g]);
                a[1] = __float_as_uint(Sc[(k0 + q) * SC_LD + m0 + 8 + g]);
                a[2] = __float_as_uint(Sc[(k0 + q + 4) * SC_LD + m0 + g]);
                a[3] = __float_as_uint(Sc[(k0 + q + 4) * SC_LD + m0 + 8 + g]);
                #pragma unroll
                for (int j = 0; j < 2; j++) {
                    const int d0 = (ng * 2 + j) * 8;
                    uint32_t bfr[2];
                    bfr[0] = __float_as_uint(Buf[(k0 + q) * BUF_LD + d0 + g]);
                    bfr[1] = __float_as_uint(Buf[(k0 + q + 4) * BUF_LD + d0 + g]);
                    mma_tf32(acc[j], a, bfr);
                }
            }
            #pragma unroll
            for (int j = 0; j < 2; j++) {
                const int d0 = (ng * 2 + j) * 8;
                const int col = h * DD + d0 + 2 * q;
                const int row0 = s0 + m0 + g;
                *(float2*)(traj + ((size_t)(b * SS + row0) * FF + f) * CC + col) =
                    make_float2(acc[j][0], acc[j][1]);
                *(float2*)(traj + ((size_t)(b * SS + row0 + 8) * FF + f) * CC + col) =
                    make_float2(acc[j][2], acc[j][3]);
            }
        }
    }
}

// ---------------- frame attention (fused logits) ----------------
// grid = B*S, 384 threads (12 warps = 12 heads).
__global__ void frame_attn_kernel(const float* __restrict__ w, const float* __restrict__ traj,
                                  float* __restrict__ Y, float* __restrict__ attn_out)
{
    const int bs = blockIdx.x;
    const int b = bs / SS;
    const int s = bs % SS;
    const int tid = threadIdx.x;
    const int h = tid >> 5;      // warp = head
    const int lane = tid & 31;

    __shared__ float ts[FF][CC];
    __shared__ float a_sm[HH][FF];

    for (int idx = tid; idx < FF * CC / 4; idx += 384) {
        int f = idx / 192, j = idx % 192;
        float4 v = *(const float4*)(traj + ((size_t)bs * FF + f) * CC + j * 4);
        *(float4*)&ts[f][j * 4] = v;
    }
    __syncthreads();

    const float* wrow = w + (size_t)bs * W12 + h * CC;
    float wreg[24];
    #pragma unroll
    for (int j = 0; j < 24; j++) wreg[j] = wrow[lane + 32 * j];

    float lg[FF];
    #pragma unroll
    for (int f = 0; f < FF; f++) {
        float dsum = 0.f;
        #pragma unroll
        for (int j = 0; j < 24; j++) dsum += wreg[j] * ts[f][lane + 32 * j];
        #pragma unroll
        for (int o = 16; o; o >>= 1) dsum += __shfl_xor_sync(0xffffffffu, dsum, o);
        lg[f] = dsum * SCALE;
    }
    float m = -1e30f;
    #pragma unroll
    for (int f = 0; f < FF; f++) m = fmaxf(m, lg[f]);
    float z = 0.f;
    #pragma unroll
    for (int f = 0; f < FF; f++) { lg[f] = __expf(lg[f] - m); z += lg[f]; }
    float inv = 1.f / z;
    #pragma unroll
    for (int f = 0; f < FF; f++) lg[f] *= inv;

    if (lane < FF) {
        a_sm[h][lane] = lg[lane];
        attn_out[(((size_t)b * HH + h) * SS + s) * FF + lane] = lg[lane];
    }
    __syncthreads();

    #pragma unroll
    for (int rep = 0; rep < 2; rep++) {
        int c = tid + rep * 384;
        int h2 = c >> 6;
        float o = 0.f;
        #pragma unroll
        for (int f = 0; f < FF; f++) o += a_sm[h2][f] * ts[f][c];
        Y[(size_t)(b * NN + 1 + s) * CC + c] = o;
    }
}

// ---------------- launcher ----------------
extern "C" void kernel_launch(void* const* d_in, const int* in_sizes, int n_in,
                              void* d_out, int out_size)
{
    const float* x      = (const float*)d_in[0];
    const float* W_qkv  = (const float*)d_in[1];
    const float* W_pq   = (const float*)d_in[2];
    const float* W_pkv  = (const float*)d_in[3];
    const float* W_proj = (const float*)d_in[4];
    const float* b_proj = (const float*)d_in[5];
    (void)in_sizes; (void)n_in;

    float *qkv, *traj, *q2, *w, *wT, *Y;
    cudaGetSymbolAddress((void**)&qkv,  g_qkv);
    cudaGetSymbolAddress((void**)&traj, g_traj);
    cudaGetSymbolAddress((void**)&q2,   g_q2);
    cudaGetSymbolAddress((void**)&w,    g_w);
    cudaGetSymbolAddress((void**)&wT,   g_wT);
    cudaGetSymbolAddress((void**)&Y,    g_Y);

    float* out_main = (float*)d_out;                                   // (B,N,C)
    float* out_attn = out_main + (size_t)BB * NN * CC;                 // (B,h,S,F)

    static int smem_set = 0;
    if (!smem_set) {
        cudaFuncSetAttribute(space_attn_kernel,
                             cudaFuncAttributeMaxDynamicSharedMemorySize, SPACE_SMEM_BYTES);
        smem_set = 1;
    }

    const int M1 = BB * NN;   // 3138
    const int M2 = BB * SS;   // 3136

    // 0) transpose of K-half of W_pkv (independent of activations)
    transpose_wpkv_kernel<<<(CC * CC + 255) / 256, 256>>>(W_pkv, wT);

    // 1) qkv = x @ W_qkv
    {
        dim3 grid(C3 / GBN, (M1 + GBM - 1) / GBM);
        tf32_gemm_kernel<<<grid, 256>>>(x, W_qkv, qkv, M1, C3, CC, CC, C3, C3,
                                        nullptr, 0, 0, 0, 0);
    }
    // 2) cls attention -> Y row 0 per batch
    cls_attn_kernel<<<BB * HH, 256>>>(qkv, Y);
    // 3) space attention -> traj (tensor cores, 2 blocks/SM)
    space_attn_kernel<<<BB * HH * (SS / SQT), 256, SPACE_SMEM_BYTES>>>(qkv, traj);
    // 4) q2 = xdiag @ W_pq with fused diagonal gather from traj
    {
        dim3 grid(CC / GBN, (M2 + GBM - 1) / GBM);
        tf32_gemm_kernel<<<grid, 256>>>(traj, W_pq, q2, M2, CC, CC, CC, CC, CC,
                                        nullptr, 1, 0, 0, 0);
    }
    // 5) w[bs,h,:] = q2[bs,h-block] @ W_pkv_h^T   (batched over z = head)
    {
        dim3 grid(CC / GBN, (M2 + GBM - 1) / GBM, HH);
        tf32_gemm_kernel<<<grid, 256>>>(q2, wT, w, M2, CC, DD, CC, CC, W12,
                                        nullptr, 0, DD, DD * CC, CC);
    }
    // 6) frame attention (fused logits) -> attn output + Y rows 1..S
    frame_attn_kernel<<<BB * SS, 384>>>(w, traj, Y, out_attn);
    // 7) out = Y @ W_proj + b_proj
    {
        dim3 grid(CC / GBN, (M1 + GBM - 1) / GBM);
        tf32_gemm_kernel<<<grid, 256>>>(Y, W_proj, out_main, M1, CC, CC, CC, CC, CC,
                                        b_proj, 0, 0, 0, 0);
    }
}

// round 10
// speedup vs baseline: 4.2516x; 1.0537x over previous
#include <cuda_runtime.h>
#include <cuda_bf16.h>
#include <math.h>
#include <stdint.h>

// Problem constants
#define BB 2
#define NN 1569          // tokens incl cls
#define CC 768
#define HH 12
#define DD 64
#define PP 196
#define FF 8
#define SS 1568          // F*P
#define C3 2304          // 3*C
#define W12 9216         // 12*768
#define SCALE 0.125f

// ---------------- device scratch (no allocations allowed) ----------------
__device__ float g_qkv[(size_t)BB * NN * C3];          // (B*N, 3C)
__device__ float g_traj[(size_t)BB * SS * FF * CC];    // (B,S,F,C)
__device__ float g_q2[(size_t)BB * SS * CC];           // (B*S, C)
__device__ float g_w[(size_t)BB * SS * W12];           // (B*S, H, C) fused k2 weights
__device__ float g_wT[(size_t)CC * CC];                // W_pkv[:, :CC]^T (tf32)
__device__ float g_Y[(size_t)BB * NN * CC];            // (B*N, C) concat[cls,out]
__device__ float g_x[(size_t)BB * NN * CC];            // tf32-rounded x
__device__ float g_wq[(size_t)CC * C3];                // tf32-rounded W_qkv
__device__ float g_wpq[(size_t)CC * CC];               // tf32-rounded W_pq
__device__ float g_wproj[(size_t)CC * CC];             // tf32-rounded W_proj

__device__ __forceinline__ float to_tf32(float x) {
    uint32_t u;
    asm("cvt.rna.tf32.f32 %0, %1;" : "=r"(u) : "f"(x));
    return __uint_as_float(u);
}

__device__ __forceinline__ void mma_tf32(float (&c)[4], const uint32_t (&a)[4], const uint32_t (&b)[2]) {
    asm volatile(
        "mma.sync.aligned.m16n8k8.row.col.f32.tf32.tf32.f32 "
        "{%0,%1,%2,%3}, {%4,%5,%6,%7}, {%8,%9}, {%0,%1,%2,%3};"
        : "+f"(c[0]), "+f"(c[1]), "+f"(c[2]), "+f"(c[3])
        : "r"(a[0]), "r"(a[1]), "r"(a[2]), "r"(a[3]), "r"(b[0]), "r"(b[1]));
}

__device__ __forceinline__ void cp16(uint32_t dst, const void* src) {
    asm volatile("cp.async.cg.shared.global [%0], [%1], 16;" :: "r"(dst), "l"(src));
}
__device__ __forceinline__ void cp16z(uint32_t dst, const void* src, int sz) {
    asm volatile("cp.async.cg.shared.global [%0], [%1], 16, %2;" :: "r"(dst), "l"(src), "r"(sz));
}
#define CP_COMMIT() asm volatile("cp.async.commit_group;")
#define CP_WAIT0()  asm volatile("cp.async.wait_group 0;")

// ---------------- input tf32-rounding prep ----------------
#define XSZ  (BB * NN * CC)    // 2409984
#define WQSZ (CC * C3)         // 1769472
#define WPSZ (CC * CC)         // 589824
__global__ void round_inputs_kernel(const float* __restrict__ x, const float* __restrict__ Wq,
                                    const float* __restrict__ Wpq, const float* __restrict__ Wpr,
                                    float* __restrict__ rx, float* __restrict__ rwq,
                                    float* __restrict__ rwpq, float* __restrict__ rwpr)
{
    const int T4 = (XSZ + WQSZ + 2 * WPSZ) / 4;
    int idx4 = blockIdx.x * 256 + threadIdx.x;
    if (idx4 >= T4) return;
    int i = idx4 * 4;
    const float* s; float* d; int off;
    if (i < XSZ)                    { s = x;   d = rx;   off = i; }
    else if (i < XSZ + WQSZ)        { s = Wq;  d = rwq;  off = i - XSZ; }
    else if (i < XSZ + WQSZ + WPSZ) { s = Wpq; d = rwpq; off = i - XSZ - WQSZ; }
    else                            { s = Wpr; d = rwpr; off = i - XSZ - WQSZ - WPSZ; }
    float4 v = *(const float4*)(s + off);
    v.x = to_tf32(v.x); v.y = to_tf32(v.y); v.z = to_tf32(v.z); v.w = to_tf32(v.w);
    *(float4*)(d + off) = v;
}

// ---------------- TF32 tensor-core GEMM, cp.async double-buffered ----------
// C = A(MxK) @ B(KxN) [+bias].  BM=128, BN=128, BK=16, 256 threads (8 warps).
// A tile row-major [128][A_LD]; B tile k-major [16][B_LD].
// Inputs must be pre-rounded tf32 (mma truncation is then exact).
// gather!=0: A row r read from A + (r*FF + (r%SS)/PP)*lda.
// round_out!=0: outputs rounded to tf32 (for mma consumers downstream).
#define GBM 128
#define GBN 128
#define GBK 16
#define A_LD 20
#define B_LD 136

__device__ __forceinline__ size_t a_row_off(int gr, int lda, int gather) {
    if (gather) {
        int s = gr % SS;
        gr = gr * FF + s / PP;
    }
    return (size_t)gr * lda;
}

__global__ void tf32_gemm_kernel(const float* __restrict__ A, const float* __restrict__ B,
                                 float* __restrict__ C, int M, int N, int K,
                                 int lda, int ldb, int ldc,
                                 const float* __restrict__ bias, int gather, int round_out,
                                 int zAcol, int zBoff, int zCcol)
{
    __shared__ float As[2][GBM][A_LD];   // row-major
    __shared__ float Bs[2][GBK][B_LD];   // k-major

    const int z = blockIdx.z;
    A += (size_t)z * zAcol;
    B += (size_t)z * zBoff;
    C += (size_t)z * zCcol;

    const int tid  = threadIdx.x;
    const int warp = tid >> 5;
    const int lane = tid & 31;
    const int g = lane >> 2;
    const int q = lane & 3;
    const int warpM = (warp & 3) * 32;
    const int warpN = (warp >> 2) * 64;
    const int by = blockIdx.y * GBM;
    const int bx = blockIdx.x * GBN;

    float acc[2][8][4];
    #pragma unroll
    for (int i = 0; i < 2; i++)
        #pragma unroll
        for (int j = 0; j < 8; j++)
            #pragma unroll
            for (int l = 0; l < 4; l++) acc[i][j][l] = 0.f;

    // A copy mapping: row = tid&127, col-groups {cg0, cg0+2} (cg0 = tid>>7)
    const int ar = tid & 127;
    const int cg0 = tid >> 7;          // 0 or 1
    const int gr = by + ar;
    const int asz = (gr < M) ? 16 : 0;
    const float* ap = A + a_row_off(gr < M ? gr : M - 1, lda, gather);
    // B copy mapping: row = tid>>4, cols b_col and b_col+64
    const int br = tid >> 4;
    const int bc = (tid & 15) << 2;
    const float* bp = B + (size_t)br * ldb + bx + bc;

    uint32_t sA = (uint32_t)__cvta_generic_to_shared(&As[0][ar][0]);
    uint32_t sB = (uint32_t)__cvta_generic_to_shared(&Bs[0][br][bc]);
    const uint32_t stA = sizeof(float) * GBM * A_LD;
    const uint32_t stB = sizeof(float) * GBK * B_LD;

    // prologue: stage 0
    cp16z(sA + (cg0 * 4) * 4, ap + cg0 * 4, asz);
    cp16z(sA + ((cg0 + 2) * 4) * 4, ap + (cg0 + 2) * 4, asz);
    cp16(sB, bp);
    cp16(sB + 64 * 4, bp + 64);
    CP_COMMIT();

    int cur = 0;
    for (int k0 = 0; k0 < K; k0 += GBK) {
        CP_WAIT0();
        __syncthreads();
        if (k0 + GBK < K) {
            uint32_t oA = (cur ^ 1) * stA, oB = (cur ^ 1) * stB;
            cp16z(sA + oA + (cg0 * 4) * 4, ap + k0 + GBK + cg0 * 4, asz);
            cp16z(sA + oA + ((cg0 + 2) * 4) * 4, ap + k0 + GBK + (cg0 + 2) * 4, asz);
            cp16(sB + oB, bp + (size_t)(k0 + GBK) * ldb);
            cp16(sB + oB + 64 * 4, bp + (size_t)(k0 + GBK) * ldb + 64);
            CP_COMMIT();
        }

        #pragma unroll
        for (int kk = 0; kk < GBK; kk += 8) {
            uint32_t afr[2][4];
            #pragma unroll
            for (int mt = 0; mt < 2; mt++) {
                int r = warpM + mt * 16 + g;
                afr[mt][0] = __float_as_uint(As[cur][r][kk + q]);
                afr[mt][1] = __float_as_uint(As[cur][r + 8][kk + q]);
                afr[mt][2] = __float_as_uint(As[cur][r][kk + q + 4]);
                afr[mt][3] = __float_as_uint(As[cur][r + 8][kk + q + 4]);
            }
            uint32_t bfr[8][2];
            #pragma unroll
            for (int nt = 0; nt < 8; nt++) {
                int c = warpN + nt * 8 + g;
                bfr[nt][0] = __float_as_uint(Bs[cur][kk + q][c]);
                bfr[nt][1] = __float_as_uint(Bs[cur][kk + q + 4][c]);
            }
            #pragma unroll
            for (int mt = 0; mt < 2; mt++)
                #pragma unroll
                for (int nt = 0; nt < 8; nt++)
                    mma_tf32(acc[mt][nt], afr[mt], bfr[nt]);
        }
        cur ^= 1;
    }

    #pragma unroll
    for (int mt = 0; mt < 2; mt++) {
        #pragma unroll
        for (int nt = 0; nt < 8; nt++) {
            int col = bx + warpN + nt * 8 + 2 * q;
            float bx0 = 0.f, bx1 = 0.f;
            if (bias) { bx0 = bias[col]; bx1 = bias[col + 1]; }
            int r0 = by + warpM + mt * 16 + g;
            float v0 = acc[mt][nt][0] + bx0, v1 = acc[mt][nt][1] + bx1;
            float v2 = acc[mt][nt][2] + bx0, v3 = acc[mt][nt][3] + bx1;
            if (round_out) {
                v0 = to_tf32(v0); v1 = to_tf32(v1); v2 = to_tf32(v2); v3 = to_tf32(v3);
            }
            if (r0 < M)     *(float2*)(C + (size_t)r0 * ldc + col) = make_float2(v0, v1);
            if (r0 + 8 < M) *(float2*)(C + (size_t)(r0 + 8) * ldc + col) = make_float2(v2, v3);
        }
    }
}

// ---------------- W_pkv[:, :CC] transpose (tf32-rounded) ----------------
__global__ void transpose_wpkv_kernel(const float* __restrict__ W_pkv, float* __restrict__ wT)
{
    int idx = blockIdx.x * 256 + threadIdx.x;
    if (idx >= CC * CC) return;
    int hd = idx / CC, c = idx % CC;
    wT[(size_t)hd * CC + c] = to_tf32(W_pkv[(size_t)c * (2 * CC) + hd]);
}

// ---------------- cls attention: 24 blocks (b,h) ----------------
__global__ void cls_attn_kernel(const float* __restrict__ qkv, float* __restrict__ Y)
{
    const int b = blockIdx.x / HH;
    const int h = blockIdx.x % HH;
    const int tid = threadIdx.x;

    __shared__ float qs[DD];
    __shared__ float sc[NN];
    __shared__ float red[256];
    __shared__ float part4[4][DD];

    if (tid < DD) qs[tid] = qkv[(size_t)(b * NN) * C3 + h * DD + tid];
    __syncthreads();

    for (int i = tid; i < NN; i += 256) {
        const float* kr = qkv + (size_t)(b * NN + i) * C3 + CC + h * DD;
        float dot = 0.f;
        for (int d = 0; d < DD; d += 4) {
            float4 k4 = *(const float4*)(kr + d);
            dot += qs[d] * k4.x + qs[d + 1] * k4.y + qs[d + 2] * k4.z + qs[d + 3] * k4.w;
        }
        sc[i] = dot * SCALE;
    }
    __syncthreads();

    float m = -1e30f;
    for (int i = tid; i < NN; i += 256) m = fmaxf(m, sc[i]);
    red[tid] = m; __syncthreads();
    for (int o = 128; o; o >>= 1) { if (tid < o) red[tid] = fmaxf(red[tid], red[tid + o]); __syncthreads(); }
    m = red[0];
    __syncthreads();

    float z = 0.f;
    for (int i = tid; i < NN; i += 256) { float e = __expf(sc[i] - m); sc[i] = e; z += e; }
    red[tid] = z; __syncthreads();
    for (int o = 128; o; o >>= 1) { if (tid < o) red[tid] += red[tid + o]; __syncthreads(); }
    float inv = 1.f / red[0];
    __syncthreads();

    int d = tid & 63, part = tid >> 6;
    float acc = 0.f;
    for (int i = part; i < NN; i += 4)
        acc += sc[i] * qkv[(size_t)(b * NN + i) * C3 + 2 * CC + h * DD + d];
    part4[part][d] = acc;
    __syncthreads();
    if (tid < DD)
        Y[(size_t)(b * NN) * CC + h * DD + tid] =
            to_tf32((part4[0][tid] + part4[1][tid] + part4[2][tid] + part4[3][tid]) * inv);
}

// ---------------- tensor-core space attention -> traj -------------------
// SQT=32 queries/block, 256 threads, grid = B*H*49, ~107KB smem -> 2 blocks/SM.
// K/V frames via cp.async; PV uses 4 warps with 1 m-tile x 4 d-tiles each.
#define SQT 32
#define BUF_LD 76
#define SC_LD 40
#define QT_LD 40
#define BUF_OFF 0
#define SC_OFF (208 * BUF_LD)                     // 15808
#define QT_OFF (SC_OFF + 208 * SC_LD)             // 24128
#define SPACE_SMEM_FLOATS (QT_OFF + 64 * QT_LD)   // 26688
#define SPACE_SMEM_BYTES (SPACE_SMEM_FLOATS * 4)  // 106752

__global__ void space_attn_kernel(const float* __restrict__ qkv, float* __restrict__ traj)
{
    extern __shared__ float smem[];
    float* Buf = smem + BUF_OFF;  // [208][76] K then V, natural [n][d]
    float* Sc  = smem + SC_OFF;   // [208][40] scores^T [n][q]
    float* Qt  = smem + QT_OFF;   // [64][40]  Q^T [d][q]
    const uint32_t sBuf = (uint32_t)__cvta_generic_to_shared(Buf);

    const int nt_blocks = SS / SQT;    // 49
    const int bh = blockIdx.x / nt_blocks;
    const int st = blockIdx.x % nt_blocks;
    const int b = bh / HH;
    const int h = bh % HH;
    const int s0 = st * SQT;
    const int tid = threadIdx.x;
    const int warp = tid >> 5;
    const int lane = tid & 31;
    const int g = lane >> 2;
    const int q = lane & 3;

    // ---- load Q transposed (qkv already tf32-exact) ----
    for (int idx = tid; idx < SQT * 16; idx += 256) {
        int row = idx >> 4, d4 = (idx & 15) << 2;
        float4 qv = *(const float4*)(qkv + (size_t)(b * NN + 1 + s0 + row) * C3 + h * DD + d4);
        Qt[(d4 + 0) * QT_LD + row] = qv.x;
        Qt[(d4 + 1) * QT_LD + row] = qv.y;
        Qt[(d4 + 2) * QT_LD + row] = qv.z;
        Qt[(d4 + 3) * QT_LD + row] = qv.w;
    }
    // zero Buf pad rows 196..199 once (never touched by cp.async)
    {
        int n = 196 + (tid >> 6), d = tid & 63;
        Buf[n * BUF_LD + d] = 0.f;
    }

    for (int f = 0; f < FF; f++) {
        __syncthreads();   // prev frame PV done reading Buf/Sc (covers Qt/pad first iter)

        const size_t frameRow = (size_t)(b * NN + 1 + f * PP);
        // ---- K frame via cp.async ----
        for (int idx = tid; idx < PP * 16; idx += 256) {
            int n = idx >> 4, d4 = (idx & 15) << 2;
            cp16(sBuf + (uint32_t)(n * BUF_LD + d4) * 4u,
                 qkv + (frameRow + n) * C3 + CC + h * DD + d4);
        }
        CP_COMMIT();
        CP_WAIT0();
        __syncthreads();

        // ---- QK: Sc^T(208x32) = K(208x64) @ Qt; b-frags hoisted ----
        {
            const int mt0 = warp;
            const int mt1 = warp + 8;
            const int m0 = mt0 * 16;
            const int m1 = mt1 * 16;
            const bool has1 = (mt1 < 13);
            float acc0[4][4], acc1[4][4];
            #pragma unroll
            for (int i = 0; i < 4; i++)
                #pragma unroll
                for (int j = 0; j < 4; j++) { acc0[i][j] = 0.f; acc1[i][j] = 0.f; }
            #pragma unroll
            for (int kb = 0; kb < 8; kb++) {
                const int k0 = kb * 8;
                uint32_t bfr[4][2];
                #pragma unroll
                for (int nt = 0; nt < 4; nt++) {
                    bfr[nt][0] = __float_as_uint(Qt[(k0 + q) * QT_LD + nt * 8 + g]);
                    bfr[nt][1] = __float_as_uint(Qt[(k0 + q + 4) * QT_LD + nt * 8 + g]);
                }
                uint32_t a[4];
                a[0] = __float_as_uint(Buf[(m0 + g) * BUF_LD + k0 + q]);
                a[1] = __float_as_uint(Buf[(m0 + 8 + g) * BUF_LD + k0 + q]);
                a[2] = __float_as_uint(Buf[(m0 + g) * BUF_LD + k0 + q + 4]);
                a[3] = __float_as_uint(Buf[(m0 + 8 + g) * BUF_LD + k0 + q + 4]);
                #pragma unroll
                for (int nt = 0; nt < 4; nt++) mma_tf32(acc0[nt], a, bfr[nt]);
                if (has1) {
                    uint32_t a1[4];
                    a1[0] = __float_as_uint(Buf[(m1 + g) * BUF_LD + k0 + q]);
                    a1[1] = __float_as_uint(Buf[(m1 + 8 + g) * BUF_LD + k0 + q]);
                    a1[2] = __float_as_uint(Buf[(m1 + g) * BUF_LD + k0 + q + 4]);
                    a1[3] = __float_as_uint(Buf[(m1 + 8 + g) * BUF_LD + k0 + q + 4]);
                    #pragma unroll
                    for (int nt = 0; nt < 4; nt++) mma_tf32(acc1[nt], a1, bfr[nt]);
                }
            }
            #pragma unroll
            for (int nt = 0; nt < 4; nt++) {
                int c0 = nt * 8 + 2 * q;
                *(float2*)&Sc[(m0 + g) * SC_LD + c0] =
                    make_float2(acc0[nt][0] * SCALE, acc0[nt][1] * SCALE);
                *(float2*)&Sc[(m0 + 8 + g) * SC_LD + c0] =
                    make_float2(acc0[nt][2] * SCALE, acc0[nt][3] * SCALE);
            }
            if (has1) {
                #pragma unroll
                for (int nt = 0; nt < 4; nt++) {
                    int c0 = nt * 8 + 2 * q;
                    *(float2*)&Sc[(m1 + g) * SC_LD + c0] =
                        make_float2(acc1[nt][0] * SCALE, acc1[nt][1] * SCALE);
                    *(float2*)&Sc[(m1 + 8 + g) * SC_LD + c0] =
                        make_float2(acc1[nt][2] * SCALE, acc1[nt][3] * SCALE);
                }
            }
        }
        __syncthreads();   // QK done reading Buf(K) & writing Sc

        // ---- V frame via cp.async (overlaps softmax) ----
        for (int idx = tid; idx < PP * 16; idx += 256) {
            int n = idx >> 4, d4 = (idx & 15) << 2;
            cp16(sBuf + (uint32_t)(n * BUF_LD + d4) * 4u,
                 qkv + (frameRow + n) * C3 + 2 * CC + h * DD + d4);
        }
        CP_COMMIT();

        // softmax down columns (8 lanes per query column); P stored tf32-exact
        {
            const int col = tid >> 3, r = tid & 7;
            float m = -1e30f;
            for (int n = r; n < PP; n += 8) m = fmaxf(m, Sc[n * SC_LD + col]);
            #pragma unroll
            for (int o = 4; o; o >>= 1) m = fmaxf(m, __shfl_xor_sync(0xffffffffu, m, o));
            float z = 0.f;
            for (int n = r; n < PP; n += 8) {
                float e = __expf(Sc[n * SC_LD + col] - m);
                Sc[n * SC_LD + col] = e;
                z += e;
            }
            #pragma unroll
            for (int o = 4; o; o >>= 1) z += __shfl_xor_sync(0xffffffffu, z, o);
            float inv = 1.f / z;
            for (int n = r; n < PP; n += 8)
                Sc[n * SC_LD + col] = to_tf32(Sc[n * SC_LD + col] * inv);
        }
        // zero P pad rows 196..199 (QK overwrote them)
        if (tid < 128) Sc[(196 + (tid >> 5)) * SC_LD + (tid & 31)] = 0.f;
        CP_WAIT0();
        __syncthreads();

        // ---- PV: out(32x64) = P(32x200) @ V(200x64); 4 warps, 1 mt x 4 d-tiles ----
        if (warp < 4) {
            const int mt = warp & 1;
            const int dgrp = warp >> 1;
            const int m0 = mt * 16;
            float acc[4][4];
            #pragma unroll
            for (int j = 0; j < 4; j++)
                #pragma unroll
                for (int l = 0; l < 4; l++) acc[j][l] = 0.f;
            for (int kb = 0; kb < 25; kb++) {
                const int k0 = kb * 8;
                uint32_t a[4];
                a[0] = __float_as_uint(Sc[(k0 + q) * SC_LD + m0 + g]);
                a[1] = __float_as_uint(Sc[(k0 + q) * SC_LD + m0 + 8 + g]);
                a[2] = __float_as_uint(Sc[(k0 + q + 4) * SC_LD + m0 + g]);
                a[3] = __float_as_uint(Sc[(k0 + q + 4) * SC_LD + m0 + 8 + g]);
                #pragma unroll
                for (int j = 0; j < 4; j++) {
                    const int d0 = dgrp * 32 + j * 8;
                    uint32_t bfr[2];
                    bfr[0] = __float_as_uint(Buf[(k0 + q) * BUF_LD + d0 + g]);
                    bfr[1] = __float_as_uint(Buf[(k0 + q + 4) * BUF_LD + d0 + g]);
                    mma_tf32(acc[j], a, bfr);
                }
            }
            #pragma unroll
            for (int j = 0; j < 4; j++) {
                const int d0 = dgrp * 32 + j * 8;
                const int col = h * DD + d0 + 2 * q;
                const int row0 = s0 + m0 + g;
                *(float2*)(traj + ((size_t)(b * SS + row0) * FF + f) * CC + col) =
                    make_float2(to_tf32(acc[j][0]), to_tf32(acc[j][1]));
                *(float2*)(traj + ((size_t)(b * SS + row0 + 8) * FF + f) * CC + col) =
                    make_float2(to_tf32(acc[j][2]), to_tf32(acc[j][3]));
            }
        }
    }
}

// ---------------- frame attention (fused logits) ----------------
// grid = B*S, 384 threads (12 warps = 12 heads).
__global__ void frame_attn_kernel(const float* __restrict__ w, const float* __restrict__ traj,
                                  float* __restrict__ Y, float* __restrict__ attn_out)
{
    const int bs = blockIdx.x;
    const int b = bs / SS;
    const int s = bs % SS;
    const int tid = threadIdx.x;
    const int h = tid >> 5;      // warp = head
    const int lane = tid & 31;

    __shared__ float ts[FF][CC];
    __shared__ float a_sm[HH][FF];

    for (int idx = tid; idx < FF * CC / 4; idx += 384) {
        int f = idx / 192, j = idx % 192;
        float4 v = *(const float4*)(traj + ((size_t)bs * FF + f) * CC + j * 4);
        *(float4*)&ts[f][j * 4] = v;
    }
    __syncthreads();

    const float* wrow = w + (size_t)bs * W12 + h * CC;
    float wreg[24];
    #pragma unroll
    for (int j = 0; j < 24; j++) wreg[j] = wrow[lane + 32 * j];

    float lg[FF];
    #pragma unroll
    for (int f = 0; f < FF; f++) {
        float dsum = 0.f;
        #pragma unroll
        for (int j = 0; j < 24; j++) dsum += wreg[j] * ts[f][lane + 32 * j];
        #pragma unroll
        for (int o = 16; o; o >>= 1) dsum += __shfl_xor_sync(0xffffffffu, dsum, o);
        lg[f] = dsum * SCALE;
    }
    float m = -1e30f;
    #pragma unroll
    for (int f = 0; f < FF; f++) m = fmaxf(m, lg[f]);
    float z = 0.f;
    #pragma unroll
    for (int f = 0; f < FF; f++) { lg[f] = __expf(lg[f] - m); z += lg[f]; }
    float inv = 1.f / z;
    #pragma unroll
    for (int f = 0; f < FF; f++) lg[f] *= inv;

    if (lane < FF) {
        a_sm[h][lane] = lg[lane];
        attn_out[(((size_t)b * HH + h) * SS + s) * FF + lane] = lg[lane];
    }
    __syncthreads();

    #pragma unroll
    for (int rep = 0; rep < 2; rep++) {
        int c = tid + rep * 384;
        int h2 = c >> 6;
        float o = 0.f;
        #pragma unroll
        for (int f = 0; f < FF; f++) o += a_sm[h2][f] * ts[f][c];
        Y[(size_t)(b * NN + 1 + s) * CC + c] = to_tf32(o);
    }
}

// ---------------- launcher ----------------
extern "C" void kernel_launch(void* const* d_in, const int* in_sizes, int n_in,
                              void* d_out, int out_size)
{
    const float* x      = (const float*)d_in[0];
    const float* W_qkv  = (const float*)d_in[1];
    const float* W_pq   = (const float*)d_in[2];
    const float* W_pkv  = (const float*)d_in[3];
    const float* W_proj = (const float*)d_in[4];
    const float* b_proj = (const float*)d_in[5];
    (void)in_sizes; (void)n_in;

    float *qkv, *traj, *q2, *w, *wT, *Y, *rx, *rwq, *rwpq, *rwproj;
    cudaGetSymbolAddress((void**)&qkv,    g_qkv);
    cudaGetSymbolAddress((void**)&traj,   g_traj);
    cudaGetSymbolAddress((void**)&q2,     g_q2);
    cudaGetSymbolAddress((void**)&w,      g_w);
    cudaGetSymbolAddress((void**)&wT,     g_wT);
    cudaGetSymbolAddress((void**)&Y,      g_Y);
    cudaGetSymbolAddress((void**)&rx,     g_x);
    cudaGetSymbolAddress((void**)&rwq,    g_wq);
    cudaGetSymbolAddress((void**)&rwpq,   g_wpq);
    cudaGetSymbolAddress((void**)&rwproj, g_wproj);

    float* out_main = (float*)d_out;                                   // (B,N,C)
    float* out_attn = out_main + (size_t)BB * NN * CC;                 // (B,h,S,F)

    static int smem_set = 0;
    if (!smem_set) {
        cudaFuncSetAttribute(space_attn_kernel,
                             cudaFuncAttributeMaxDynamicSharedMemorySize, SPACE_SMEM_BYTES);
        smem_set = 1;
    }

    const int M1 = BB * NN;   // 3138
    const int M2 = BB * SS;   // 3136

    // 0) round inputs to tf32 + transpose W_pkv K-half
    {
        int t4 = (XSZ + WQSZ + 2 * WPSZ) / 4;
        round_inputs_kernel<<<(t4 + 255) / 256, 256>>>(x, W_qkv, W_pq, W_proj,
                                                       rx, rwq, rwpq, rwproj);
        transpose_wpkv_kernel<<<(CC * CC + 255) / 256, 256>>>(W_pkv, wT);
    }
    // 1) qkv = x @ W_qkv (tf32-rounded output)
    {
        dim3 grid(C3 / GBN, (M1 + GBM - 1) / GBM);
        tf32_gemm_kernel<<<grid, 256>>>(rx, rwq, qkv, M1, C3, CC, CC, C3, C3,
                                        nullptr, 0, 1, 0, 0, 0);
    }
    // 2) cls attention -> Y row 0 per batch
    cls_attn_kernel<<<BB * HH, 256>>>(qkv, Y);
    // 3) space attention -> traj
    space_attn_kernel<<<BB * HH * (SS / SQT), 256, SPACE_SMEM_BYTES>>>(qkv, traj);
    // 4) q2 = xdiag @ W_pq with fused diagonal gather (tf32-rounded output)
    {
        dim3 grid(CC / GBN, (M2 + GBM - 1) / GBM);
        tf32_gemm_kernel<<<grid, 256>>>(traj, rwpq, q2, M2, CC, CC, CC, CC, CC,
                                        nullptr, 1, 1, 0, 0, 0);
    }
    // 5) w[bs,h,:] = q2[bs,h-block] @ W_pkv_h^T   (batched over z = head)
    {
        dim3 grid(CC / GBN, (M2 + GBM - 1) / GBM, HH);
        tf32_gemm_kernel<<<grid, 256>>>(q2, wT, w, M2, CC, DD, CC, CC, W12,
                                        nullptr, 0, 0, DD, DD * CC, CC);
    }
    // 6) frame attention (fused logits) -> attn output + Y rows 1..S
    frame_attn_kernel<<<BB * SS, 384>>>(w, traj, Y, out_attn);
    // 7) out = Y @ W_proj + b_proj (final, unrounded)
    {
        dim3 grid(CC / GBN, (M1 + GBM - 1) / GBM);
        tf32_gemm_kernel<<<grid, 256>>>(Y, rwproj, out_main, M1, CC, CC, CC, CC, CC,
                                        b_proj, 0, 0, 0, 0, 0);
    }
}

// round 11
// speedup vs baseline: 4.3873x; 1.0319x over previous
#include <cuda_runtime.h>
#include <cuda_bf16.h>
#include <math.h>
#include <stdint.h>

// Problem constants
#define BB 2
#define NN 1569          // tokens incl cls
#define CC 768
#define HH 12
#define DD 64
#define PP 196
#define FF 8
#define SS 1568          // F*P
#define C3 2304          // 3*C
#define W12 9216         // 12*768
#define SCALE 0.125f
#define CLS_CH 8         // cls split-softmax chunks
#define CLS_CHUNK 197    // ceil(NN/CLS_CH)

// ---------------- device scratch (no allocations allowed) ----------------
__device__ float g_qkv[(size_t)BB * NN * C3];          // (B*N, 3C)
__device__ float g_traj[(size_t)BB * SS * FF * CC];    // (B,S,F,C)
__device__ float g_q2[(size_t)BB * SS * CC];           // (B*S, C)
__device__ float g_w[(size_t)BB * SS * W12];           // (B*S, H, C) fused k2 weights
__device__ float g_wT[(size_t)CC * CC];                // W_pkv[:, :CC]^T (tf32)
__device__ float g_Y[(size_t)BB * NN * CC];            // (B*N, C) concat[cls,out]
__device__ float g_x[(size_t)BB * NN * CC];            // tf32-rounded x
__device__ float g_wq[(size_t)CC * C3];                // tf32-rounded W_qkv
__device__ float g_wpq[(size_t)CC * CC];               // tf32-rounded W_pq
__device__ float g_wproj[(size_t)CC * CC];             // tf32-rounded W_proj
__device__ float g_clsP[(size_t)BB * HH * CLS_CH * (DD + 2)];  // cls partials

__device__ __forceinline__ float to_tf32(float x) {
    uint32_t u;
    asm("cvt.rna.tf32.f32 %0, %1;" : "=r"(u) : "f"(x));
    return __uint_as_float(u);
}

__device__ __forceinline__ void mma_tf32(float (&c)[4], const uint32_t (&a)[4], const uint32_t (&b)[2]) {
    asm volatile(
        "mma.sync.aligned.m16n8k8.row.col.f32.tf32.tf32.f32 "
        "{%0,%1,%2,%3}, {%4,%5,%6,%7}, {%8,%9}, {%0,%1,%2,%3};"
        : "+f"(c[0]), "+f"(c[1]), "+f"(c[2]), "+f"(c[3])
        : "r"(a[0]), "r"(a[1]), "r"(a[2]), "r"(a[3]), "r"(b[0]), "r"(b[1]));
}

__device__ __forceinline__ void cp16(uint32_t dst, const void* src) {
    asm volatile("cp.async.cg.shared.global [%0], [%1], 16;" :: "r"(dst), "l"(src));
}
__device__ __forceinline__ void cp16z(uint32_t dst, const void* src, int sz) {
    asm volatile("cp.async.cg.shared.global [%0], [%1], 16, %2;" :: "r"(dst), "l"(src), "r"(sz));
}
#define CP_COMMIT() asm volatile("cp.async.commit_group;")
#define CP_WAIT0()  asm volatile("cp.async.wait_group 0;")

// ---------------- input tf32-rounding prep ----------------
#define XSZ  (BB * NN * CC)    // 2409984
#define WQSZ (CC * C3)         // 1769472
#define WPSZ (CC * CC)         // 589824
__global__ void round_inputs_kernel(const float* __restrict__ x, const float* __restrict__ Wq,
                                    const float* __restrict__ Wpq, const float* __restrict__ Wpr,
                                    float* __restrict__ rx, float* __restrict__ rwq,
                                    float* __restrict__ rwpq, float* __restrict__ rwpr)
{
    const int T4 = (XSZ + WQSZ + 2 * WPSZ) / 4;
    int idx4 = blockIdx.x * 256 + threadIdx.x;
    if (idx4 >= T4) return;
    int i = idx4 * 4;
    const float* s; float* d; int off;
    if (i < XSZ)                    { s = x;   d = rx;   off = i; }
    else if (i < XSZ + WQSZ)        { s = Wq;  d = rwq;  off = i - XSZ; }
    else if (i < XSZ + WQSZ + WPSZ) { s = Wpq; d = rwpq; off = i - XSZ - WQSZ; }
    else                            { s = Wpr; d = rwpr; off = i - XSZ - WQSZ - WPSZ; }
    float4 v = *(const float4*)(s + off);
    v.x = to_tf32(v.x); v.y = to_tf32(v.y); v.z = to_tf32(v.z); v.w = to_tf32(v.w);
    *(float4*)(d + off) = v;
}

// ---------------- TF32 tensor-core GEMM, cp.async double-buffered ----------
#define GBM 128
#define GBN 128
#define GBK 16
#define A_LD 20
#define B_LD 136

__device__ __forceinline__ size_t a_row_off(int gr, int lda, int gather) {
    if (gather) {
        int s = gr % SS;
        gr = gr * FF + s / PP;
    }
    return (size_t)gr * lda;
}

__global__ void tf32_gemm_kernel(const float* __restrict__ A, const float* __restrict__ B,
                                 float* __restrict__ C, int M, int N, int K,
                                 int lda, int ldb, int ldc,
                                 const float* __restrict__ bias, int gather, int round_out,
                                 int zAcol, int zBoff, int zCcol)
{
    __shared__ float As[2][GBM][A_LD];   // row-major
    __shared__ float Bs[2][GBK][B_LD];   // k-major

    const int z = blockIdx.z;
    A += (size_t)z * zAcol;
    B += (size_t)z * zBoff;
    C += (size_t)z * zCcol;

    const int tid  = threadIdx.x;
    const int warp = tid >> 5;
    const int lane = tid & 31;
    const int g = lane >> 2;
    const int q = lane & 3;
    const int warpM = (warp & 3) * 32;
    const int warpN = (warp >> 2) * 64;
    const int by = blockIdx.y * GBM;
    const int bx = blockIdx.x * GBN;

    float acc[2][8][4];
    #pragma unroll
    for (int i = 0; i < 2; i++)
        #pragma unroll
        for (int j = 0; j < 8; j++)
            #pragma unroll
            for (int l = 0; l < 4; l++) acc[i][j][l] = 0.f;

    const int ar = tid & 127;
    const int cg0 = tid >> 7;          // 0 or 1
    const int gr = by + ar;
    const int asz = (gr < M) ? 16 : 0;
    const float* ap = A + a_row_off(gr < M ? gr : M - 1, lda, gather);
    const int br = tid >> 4;
    const int bc = (tid & 15) << 2;
    const float* bp = B + (size_t)br * ldb + bx + bc;

    uint32_t sA = (uint32_t)__cvta_generic_to_shared(&As[0][ar][0]);
    uint32_t sB = (uint32_t)__cvta_generic_to_shared(&Bs[0][br][bc]);
    const uint32_t stA = sizeof(float) * GBM * A_LD;
    const uint32_t stB = sizeof(float) * GBK * B_LD;

    cp16z(sA + (cg0 * 4) * 4, ap + cg0 * 4, asz);
    cp16z(sA + ((cg0 + 2) * 4) * 4, ap + (cg0 + 2) * 4, asz);
    cp16(sB, bp);
    cp16(sB + 64 * 4, bp + 64);
    CP_COMMIT();

    int cur = 0;
    for (int k0 = 0; k0 < K; k0 += GBK) {
        CP_WAIT0();
        __syncthreads();
        if (k0 + GBK < K) {
            uint32_t oA = (cur ^ 1) * stA, oB = (cur ^ 1) * stB;
            cp16z(sA + oA + (cg0 * 4) * 4, ap + k0 + GBK + cg0 * 4, asz);
            cp16z(sA + oA + ((cg0 + 2) * 4) * 4, ap + k0 + GBK + (cg0 + 2) * 4, asz);
            cp16(sB + oB, bp + (size_t)(k0 + GBK) * ldb);
            cp16(sB + oB + 64 * 4, bp + (size_t)(k0 + GBK) * ldb + 64);
            CP_COMMIT();
        }

        #pragma unroll
        for (int kk = 0; kk < GBK; kk += 8) {
            uint32_t afr[2][4];
            #pragma unroll
            for (int mt = 0; mt < 2; mt++) {
                int r = warpM + mt * 16 + g;
                afr[mt][0] = __float_as_uint(As[cur][r][kk + q]);
                afr[mt][1] = __float_as_uint(As[cur][r + 8][kk + q]);
                afr[mt][2] = __float_as_uint(As[cur][r][kk + q + 4]);
                afr[mt][3] = __float_as_uint(As[cur][r + 8][kk + q + 4]);
            }
            uint32_t bfr[8][2];
            #pragma unroll
            for (int nt = 0; nt < 8; nt++) {
                int c = warpN + nt * 8 + g;
                bfr[nt][0] = __float_as_uint(Bs[cur][kk + q][c]);
                bfr[nt][1] = __float_as_uint(Bs[cur][kk + q + 4][c]);
            }
            #pragma unroll
            for (int mt = 0; mt < 2; mt++)
                #pragma unroll
                for (int nt = 0; nt < 8; nt++)
                    mma_tf32(acc[mt][nt], afr[mt], bfr[nt]);
        }
        cur ^= 1;
    }

    #pragma unroll
    for (int mt = 0; mt < 2; mt++) {
        #pragma unroll
        for (int nt = 0; nt < 8; nt++) {
            int col = bx + warpN + nt * 8 + 2 * q;
            float bx0 = 0.f, bx1 = 0.f;
            if (bias) { bx0 = bias[col]; bx1 = bias[col + 1]; }
            int r0 = by + warpM + mt * 16 + g;
            float v0 = acc[mt][nt][0] + bx0, v1 = acc[mt][nt][1] + bx1;
            float v2 = acc[mt][nt][2] + bx0, v3 = acc[mt][nt][3] + bx1;
            if (round_out) {
                v0 = to_tf32(v0); v1 = to_tf32(v1); v2 = to_tf32(v2); v3 = to_tf32(v3);
            }
            if (r0 < M)     *(float2*)(C + (size_t)r0 * ldc + col) = make_float2(v0, v1);
            if (r0 + 8 < M) *(float2*)(C + (size_t)(r0 + 8) * ldc + col) = make_float2(v2, v3);
        }
    }
}

// ---------------- W_pkv[:, :CC] transpose (tf32-rounded) ----------------
__global__ void transpose_wpkv_kernel(const float* __restrict__ W_pkv, float* __restrict__ wT)
{
    int idx = blockIdx.x * 256 + threadIdx.x;
    if (idx >= CC * CC) return;
    int hd = idx / CC, c = idx % CC;
    wT[(size_t)hd * CC + c] = to_tf32(W_pkv[(size_t)c * (2 * CC) + hd]);
}

// ---------------- cls attention phase A: split-softmax partials ----------
// grid (BB*HH, CLS_CH), 256 threads. Each block: ~197 tokens -> (m, z, acc[64]).
__global__ void cls_partial_kernel(const float* __restrict__ qkv, float* __restrict__ P)
{
    const int bh = blockIdx.x;
    const int c  = blockIdx.y;
    const int b = bh / HH;
    const int h = bh % HH;
    const int base = c * CLS_CHUNK;
    const int count = min(CLS_CHUNK, NN - base);
    const int tid = threadIdx.x;

    __shared__ float qs[DD];
    __shared__ float sc[CLS_CHUNK];
    __shared__ float red[256];
    __shared__ float part4[4][DD];

    if (tid < DD) qs[tid] = qkv[(size_t)(b * NN) * C3 + h * DD + tid];
    __syncthreads();

    float s = -1e30f;
    if (tid < count) {
        const float* kr = qkv + (size_t)(b * NN + base + tid) * C3 + CC + h * DD;
        float dot = 0.f;
        #pragma unroll
        for (int d = 0; d < DD; d += 4) {
            float4 k4 = *(const float4*)(kr + d);
            dot += qs[d] * k4.x + qs[d + 1] * k4.y + qs[d + 2] * k4.z + qs[d + 3] * k4.w;
        }
        s = dot * SCALE;
        sc[tid] = s;
    }
    red[tid] = s; __syncthreads();
    for (int o = 128; o; o >>= 1) { if (tid < o) red[tid] = fmaxf(red[tid], red[tid + o]); __syncthreads(); }
    const float m = red[0];
    __syncthreads();

    float e = 0.f;
    if (tid < count) { e = __expf(sc[tid] - m); sc[tid] = e; }
    red[tid] = e; __syncthreads();
    for (int o = 128; o; o >>= 1) { if (tid < o) red[tid] += red[tid + o]; __syncthreads(); }
    const float z = red[0];
    __syncthreads();

    const int d = tid & 63, part = tid >> 6;
    float acc = 0.f;
    for (int i = part; i < count; i += 4)
        acc += sc[i] * qkv[(size_t)(b * NN + base + i) * C3 + 2 * CC + h * DD + d];
    part4[part][d] = acc;
    __syncthreads();

    float* out = P + (size_t)(bh * CLS_CH + c) * (DD + 2);
    if (tid < DD)
        out[tid] = part4[0][tid] + part4[1][tid] + part4[2][tid] + part4[3][tid];
    if (tid == DD)     out[DD] = m;
    if (tid == DD + 1) out[DD + 1] = z;
}

// ---------------- cls attention phase B: combine -> Y row 0 -------------
// grid BB*HH, 64 threads.
__global__ void cls_combine_kernel(const float* __restrict__ P, float* __restrict__ Y)
{
    const int bh = blockIdx.x;
    const int b = bh / HH;
    const int h = bh % HH;
    const int tid = threadIdx.x;   // 0..63

    const float* base = P + (size_t)bh * CLS_CH * (DD + 2);
    float m = -1e30f;
    #pragma unroll
    for (int c = 0; c < CLS_CH; c++) m = fmaxf(m, base[c * (DD + 2) + DD]);
    float z = 0.f, acc = 0.f;
    #pragma unroll
    for (int c = 0; c < CLS_CH; c++) {
        float sc = __expf(base[c * (DD + 2) + DD] - m);
        z += base[c * (DD + 2) + DD + 1] * sc;
        acc += base[c * (DD + 2) + tid] * sc;
    }
    Y[(size_t)(b * NN) * CC + h * DD + tid] = to_tf32(acc / z);
}

// ---------------- tensor-core space attention -> traj -------------------
// SQT=32 queries/block, 256 threads, grid = B*H*49, ~107KB smem -> 2 blocks/SM.
#define SQT 32
#define BUF_LD 76
#define SC_LD 40
#define QT_LD 40
#define BUF_OFF 0
#define SC_OFF (208 * BUF_LD)                     // 15808
#define QT_OFF (SC_OFF + 208 * SC_LD)             // 24128
#define SPACE_SMEM_FLOATS (QT_OFF + 64 * QT_LD)   // 26688
#define SPACE_SMEM_BYTES (SPACE_SMEM_FLOATS * 4)  // 106752

__global__ void space_attn_kernel(const float* __restrict__ qkv, float* __restrict__ traj)
{
    extern __shared__ float smem[];
    float* Buf = smem + BUF_OFF;  // [208][76] K then V, natural [n][d]
    float* Sc  = smem + SC_OFF;   // [208][40] scores^T [n][q]
    float* Qt  = smem + QT_OFF;   // [64][40]  Q^T [d][q]
    const uint32_t sBuf = (uint32_t)__cvta_generic_to_shared(Buf);

    const int nt_blocks = SS / SQT;    // 49
    const int bh = blockIdx.x / nt_blocks;
    const int st = blockIdx.x % nt_blocks;
    const int b = bh / HH;
    const int h = bh % HH;
    const int s0 = st * SQT;
    const int tid = threadIdx.x;
    const int warp = tid >> 5;
    const int lane = tid & 31;
    const int g = lane >> 2;
    const int q = lane & 3;

    for (int idx = tid; idx < SQT * 16; idx += 256) {
        int row = idx >> 4, d4 = (idx & 15) << 2;
        float4 qv = *(const float4*)(qkv + (size_t)(b * NN + 1 + s0 + row) * C3 + h * DD + d4);
        Qt[(d4 + 0) * QT_LD + row] = qv.x;
        Qt[(d4 + 1) * QT_LD + row] = qv.y;
        Qt[(d4 + 2) * QT_LD + row] = qv.z;
        Qt[(d4 + 3) * QT_LD + row] = qv.w;
    }
    {
        int n = 196 + (tid >> 6), d = tid & 63;
        Buf[n * BUF_LD + d] = 0.f;
    }

    for (int f = 0; f < FF; f++) {
        __syncthreads();

        const size_t frameRow = (size_t)(b * NN + 1 + f * PP);
        for (int idx = tid; idx < PP * 16; idx += 256) {
            int n = idx >> 4, d4 = (idx & 15) << 2;
            cp16(sBuf + (uint32_t)(n * BUF_LD + d4) * 4u,
                 qkv + (frameRow + n) * C3 + CC + h * DD + d4);
        }
        CP_COMMIT();
        CP_WAIT0();
        __syncthreads();

        // ---- QK ----
        {
            const int mt0 = warp;
            const int mt1 = warp + 8;
            const int m0 = mt0 * 16;
            const int m1 = mt1 * 16;
            const bool has1 = (mt1 < 13);
            float acc0[4][4], acc1[4][4];
            #pragma unroll
            for (int i = 0; i < 4; i++)
                #pragma unroll
                for (int j = 0; j < 4; j++) { acc0[i][j] = 0.f; acc1[i][j] = 0.f; }
            #pragma unroll
            for (int kb = 0; kb < 8; kb++) {
                const int k0 = kb * 8;
                uint32_t bfr[4][2];
                #pragma unroll
                for (int nt = 0; nt < 4; nt++) {
                    bfr[nt][0] = __float_as_uint(Qt[(k0 + q) * QT_LD + nt * 8 + g]);
                    bfr[nt][1] = __float_as_uint(Qt[(k0 + q + 4) * QT_LD + nt * 8 + g]);
                }
                uint32_t a[4];
                a[0] = __float_as_uint(Buf[(m0 + g) * BUF_LD + k0 + q]);
                a[1] = __float_as_uint(Buf[(m0 + 8 + g) * BUF_LD + k0 + q]);
                a[2] = __float_as_uint(Buf[(m0 + g) * BUF_LD + k0 + q + 4]);
                a[3] = __float_as_uint(Buf[(m0 + 8 + g) * BUF_LD + k0 + q + 4]);
                #pragma unroll
                for (int nt = 0; nt < 4; nt++) mma_tf32(acc0[nt], a, bfr[nt]);
                if (has1) {
                    uint32_t a1[4];
                    a1[0] = __float_as_uint(Buf[(m1 + g) * BUF_LD + k0 + q]);
                    a1[1] = __float_as_uint(Buf[(m1 + 8 + g) * BUF_LD + k0 + q]);
                    a1[2] = __float_as_uint(Buf[(m1 + g) * BUF_LD + k0 + q + 4]);
                    a1[3] = __float_as_uint(Buf[(m1 + 8 + g) * BUF_LD + k0 + q + 4]);
                    #pragma unroll
                    for (int nt = 0; nt < 4; nt++) mma_tf32(acc1[nt], a1, bfr[nt]);
                }
            }
            #pragma unroll
            for (int nt = 0; nt < 4; nt++) {
                int c0 = nt * 8 + 2 * q;
                *(float2*)&Sc[(m0 + g) * SC_LD + c0] =
                    make_float2(acc0[nt][0] * SCALE, acc0[nt][1] * SCALE);
                *(float2*)&Sc[(m0 + 8 + g) * SC_LD + c0] =
                    make_float2(acc0[nt][2] * SCALE, acc0[nt][3] * SCALE);
            }
            if (has1) {
                #pragma unroll
                for (int nt = 0; nt < 4; nt++) {
                    int c0 = nt * 8 + 2 * q;
                    *(float2*)&Sc[(m1 + g) * SC_LD + c0] =
                        make_float2(acc1[nt][0] * SCALE, acc1[nt][1] * SCALE);
                    *(float2*)&Sc[(m1 + 8 + g) * SC_LD + c0] =
                        make_float2(acc1[nt][2] * SCALE, acc1[nt][3] * SCALE);
                }
            }
        }
        __syncthreads();

        // ---- V via cp.async (overlaps softmax) ----
        for (int idx = tid; idx < PP * 16; idx += 256) {
            int n = idx >> 4, d4 = (idx & 15) << 2;
            cp16(sBuf + (uint32_t)(n * BUF_LD + d4) * 4u,
                 qkv + (frameRow + n) * C3 + 2 * CC + h * DD + d4);
        }
        CP_COMMIT();

        {
            const int col = tid >> 3, r = tid & 7;
            float m = -1e30f;
            for (int n = r; n < PP; n += 8) m = fmaxf(m, Sc[n * SC_LD + col]);
            #pragma unroll
            for (int o = 4; o; o >>= 1) m = fmaxf(m, __shfl_xor_sync(0xffffffffu, m, o));
            float z = 0.f;
            for (int n = r; n < PP; n += 8) {
                float e = __expf(Sc[n * SC_LD + col] - m);
                Sc[n * SC_LD + col] = e;
                z += e;
            }
            #pragma unroll
            for (int o = 4; o; o >>= 1) z += __shfl_xor_sync(0xffffffffu, z, o);
            float inv = 1.f / z;
            for (int n = r; n < PP; n += 8)
                Sc[n * SC_LD + col] = to_tf32(Sc[n * SC_LD + col] * inv);
        }
        if (tid < 128) Sc[(196 + (tid >> 5)) * SC_LD + (tid & 31)] = 0.f;
        CP_WAIT0();
        __syncthreads();

        // ---- PV ----
        if (warp < 4) {
            const int mt = warp & 1;
            const int dgrp = warp >> 1;
            const int m0 = mt * 16;
            float acc[4][4];
            #pragma unroll
            for (int j = 0; j < 4; j++)
                #pragma unroll
                for (int l = 0; l < 4; l++) acc[j][l] = 0.f;
            for (int kb = 0; kb < 25; kb++) {
                const int k0 = kb * 8;
                uint32_t a[4];
                a[0] = __float_as_uint(Sc[(k0 + q) * SC_LD + m0 + g]);
                a[1] = __float_as_uint(Sc[(k0 + q) * SC_LD + m0 + 8 + g]);
                a[2] = __float_as_uint(Sc[(k0 + q + 4) * SC_LD + m0 + g]);
                a[3] = __float_as_uint(Sc[(k0 + q + 4) * SC_LD + m0 + 8 + g]);
                #pragma unroll
                for (int j = 0; j < 4; j++) {
                    const int d0 = dgrp * 32 + j * 8;
                    uint32_t bfr[2];
                    bfr[0] = __float_as_uint(Buf[(k0 + q) * BUF_LD + d0 + g]);
                    bfr[1] = __float_as_uint(Buf[(k0 + q + 4) * BUF_LD + d0 + g]);
                    mma_tf32(acc[j], a, bfr);
                }
            }
            #pragma unroll
            for (int j = 0; j < 4; j++) {
                const int d0 = dgrp * 32 + j * 8;
                const int col = h * DD + d0 + 2 * q;
                const int row0 = s0 + m0 + g;
                *(float2*)(traj + ((size_t)(b * SS + row0) * FF + f) * CC + col) =
                    make_float2(to_tf32(acc[j][0]), to_tf32(acc[j][1]));
                *(float2*)(traj + ((size_t)(b * SS + row0 + 8) * FF + f) * CC + col) =
                    make_float2(to_tf32(acc[j][2]), to_tf32(acc[j][3]));
            }
        }
    }
}

// ---------------- frame attention (fused logits) ----------------
__global__ void frame_attn_kernel(const float* __restrict__ w, const float* __restrict__ traj,
                                  float* __restrict__ Y, float* __restrict__ attn_out)
{
    const int bs = blockIdx.x;
    const int b = bs / SS;
    const int s = bs % SS;
    const int tid = threadIdx.x;
    const int h = tid >> 5;      // warp = head
    const int lane = tid & 31;

    __shared__ float ts[FF][CC];
    __shared__ float a_sm[HH][FF];

    for (int idx = tid; idx < FF * CC / 4; idx += 384) {
        int f = idx / 192, j = idx % 192;
        float4 v = *(const float4*)(traj + ((size_t)bs * FF + f) * CC + j * 4);
        *(float4*)&ts[f][j * 4] = v;
    }
    __syncthreads();

    const float* wrow = w + (size_t)bs * W12 + h * CC;
    float wreg[24];
    #pragma unroll
    for (int j = 0; j < 24; j++) wreg[j] = wrow[lane + 32 * j];

    float lg[FF];
    #pragma unroll
    for (int f = 0; f < FF; f++) {
        float dsum = 0.f;
        #pragma unroll
        for (int j = 0; j < 24; j++) dsum += wreg[j] * ts[f][lane + 32 * j];
        #pragma unroll
        for (int o = 16; o; o >>= 1) dsum += __shfl_xor_sync(0xffffffffu, dsum, o);
        lg[f] = dsum * SCALE;
    }
    float m = -1e30f;
    #pragma unroll
    for (int f = 0; f < FF; f++) m = fmaxf(m, lg[f]);
    float z = 0.f;
    #pragma unroll
    for (int f = 0; f < FF; f++) { lg[f] = __expf(lg[f] - m); z += lg[f]; }
    float inv = 1.f / z;
    #pragma unroll
    for (int f = 0; f < FF; f++) lg[f] *= inv;

    if (lane < FF) {
        a_sm[h][lane] = lg[lane];
        attn_out[(((size_t)b * HH + h) * SS + s) * FF + lane] = lg[lane];
    }
    __syncthreads();

    #pragma unroll
    for (int rep = 0; rep < 2; rep++) {
        int c = tid + rep * 384;
        int h2 = c >> 6;
        float o = 0.f;
        #pragma unroll
        for (int f = 0; f < FF; f++) o += a_sm[h2][f] * ts[f][c];
        Y[(size_t)(b * NN + 1 + s) * CC + c] = to_tf32(o);
    }
}

// ---------------- launcher ----------------
extern "C" void kernel_launch(void* const* d_in, const int* in_sizes, int n_in,
                              void* d_out, int out_size)
{
    const float* x      = (const float*)d_in[0];
    const float* W_qkv  = (const float*)d_in[1];
    const float* W_pq   = (const float*)d_in[2];
    const float* W_pkv  = (const float*)d_in[3];
    const float* W_proj = (const float*)d_in[4];
    const float* b_proj = (const float*)d_in[5];
    (void)in_sizes; (void)n_in;

    float *qkv, *traj, *q2, *w, *wT, *Y, *rx, *rwq, *rwpq, *rwproj, *clsP;
    cudaGetSymbolAddress((void**)&qkv,    g_qkv);
    cudaGetSymbolAddress((void**)&traj,   g_traj);
    cudaGetSymbolAddress((void**)&q2,     g_q2);
    cudaGetSymbolAddress((void**)&w,      g_w);
    cudaGetSymbolAddress((void**)&wT,     g_wT);
    cudaGetSymbolAddress((void**)&Y,      g_Y);
    cudaGetSymbolAddress((void**)&rx,     g_x);
    cudaGetSymbolAddress((void**)&rwq,    g_wq);
    cudaGetSymbolAddress((void**)&rwpq,   g_wpq);
    cudaGetSymbolAddress((void**)&rwproj, g_wproj);
    cudaGetSymbolAddress((void**)&clsP,   g_clsP);

    float* out_main = (float*)d_out;                                   // (B,N,C)
    float* out_attn = out_main + (size_t)BB * NN * CC;                 // (B,h,S,F)

    static int smem_set = 0;
    if (!smem_set) {
        cudaFuncSetAttribute(space_attn_kernel,
                             cudaFuncAttributeMaxDynamicSharedMemorySize, SPACE_SMEM_BYTES);
        smem_set = 1;
    }

    const int M1 = BB * NN;   // 3138
    const int M2 = BB * SS;   // 3136

    // 0) round inputs to tf32 + transpose W_pkv K-half
    {
        int t4 = (XSZ + WQSZ + 2 * WPSZ) / 4;
        round_inputs_kernel<<<(t4 + 255) / 256, 256>>>(x, W_qkv, W_pq, W_proj,
                                                       rx, rwq, rwpq, rwproj);
        transpose_wpkv_kernel<<<(CC * CC + 255) / 256, 256>>>(W_pkv, wT);
    }
    // 1) qkv = x @ W_qkv (tf32-rounded output)
    {
        dim3 grid(C3 / GBN, (M1 + GBM - 1) / GBM);
        tf32_gemm_kernel<<<grid, 256>>>(rx, rwq, qkv, M1, C3, CC, CC, C3, C3,
                                        nullptr, 0, 1, 0, 0, 0);
    }
    // 2) cls attention (split-softmax) -> Y row 0 per batch
    {
        dim3 gridA(BB * HH, CLS_CH);
        cls_partial_kernel<<<gridA, 256>>>(qkv, clsP);
        cls_combine_kernel<<<BB * HH, 64>>>(clsP, Y);
    }
    // 3) space attention -> traj
    space_attn_kernel<<<BB * HH * (SS / SQT), 256, SPACE_SMEM_BYTES>>>(qkv, traj);
    // 4) q2 = xdiag @ W_pq with fused diagonal gather (tf32-rounded output)
    {
        dim3 grid(CC / GBN, (M2 + GBM - 1) / GBM);
        tf32_gemm_kernel<<<grid, 256>>>(traj, rwpq, q2, M2, CC, CC, CC, CC, CC,
                                        nullptr, 1, 1, 0, 0, 0);
    }
    // 5) w[bs,h,:] = q2[bs,h-block] @ W_pkv_h^T   (batched over z = head)
    {
        dim3 grid(CC / GBN, (M2 + GBM - 1) / GBM, HH);
        tf32_gemm_kernel<<<grid, 256>>>(q2, wT, w, M2, CC, DD, CC, CC, W12,
                                        nullptr, 0, 0, DD, DD * CC, CC);
    }
    // 6) frame attention (fused logits) -> attn output + Y rows 1..S
    frame_attn_kernel<<<BB * SS, 384>>>(w, traj, Y, out_attn);
    // 7) out = Y @ W_proj + b_proj (final, unrounded)
    {
        dim3 grid(CC / GBN, (M1 + GBM - 1) / GBM);
        tf32_gemm_kernel<<<grid, 256>>>(Y, rwproj, out_main, M1, CC, CC, CC, CC, CC,
                                        b_proj, 0, 0, 0, 0, 0);
    }
}

// round 15
// speedup vs baseline: 4.4341x; 1.0107x over previous
#include <cuda_runtime.h>
#include <cuda_bf16.h>
#include <math.h>
#include <stdint.h>

// Problem constants
#define BB 2
#define NN 1569          // tokens incl cls
#define CC 768
#define HH 12
#define DD 64
#define PP 196
#define FF 8
#define SS 1568          // F*P
#define C3 2304          // 3*C
#define W12 9216         // 12*768
#define SCALE 0.125f
#define CLS_CH 16        // cls split-softmax chunks
#define CLS_CHUNK 99     // ceil(NN/CLS_CH)

// ---------------- device scratch (no allocations allowed) ----------------
__device__ float g_qkv[(size_t)BB * NN * C3];          // (B*N, 3C)
__device__ float g_traj[(size_t)BB * SS * FF * CC];    // (B,S,F,C)
__device__ float g_q2[(size_t)BB * SS * CC];           // (B*S, C)
__device__ float g_w[(size_t)BB * SS * W12];           // (B*S, H, C) fused k2 weights
__device__ float g_wT[(size_t)CC * CC];                // W_pkv[:, :CC]^T (tf32)
__device__ float g_Y[(size_t)BB * NN * CC];            // (B*N, C) concat[cls,out]
__device__ float g_x[(size_t)BB * NN * CC];            // tf32-rounded x
__device__ float g_wq[(size_t)CC * C3];                // tf32-rounded W_qkv
__device__ float g_wpq[(size_t)CC * CC];               // tf32-rounded W_pq
__device__ float g_wproj[(size_t)CC * CC];             // tf32-rounded W_proj
__device__ float g_clsP[(size_t)BB * HH * CLS_CH * (DD + 2)];  // cls partials

__device__ __forceinline__ float to_tf32(float x) {
    uint32_t u;
    asm("cvt.rna.tf32.f32 %0, %1;" : "=r"(u) : "f"(x));
    return __uint_as_float(u);
}

__device__ __forceinline__ void mma_tf32(float (&c)[4], const uint32_t (&a)[4], const uint32_t (&b)[2]) {
    asm volatile(
        "mma.sync.aligned.m16n8k8.row.col.f32.tf32.tf32.f32 "
        "{%0,%1,%2,%3}, {%4,%5,%6,%7}, {%8,%9}, {%0,%1,%2,%3};"
        : "+f"(c[0]), "+f"(c[1]), "+f"(c[2]), "+f"(c[3])
        : "r"(a[0]), "r"(a[1]), "r"(a[2]), "r"(a[3]), "r"(b[0]), "r"(b[1]));
}

__device__ __forceinline__ void cp16(uint32_t dst, const void* src) {
    asm volatile("cp.async.cg.shared.global [%0], [%1], 16;" :: "r"(dst), "l"(src));
}
__device__ __forceinline__ void cp16z(uint32_t dst, const void* src, int sz) {
    asm volatile("cp.async.cg.shared.global [%0], [%1], 16, %2;" :: "r"(dst), "l"(src), "r"(sz));
}
#define CP_COMMIT() asm volatile("cp.async.commit_group;")
#define CP_WAIT0()  asm volatile("cp.async.wait_group 0;")

// ---------------- input tf32-rounding prep ----------------
#define XSZ  (BB * NN * CC)    // 2409984
#define WQSZ (CC * C3)         // 1769472
#define WPSZ (CC * CC)         // 589824
__global__ void round_inputs_kernel(const float* __restrict__ x, const float* __restrict__ Wq,
                                    const float* __restrict__ Wpq, const float* __restrict__ Wpr,
                                    float* __restrict__ rx, float* __restrict__ rwq,
                                    float* __restrict__ rwpq, float* __restrict__ rwpr)
{
    const int T4 = (XSZ + WQSZ + 2 * WPSZ) / 4;
    int idx4 = blockIdx.x * 256 + threadIdx.x;
    if (idx4 >= T4) return;
    int i = idx4 * 4;
    const float* s; float* d; int off;
    if (i < XSZ)                    { s = x;   d = rx;   off = i; }
    else if (i < XSZ + WQSZ)        { s = Wq;  d = rwq;  off = i - XSZ; }
    else if (i < XSZ + WQSZ + WPSZ) { s = Wpq; d = rwpq; off = i - XSZ - WQSZ; }
    else                            { s = Wpr; d = rwpr; off = i - XSZ - WQSZ - WPSZ; }
    float4 v = *(const float4*)(s + off);
    v.x = to_tf32(v.x); v.y = to_tf32(v.y); v.z = to_tf32(v.z); v.w = to_tf32(v.w);
    *(float4*)(d + off) = v;
}

// ---------------- TF32 tensor-core GEMM, cp.async double-buffered ----------
#define GBM 128
#define GBN 128
#define GBK 16
#define A_LD 20
#define B_LD 136

__device__ __forceinline__ size_t a_row_off(int gr, int lda, int gather) {
    if (gather) {
        int s = gr % SS;
        gr = gr * FF + s / PP;
    }
    return (size_t)gr * lda;
}

__global__ void tf32_gemm_kernel(const float* __restrict__ A, const float* __restrict__ B,
                                 float* __restrict__ C, int M, int N, int K,
                                 int lda, int ldb, int ldc,
                                 const float* __restrict__ bias, int gather, int round_out,
                                 int zAcol, int zBoff, int zCcol)
{
    __shared__ float As[2][GBM][A_LD];   // row-major
    __shared__ float Bs[2][GBK][B_LD];   // k-major

    const int z = blockIdx.z;
    A += (size_t)z * zAcol;
    B += (size_t)z * zBoff;
    C += (size_t)z * zCcol;

    const int tid  = threadIdx.x;
    const int warp = tid >> 5;
    const int lane = tid & 31;
    const int g = lane >> 2;
    const int q = lane & 3;
    const int warpM = (warp & 3) * 32;
    const int warpN = (warp >> 2) * 64;
    const int by = blockIdx.y * GBM;
    const int bx = blockIdx.x * GBN;

    float acc[2][8][4];
    #pragma unroll
    for (int i = 0; i < 2; i++)
        #pragma unroll
        for (int j = 0; j < 8; j++)
            #pragma unroll
            for (int l = 0; l < 4; l++) acc[i][j][l] = 0.f;

    const int ar = tid & 127;
    const int cg0 = tid >> 7;          // 0 or 1
    const int gr = by + ar;
    const int asz = (gr < M) ? 16 : 0;
    const float* ap = A + a_row_off(gr < M ? gr : M - 1, lda, gather);
    const int br = tid >> 4;
    const int bc = (tid & 15) << 2;
    const float* bp = B + (size_t)br * ldb + bx + bc;

    uint32_t sA = (uint32_t)__cvta_generic_to_shared(&As[0][ar][0]);
    uint32_t sB = (uint32_t)__cvta_generic_to_shared(&Bs[0][br][bc]);
    const uint32_t stA = sizeof(float) * GBM * A_LD;
    const uint32_t stB = sizeof(float) * GBK * B_LD;

    cp16z(sA + (cg0 * 4) * 4, ap + cg0 * 4, asz);
    cp16z(sA + ((cg0 + 2) * 4) * 4, ap + (cg0 + 2) * 4, asz);
    cp16(sB, bp);
    cp16(sB + 64 * 4, bp + 64);
    CP_COMMIT();

    int cur = 0;
    for (int k0 = 0; k0 < K; k0 += GBK) {
        CP_WAIT0();
        __syncthreads();
        if (k0 + GBK < K) {
            uint32_t oA = (cur ^ 1) * stA, oB = (cur ^ 1) * stB;
            cp16z(sA + oA + (cg0 * 4) * 4, ap + k0 + GBK + cg0 * 4, asz);
            cp16z(sA + oA + ((cg0 + 2) * 4) * 4, ap + k0 + GBK + (cg0 + 2) * 4, asz);
            cp16(sB + oB, bp + (size_t)(k0 + GBK) * ldb);
            cp16(sB + oB + 64 * 4, bp + (size_t)(k0 + GBK) * ldb + 64);
            CP_COMMIT();
        }

        #pragma unroll
        for (int kk = 0; kk < GBK; kk += 8) {
            uint32_t afr[2][4];
            #pragma unroll
            for (int mt = 0; mt < 2; mt++) {
                int r = warpM + mt * 16 + g;
                afr[mt][0] = __float_as_uint(As[cur][r][kk + q]);
                afr[mt][1] = __float_as_uint(As[cur][r + 8][kk + q]);
                afr[mt][2] = __float_as_uint(As[cur][r][kk + q + 4]);
                afr[mt][3] = __float_as_uint(As[cur][r + 8][kk + q + 4]);
            }
            uint32_t bfr[8][2];
            #pragma unroll
            for (int nt = 0; nt < 8; nt++) {
                int c = warpN + nt * 8 + g;
                bfr[nt][0] = __float_as_uint(Bs[cur][kk + q][c]);
                bfr[nt][1] = __float_as_uint(Bs[cur][kk + q + 4][c]);
            }
            #pragma unroll
            for (int mt = 0; mt < 2; mt++)
                #pragma unroll
                for (int nt = 0; nt < 8; nt++)
                    mma_tf32(acc[mt][nt], afr[mt], bfr[nt]);
        }
        cur ^= 1;
    }

    #pragma unroll
    for (int mt = 0; mt < 2; mt++) {
        #pragma unroll
        for (int nt = 0; nt < 8; nt++) {
            int col = bx + warpN + nt * 8 + 2 * q;
            float bx0 = 0.f, bx1 = 0.f;
            if (bias) { bx0 = bias[col]; bx1 = bias[col + 1]; }
            int r0 = by + warpM + mt * 16 + g;
            float v0 = acc[mt][nt][0] + bx0, v1 = acc[mt][nt][1] + bx1;
            float v2 = acc[mt][nt][2] + bx0, v3 = acc[mt][nt][3] + bx1;
            if (round_out) {
                v0 = to_tf32(v0); v1 = to_tf32(v1); v2 = to_tf32(v2); v3 = to_tf32(v3);
            }
            if (r0 < M)     *(float2*)(C + (size_t)r0 * ldc + col) = make_float2(v0, v1);
            if (r0 + 8 < M) *(float2*)(C + (size_t)(r0 + 8) * ldc + col) = make_float2(v2, v3);
        }
    }
}

// ---------------- W_pkv[:, :CC] transpose (tf32-rounded) ----------------
__global__ void transpose_wpkv_kernel(const float* __restrict__ W_pkv, float* __restrict__ wT)
{
    int idx = blockIdx.x * 256 + threadIdx.x;
    if (idx >= CC * CC) return;
    int hd = idx / CC, c = idx % CC;
    wT[(size_t)hd * CC + c] = to_tf32(W_pkv[(size_t)c * (2 * CC) + hd]);
}

// ---------------- cls attention phase A: split-softmax partials ----------
// grid (BB*HH, CLS_CH), 256 threads. Each block: <=99 tokens -> (m, z, acc[64]).
// NOTE: no vector shared-memory stores anywhere (scalar STS only).
__global__ void cls_partial_kernel(const float* __restrict__ qkv, float* __restrict__ P)
{
    const int bh = blockIdx.x;
    const int c  = blockIdx.y;
    const int b = bh / HH;
    const int h = bh % HH;
    const int base = c * CLS_CHUNK;
    const int count = min(CLS_CHUNK, NN - base);
    const int tid = threadIdx.x;

    __shared__ float qs[DD];
    __shared__ float sc[CLS_CHUNK];
    __shared__ float red[256];
    __shared__ float part16[16][DD];

    if (tid < DD) qs[tid] = qkv[(size_t)(b * NN) * C3 + h * DD + tid];
    __syncthreads();

    float s = -1e30f;
    if (tid < count) {
        const float* kr = qkv + (size_t)(b * NN + base + tid) * C3 + CC + h * DD;
        float dot = 0.f;
        #pragma unroll
        for (int d = 0; d < DD; d += 4) {
            float4 k4 = *(const float4*)(kr + d);
            dot += qs[d] * k4.x + qs[d + 1] * k4.y + qs[d + 2] * k4.z + qs[d + 3] * k4.w;
        }
        s = dot * SCALE;
        sc[tid] = s;
    }
    red[tid] = s; __syncthreads();
    for (int o = 128; o; o >>= 1) { if (tid < o) red[tid] = fmaxf(red[tid], red[tid + o]); __syncthreads(); }
    const float m = red[0];
    __syncthreads();

    float e = 0.f;
    if (tid < count) { e = __expf(sc[tid] - m); sc[tid] = e; }
    red[tid] = e; __syncthreads();
    for (int o = 128; o; o >>= 1) { if (tid < o) red[tid] += red[tid + o]; __syncthreads(); }
    const float z = red[0];
    __syncthreads();

    // PV: 16 parts x float4 GLOBAL loads (high MLP); SCALAR shared stores.
    const int part = tid >> 4;           // 0..15
    const int d4 = (tid & 15) << 2;      // 0,4,..,60
    float4 facc = make_float4(0.f, 0.f, 0.f, 0.f);
    for (int i = part; i < count; i += 16) {
        float4 v = *(const float4*)(qkv + (size_t)(b * NN + base + i) * C3 + 2 * CC + h * DD + d4);
        float sv = sc[i];
        facc.x += sv * v.x; facc.y += sv * v.y; facc.z += sv * v.z; facc.w += sv * v.w;
    }
    part16[part][d4 + 0] = facc.x;
    part16[part][d4 + 1] = facc.y;
    part16[part][d4 + 2] = facc.z;
    part16[part][d4 + 3] = facc.w;
    __syncthreads();

    float* out = P + (size_t)(bh * CLS_CH + c) * (DD + 2);
    if (tid < DD) {
        float a = 0.f;
        #pragma unroll
        for (int p = 0; p < 16; p++) a += part16[p][tid];
        out[tid] = a;
    }
    if (tid == DD)     out[DD] = m;
    if (tid == DD + 1) out[DD + 1] = z;
}

// ---------------- cls attention phase B: combine -> Y row 0 -------------
__global__ void cls_combine_kernel(const float* __restrict__ P, float* __restrict__ Y)
{
    const int bh = blockIdx.x;
    const int b = bh / HH;
    const int h = bh % HH;
    const int tid = threadIdx.x;   // 0..63

    const float* base = P + (size_t)bh * CLS_CH * (DD + 2);
    float m = -1e30f;
    #pragma unroll
    for (int c = 0; c < CLS_CH; c++) m = fmaxf(m, base[c * (DD + 2) + DD]);
    float z = 0.f, acc = 0.f;
    #pragma unroll
    for (int c = 0; c < CLS_CH; c++) {
        float sc = __expf(base[c * (DD + 2) + DD] - m);
        z += base[c * (DD + 2) + DD + 1] * sc;
        acc += base[c * (DD + 2) + tid] * sc;
    }
    Y[(size_t)(b * NN) * CC + h * DD + tid] = to_tf32(acc / z);
}

// ---------------- tensor-core space attention -> traj -------------------
// SQT=32 queries/block, 256 threads, grid = B*H*49, ~107KB smem -> 2 blocks/SM.
// (PROVEN config — thread count stays 256; do not change.)
#define SQT 32
#define BUF_LD 76
#define SC_LD 40
#define QT_LD 40
#define BUF_OFF 0
#define SC_OFF (208 * BUF_LD)                     // 15808
#define QT_OFF (SC_OFF + 208 * SC_LD)             // 24128
#define SPACE_SMEM_FLOATS (QT_OFF + 64 * QT_LD)   // 26688
#define SPACE_SMEM_BYTES (SPACE_SMEM_FLOATS * 4)  // 106752

__global__ void space_attn_kernel(const float* __restrict__ qkv, float* __restrict__ traj)
{
    extern __shared__ float smem[];
    float* Buf = smem + BUF_OFF;  // [208][76] K then V, natural [n][d]
    float* Sc  = smem + SC_OFF;   // [208][40] scores^T [n][q]
    float* Qt  = smem + QT_OFF;   // [64][40]  Q^T [d][q]
    const uint32_t sBuf = (uint32_t)__cvta_generic_to_shared(Buf);

    const int nt_blocks = SS / SQT;    // 49
    const int bh = blockIdx.x / nt_blocks;
    const int st = blockIdx.x % nt_blocks;
    const int b = bh / HH;
    const int h = bh % HH;
    const int s0 = st * SQT;
    const int tid = threadIdx.x;
    const int warp = tid >> 5;
    const int lane = tid & 31;
    const int g = lane >> 2;
    const int q = lane & 3;

    for (int idx = tid; idx < SQT * 16; idx += 256) {
        int row = idx >> 4, d4 = (idx & 15) << 2;
        float4 qv = *(const float4*)(qkv + (size_t)(b * NN + 1 + s0 + row) * C3 + h * DD + d4);
        Qt[(d4 + 0) * QT_LD + row] = qv.x;
        Qt[(d4 + 1) * QT_LD + row] = qv.y;
        Qt[(d4 + 2) * QT_LD + row] = qv.z;
        Qt[(d4 + 3) * QT_LD + row] = qv.w;
    }
    {
        int n = 196 + (tid >> 6), d = tid & 63;
        Buf[n * BUF_LD + d] = 0.f;
    }

    for (int f = 0; f < FF; f++) {
        __syncthreads();

        const size_t frameRow = (size_t)(b * NN + 1 + f * PP);
        for (int idx = tid; idx < PP * 16; idx += 256) {
            int n = idx >> 4, d4 = (idx & 15) << 2;
            cp16(sBuf + (uint32_t)(n * BUF_LD + d4) * 4u,
                 qkv + (frameRow + n) * C3 + CC + h * DD + d4);
        }
        CP_COMMIT();
        CP_WAIT0();
        __syncthreads();

        // ---- QK: warp handles m-tiles {warp, warp+8}; b-frags hoisted ----
        {
            const int mt0 = warp;
            const int mt1 = warp + 8;
            const int m0 = mt0 * 16;
            const int m1 = mt1 * 16;
            const bool has1 = (mt1 < 13);
            float acc0[4][4], acc1[4][4];
            #pragma unroll
            for (int i = 0; i < 4; i++)
                #pragma unroll
                for (int j = 0; j < 4; j++) { acc0[i][j] = 0.f; acc1[i][j] = 0.f; }
            #pragma unroll
            for (int kb = 0; kb < 8; kb++) {
                const int k0 = kb * 8;
                uint32_t bfr[4][2];
                #pragma unroll
                for (int nt = 0; nt < 4; nt++) {
                    bfr[nt][0] = __float_as_uint(Qt[(k0 + q) * QT_LD + nt * 8 + g]);
                    bfr[nt][1] = __float_as_uint(Qt[(k0 + q + 4) * QT_LD + nt * 8 + g]);
                }
                uint32_t a[4];
                a[0] = __float_as_uint(Buf[(m0 + g) * BUF_LD + k0 + q]);
                a[1] = __float_as_uint(Buf[(m0 + 8 + g) * BUF_LD + k0 + q]);
                a[2] = __float_as_uint(Buf[(m0 + g) * BUF_LD + k0 + q + 4]);
                a[3] = __float_as_uint(Buf[(m0 + 8 + g) * BUF_LD + k0 + q + 4]);
                #pragma unroll
                for (int nt = 0; nt < 4; nt++) mma_tf32(acc0[nt], a, bfr[nt]);
                if (has1) {
                    uint32_t a1[4];
                    a1[0] = __float_as_uint(Buf[(m1 + g) * BUF_LD + k0 + q]);
                    a1[1] = __float_as_uint(Buf[(m1 + 8 + g) * BUF_LD + k0 + q]);
                    a1[2] = __float_as_uint(Buf[(m1 + g) * BUF_LD + k0 + q + 4]);
                    a1[3] = __float_as_uint(Buf[(m1 + 8 + g) * BUF_LD + k0 + q + 4]);
                    #pragma unroll
                    for (int nt = 0; nt < 4; nt++) mma_tf32(acc1[nt], a1, bfr[nt]);
                }
            }
            #pragma unroll
            for (int nt = 0; nt < 4; nt++) {
                int c0 = nt * 8 + 2 * q;
                *(float2*)&Sc[(m0 + g) * SC_LD + c0] =
                    make_float2(acc0[nt][0] * SCALE, acc0[nt][1] * SCALE);
                *(float2*)&Sc[(m0 + 8 + g) * SC_LD + c0] =
                    make_float2(acc0[nt][2] * SCALE, acc0[nt][3] * SCALE);
            }
            if (has1) {
                #pragma unroll
                for (int nt = 0; nt < 4; nt++) {
                    int c0 = nt * 8 + 2 * q;
                    *(float2*)&Sc[(m1 + g) * SC_LD + c0] =
                        make_float2(acc1[nt][0] * SCALE, acc1[nt][1] * SCALE);
                    *(float2*)&Sc[(m1 + 8 + g) * SC_LD + c0] =
                        make_float2(acc1[nt][2] * SCALE, acc1[nt][3] * SCALE);
                }
            }
        }
        __syncthreads();

        // ---- V via cp.async (overlaps softmax) ----
        for (int idx = tid; idx < PP * 16; idx += 256) {
            int n = idx >> 4, d4 = (idx & 15) << 2;
            cp16(sBuf + (uint32_t)(n * BUF_LD + d4) * 4u,
                 qkv + (frameRow + n) * C3 + 2 * CC + h * DD + d4);
        }
        CP_COMMIT();

        {
            const int col = tid >> 3, r = tid & 7;
            float m = -1e30f;
            for (int n = r; n < PP; n += 8) m = fmaxf(m, Sc[n * SC_LD + col]);
            #pragma unroll
            for (int o = 4; o; o >>= 1) m = fmaxf(m, __shfl_xor_sync(0xffffffffu, m, o));
            float z = 0.f;
            for (int n = r; n < PP; n += 8) {
                float e = __expf(Sc[n * SC_LD + col] - m);
                Sc[n * SC_LD + col] = e;
                z += e;
            }
            #pragma unroll
            for (int o = 4; o; o >>= 1) z += __shfl_xor_sync(0xffffffffu, z, o);
            float inv = 1.f / z;
            for (int n = r; n < PP; n += 8)
                Sc[n * SC_LD + col] = to_tf32(Sc[n * SC_LD + col] * inv);
        }
        if (tid < 128) Sc[(196 + (tid >> 5)) * SC_LD + (tid & 31)] = 0.f;
        CP_WAIT0();
        __syncthreads();

        // ---- PV: 4 warps, 1 m-tile x 4 d-tiles each ----
        if (warp < 4) {
            const int mt = warp & 1;
            const int dgrp = warp >> 1;
            const int m0 = mt * 16;
            float acc[4][4];
            #pragma unroll
            for (int j = 0; j < 4; j++)
                #pragma unroll
                for (int l = 0; l < 4; l++) acc[j][l] = 0.f;
            for (int kb = 0; kb < 25; kb++) {
                const int k0 = kb * 8;
                uint32_t a[4];
                a[0] = __float_as_uint(Sc[(k0 + q) * SC_LD + m0 + g]);
                a[1] = __float_as_uint(Sc[(k0 + q) * SC_LD + m0 + 8 + g]);
                a[2] = __float_as_uint(Sc[(k0 + q + 4) * SC_LD + m0 + g]);
                a[3] = __float_as_uint(Sc[(k0 + q + 4) * SC_LD + m0 + 8 + g]);
                #pragma unroll
                for (int j = 0; j < 4; j++) {
                    const int d0 = dgrp * 32 + j * 8;
                    uint32_t bfr[2];
                    bfr[0] = __float_as_uint(Buf[(k0 + q) * BUF_LD + d0 + g]);
                    bfr[1] = __float_as_uint(Buf[(k0 + q + 4) * BUF_LD + d0 + g]);
                    mma_tf32(acc[j], a, bfr);
                }
            }
            #pragma unroll
            for (int j = 0; j < 4; j++) {
                const int d0 = dgrp * 32 + j * 8;
                const int col = h * DD + d0 + 2 * q;
                const int row0 = s0 + m0 + g;
                *(float2*)(traj + ((size_t)(b * SS + row0) * FF + f) * CC + col) =
                    make_float2(to_tf32(acc[j][0]), to_tf32(acc[j][1]));
                *(float2*)(traj + ((size_t)(b * SS + row0 + 8) * FF + f) * CC + col) =
                    make_float2(to_tf32(acc[j][2]), to_tf32(acc[j][3]));
            }
        }
    }
}

// ---------------- frame attention (fused logits) ----------------
__global__ void frame_attn_kernel(const float* __restrict__ w, const float* __restrict__ traj,
                                  float* __restrict__ Y, float* __restrict__ attn_out)
{
    const int bs = blockIdx.x;
    const int b = bs / SS;
    const int s = bs % SS;
    const int tid = threadIdx.x;
    const int h = tid >> 5;      // warp = head
    const int lane = tid & 31;

    __shared__ float ts[FF][CC];
    __shared__ float a_sm[HH][FF];

    for (int idx = tid; idx < FF * CC / 4; idx += 384) {
        int f = idx / 192, j = idx % 192;
        float4 v = *(const float4*)(traj + ((size_t)bs * FF + f) * CC + j * 4);
        *(float4*)&ts[f][j * 4] = v;
    }
    __syncthreads();

    const float* wrow = w + (size_t)bs * W12 + h * CC;
    float wreg[24];
    #pragma unroll
    for (int j = 0; j < 24; j++) wreg[j] = wrow[lane + 32 * j];

    float lg[FF];
    #pragma unroll
    for (int f = 0; f < FF; f++) {
        float dsum = 0.f;
        #pragma unroll
        for (int j = 0; j < 24; j++) dsum += wreg[j] * ts[f][lane + 32 * j];
        #pragma unroll
        for (int o = 16; o; o >>= 1) dsum += __shfl_xor_sync(0xffffffffu, dsum, o);
        lg[f] = dsum * SCALE;
    }
    float m = -1e30f;
    #pragma unroll
    for (int f = 0; f < FF; f++) m = fmaxf(m, lg[f]);
    float z = 0.f;
    #pragma unroll
    for (int f = 0; f < FF; f++) { lg[f] = __expf(lg[f] - m); z += lg[f]; }
    float inv = 1.f / z;
    #pragma unroll
    for (int f = 0; f < FF; f++) lg[f] *= inv;

    if (lane < FF) {
        a_sm[h][lane] = lg[lane];
        attn_out[(((size_t)b * HH + h) * SS + s) * FF + lane] = lg[lane];
    }
    __syncthreads();

    #pragma unroll
    for (int rep = 0; rep < 2; rep++) {
        int c = tid + rep * 384;
        int h2 = c >> 6;
        float o = 0.f;
        #pragma unroll
        for (int f = 0; f < FF; f++) o += a_sm[h2][f] * ts[f][c];
        Y[(size_t)(b * NN + 1 + s) * CC + c] = to_tf32(o);
    }
}

// ---------------- launcher ----------------
extern "C" void kernel_launch(void* const* d_in, const int* in_sizes, int n_in,
                              void* d_out, int out_size)
{
    const float* x      = (const float*)d_in[0];
    const float* W_qkv  = (const float*)d_in[1];
    const float* W_pq   = (const float*)d_in[2];
    const float* W_pkv  = (const float*)d_in[3];
    const float* W_proj = (const float*)d_in[4];
    const float* b_proj = (const float*)d_in[5];
    (void)in_sizes; (void)n_in;

    float *qkv, *traj, *q2, *w, *wT, *Y, *rx, *rwq, *rwpq, *rwproj, *clsP;
    cudaGetSymbolAddress((void**)&qkv,    g_qkv);
    cudaGetSymbolAddress((void**)&traj,   g_traj);
    cudaGetSymbolAddress((void**)&q2,     g_q2);
    cudaGetSymbolAddress((void**)&w,      g_w);
    cudaGetSymbolAddress((void**)&wT,     g_wT);
    cudaGetSymbolAddress((void**)&Y,      g_Y);
    cudaGetSymbolAddress((void**)&rx,     g_x);
    cudaGetSymbolAddress((void**)&rwq,    g_wq);
    cudaGetSymbolAddress((void**)&rwpq,   g_wpq);
    cudaGetSymbolAddress((void**)&rwproj, g_wproj);
    cudaGetSymbolAddress((void**)&clsP,   g_clsP);

    float* out_main = (float*)d_out;                                   // (B,N,C)
    float* out_attn = out_main + (size_t)BB * NN * CC;                 // (B,h,S,F)

    static int smem_set = 0;
    if (!smem_set) {
        cudaFuncSetAttribute(space_attn_kernel,
                             cudaFuncAttributeMaxDynamicSharedMemorySize, SPACE_SMEM_BYTES);
        smem_set = 1;
    }

    const int M1 = BB * NN;   // 3138
    const int M2 = BB * SS;   // 3136

    // 0) round inputs to tf32 + transpose W_pkv K-half
    {
        int t4 = (XSZ + WQSZ + 2 * WPSZ) / 4;
        round_inputs_kernel<<<(t4 + 255) / 256, 256>>>(x, W_qkv, W_pq, W_proj,
                                                       rx, rwq, rwpq, rwproj);
        transpose_wpkv_kernel<<<(CC * CC + 255) / 256, 256>>>(W_pkv, wT);
    }
    // 1) qkv = x @ W_qkv (tf32-rounded output)
    {
        dim3 grid(C3 / GBN, (M1 + GBM - 1) / GBM);
        tf32_gemm_kernel<<<grid, 256>>>(rx, rwq, qkv, M1, C3, CC, CC, C3, C3,
                                        nullptr, 0, 1, 0, 0, 0);
    }
    // 2) cls attention (split-softmax, 16 chunks) -> Y row 0 per batch
    {
        dim3 gridA(BB * HH, CLS_CH);
        cls_partial_kernel<<<gridA, 256>>>(qkv, clsP);
        cls_combine_kernel<<<BB * HH, 64>>>(clsP, Y);
    }
    // 3) space attention -> traj (256 threads, 2 blocks/SM — proven config)
    space_attn_kernel<<<BB * HH * (SS / SQT), 256, SPACE_SMEM_BYTES>>>(qkv, traj);
    // 4) q2 = xdiag @ W_pq with fused diagonal gather (tf32-rounded output)
    {
        dim3 grid(CC / GBN, (M2 + GBM - 1) / GBM);
        tf32_gemm_kernel<<<grid, 256>>>(traj, rwpq, q2, M2, CC, CC, CC, CC, CC,
                                        nullptr, 1, 1, 0, 0, 0);
    }
    // 5) w[bs,h,:] = q2[bs,h-block] @ W_pkv_h^T   (batched over z = head)
    {
        dim3 grid(CC / GBN, (M2 + GBM - 1) / GBM, HH);
        tf32_gemm_kernel<<<grid, 256>>>(q2, wT, w, M2, CC, DD, CC, CC, W12,
                                        nullptr, 0, 0, DD, DD * CC, CC);
    }
    // 6) frame attention (fused logits) -> attn output + Y rows 1..S
    frame_attn_kernel<<<BB * SS, 384>>>(w, traj, Y, out_attn);
    // 7) out = Y @ W_proj + b_proj (final, unrounded)
    {
        dim3 grid(CC / GBN, (M1 + GBM - 1) / GBM);
        tf32_gemm_kernel<<<grid, 256>>>(Y, rwproj, out_main, M1, CC, CC, CC, CC, CC,
                                        b_proj, 0, 0, 0, 0, 0);
    }
}

// round 16
// speedup vs baseline: 4.6091x; 1.0395x over previous
#include <cuda_runtime.h>
#include <cuda_bf16.h>
#include <math.h>
#include <stdint.h>

// Problem constants
#define BB 2
#define NN 1569          // tokens incl cls
#define CC 768
#define HH 12
#define DD 64
#define PP 196
#define FF 8
#define SS 1568          // F*P
#define C3 2304          // 3*C
#define W12 9216         // 12*768
#define SCALE 0.125f
#define CLS_CH 16        // cls split-softmax chunks
#define CLS_CHUNK 99     // ceil(NN/CLS_CH)

// ---------------- device scratch (no allocations allowed) ----------------
__device__ float g_qkv[(size_t)BB * NN * C3];          // (B*N, 3C)
__device__ float g_traj[(size_t)BB * SS * FF * CC];    // (B,S,F,C)
__device__ float g_q2[(size_t)BB * SS * CC];           // (B*S, C)
__device__ float g_w[(size_t)BB * SS * W12];           // (B*S, H, C) fused k2 weights
__device__ float g_wT[(size_t)CC * CC];                // W_pkv[:, :CC]^T (tf32)
__device__ float g_Y[(size_t)BB * NN * CC];            // (B*N, C) concat[cls,out]
__device__ float g_x[(size_t)BB * NN * CC];            // tf32-rounded x
__device__ float g_wq[(size_t)CC * C3];                // tf32-rounded W_qkv
__device__ float g_wpq[(size_t)CC * CC];               // tf32-rounded W_pq
__device__ float g_wproj[(size_t)CC * CC];             // tf32-rounded W_proj
__device__ float g_clsP[(size_t)BB * HH * CLS_CH * (DD + 2)];  // cls partials

__device__ __forceinline__ float to_tf32(float x) {
    uint32_t u;
    asm("cvt.rna.tf32.f32 %0, %1;" : "=r"(u) : "f"(x));
    return __uint_as_float(u);
}

__device__ __forceinline__ void mma_tf32(float (&c)[4], const uint32_t (&a)[4], const uint32_t (&b)[2]) {
    asm volatile(
        "mma.sync.aligned.m16n8k8.row.col.f32.tf32.tf32.f32 "
        "{%0,%1,%2,%3}, {%4,%5,%6,%7}, {%8,%9}, {%0,%1,%2,%3};"
        : "+f"(c[0]), "+f"(c[1]), "+f"(c[2]), "+f"(c[3])
        : "r"(a[0]), "r"(a[1]), "r"(a[2]), "r"(a[3]), "r"(b[0]), "r"(b[1]));
}

__device__ __forceinline__ void cp16(uint32_t dst, const void* src) {
    asm volatile("cp.async.cg.shared.global [%0], [%1], 16;" :: "r"(dst), "l"(src));
}
__device__ __forceinline__ void cp16z(uint32_t dst, const void* src, int sz) {
    asm volatile("cp.async.cg.shared.global [%0], [%1], 16, %2;" :: "r"(dst), "l"(src), "r"(sz));
}
#define CP_COMMIT() asm volatile("cp.async.commit_group;")
#define CP_WAIT0()  asm volatile("cp.async.wait_group 0;")

// ---------------- input tf32-rounding prep ----------------
#define XSZ  (BB * NN * CC)    // 2409984
#define WQSZ (CC * C3)         // 1769472
#define WPSZ (CC * CC)         // 589824
__global__ void round_inputs_kernel(const float* __restrict__ x, const float* __restrict__ Wq,
                                    const float* __restrict__ Wpq, const float* __restrict__ Wpr,
                                    float* __restrict__ rx, float* __restrict__ rwq,
                                    float* __restrict__ rwpq, float* __restrict__ rwpr)
{
    const int T4 = (XSZ + WQSZ + 2 * WPSZ) / 4;
    int idx4 = blockIdx.x * 256 + threadIdx.x;
    if (idx4 >= T4) return;
    int i = idx4 * 4;
    const float* s; float* d; int off;
    if (i < XSZ)                    { s = x;   d = rx;   off = i; }
    else if (i < XSZ + WQSZ)        { s = Wq;  d = rwq;  off = i - XSZ; }
    else if (i < XSZ + WQSZ + WPSZ) { s = Wpq; d = rwpq; off = i - XSZ - WQSZ; }
    else                            { s = Wpr; d = rwpr; off = i - XSZ - WQSZ - WPSZ; }
    float4 v = *(const float4*)(s + off);
    v.x = to_tf32(v.x); v.y = to_tf32(v.y); v.z = to_tf32(v.z); v.w = to_tf32(v.w);
    *(float4*)(d + off) = v;
}

// ---------------- TF32 tensor-core GEMM, cp.async double-buffered ----------
#define GBM 128
#define GBN 128
#define GBK 16
#define A_LD 20
#define B_LD 136

__device__ __forceinline__ size_t a_row_off(int gr, int lda, int gather) {
    if (gather) {
        int s = gr % SS;
        gr = gr * FF + s / PP;
    }
    return (size_t)gr * lda;
}

__global__ void tf32_gemm_kernel(const float* __restrict__ A, const float* __restrict__ B,
                                 float* __restrict__ C, int M, int N, int K,
                                 int lda, int ldb, int ldc,
                                 const float* __restrict__ bias, int gather, int round_out,
                                 int zAcol, int zBoff, int zCcol)
{
    __shared__ float As[2][GBM][A_LD];   // row-major
    __shared__ float Bs[2][GBK][B_LD];   // k-major

    const int z = blockIdx.z;
    A += (size_t)z * zAcol;
    B += (size_t)z * zBoff;
    C += (size_t)z * zCcol;

    const int tid  = threadIdx.x;
    const int warp = tid >> 5;
    const int lane = tid & 31;
    const int g = lane >> 2;
    const int q = lane & 3;
    const int warpM = (warp & 3) * 32;
    const int warpN = (warp >> 2) * 64;
    const int by = blockIdx.y * GBM;
    const int bx = blockIdx.x * GBN;

    float acc[2][8][4];
    #pragma unroll
    for (int i = 0; i < 2; i++)
        #pragma unroll
        for (int j = 0; j < 8; j++)
            #pragma unroll
            for (int l = 0; l < 4; l++) acc[i][j][l] = 0.f;

    const int ar = tid & 127;
    const int cg0 = tid >> 7;          // 0 or 1
    const int gr = by + ar;
    const int asz = (gr < M) ? 16 : 0;
    const float* ap = A + a_row_off(gr < M ? gr : M - 1, lda, gather);
    const int br = tid >> 4;
    const int bc = (tid & 15) << 2;
    const float* bp = B + (size_t)br * ldb + bx + bc;

    uint32_t sA = (uint32_t)__cvta_generic_to_shared(&As[0][ar][0]);
    uint32_t sB = (uint32_t)__cvta_generic_to_shared(&Bs[0][br][bc]);
    const uint32_t stA = sizeof(float) * GBM * A_LD;
    const uint32_t stB = sizeof(float) * GBK * B_LD;

    cp16z(sA + (cg0 * 4) * 4, ap + cg0 * 4, asz);
    cp16z(sA + ((cg0 + 2) * 4) * 4, ap + (cg0 + 2) * 4, asz);
    cp16(sB, bp);
    cp16(sB + 64 * 4, bp + 64);
    CP_COMMIT();

    int cur = 0;
    for (int k0 = 0; k0 < K; k0 += GBK) {
        CP_WAIT0();
        __syncthreads();
        if (k0 + GBK < K) {
            uint32_t oA = (cur ^ 1) * stA, oB = (cur ^ 1) * stB;
            cp16z(sA + oA + (cg0 * 4) * 4, ap + k0 + GBK + cg0 * 4, asz);
            cp16z(sA + oA + ((cg0 + 2) * 4) * 4, ap + k0 + GBK + (cg0 + 2) * 4, asz);
            cp16(sB + oB, bp + (size_t)(k0 + GBK) * ldb);
            cp16(sB + oB + 64 * 4, bp + (size_t)(k0 + GBK) * ldb + 64);
            CP_COMMIT();
        }

        #pragma unroll
        for (int kk = 0; kk < GBK; kk += 8) {
            uint32_t afr[2][4];
            #pragma unroll
            for (int mt = 0; mt < 2; mt++) {
                int r = warpM + mt * 16 + g;
                afr[mt][0] = __float_as_uint(As[cur][r][kk + q]);
                afr[mt][1] = __float_as_uint(As[cur][r + 8][kk + q]);
                afr[mt][2] = __float_as_uint(As[cur][r][kk + q + 4]);
                afr[mt][3] = __float_as_uint(As[cur][r + 8][kk + q + 4]);
            }
            uint32_t bfr[8][2];
            #pragma unroll
            for (int nt = 0; nt < 8; nt++) {
                int c = warpN + nt * 8 + g;
                bfr[nt][0] = __float_as_uint(Bs[cur][kk + q][c]);
                bfr[nt][1] = __float_as_uint(Bs[cur][kk + q + 4][c]);
            }
            #pragma unroll
            for (int mt = 0; mt < 2; mt++)
                #pragma unroll
                for (int nt = 0; nt < 8; nt++)
                    mma_tf32(acc[mt][nt], afr[mt], bfr[nt]);
        }
        cur ^= 1;
    }

    #pragma unroll
    for (int mt = 0; mt < 2; mt++) {
        #pragma unroll
        for (int nt = 0; nt < 8; nt++) {
            int col = bx + warpN + nt * 8 + 2 * q;
            float bx0 = 0.f, bx1 = 0.f;
            if (bias) { bx0 = bias[col]; bx1 = bias[col + 1]; }
            int r0 = by + warpM + mt * 16 + g;
            float v0 = acc[mt][nt][0] + bx0, v1 = acc[mt][nt][1] + bx1;
            float v2 = acc[mt][nt][2] + bx0, v3 = acc[mt][nt][3] + bx1;
            if (round_out) {
                v0 = to_tf32(v0); v1 = to_tf32(v1); v2 = to_tf32(v2); v3 = to_tf32(v3);
            }
            if (r0 < M)     *(float2*)(C + (size_t)r0 * ldc + col) = make_float2(v0, v1);
            if (r0 + 8 < M) *(float2*)(C + (size_t)(r0 + 8) * ldc + col) = make_float2(v2, v3);
        }
    }
}

// ---------------- W_pkv[:, :CC] transpose (tf32-rounded) ----------------
__global__ void transpose_wpkv_kernel(const float* __restrict__ W_pkv, float* __restrict__ wT)
{
    int idx = blockIdx.x * 256 + threadIdx.x;
    if (idx >= CC * CC) return;
    int hd = idx / CC, c = idx % CC;
    wT[(size_t)hd * CC + c] = to_tf32(W_pkv[(size_t)c * (2 * CC) + hd]);
}

// ---------------- cls attention phase A: split-softmax partials ----------
// grid (BB*HH, CLS_CH), 256 threads. Scalar shared stores only.
__global__ void cls_partial_kernel(const float* __restrict__ qkv, float* __restrict__ P)
{
    const int bh = blockIdx.x;
    const int c  = blockIdx.y;
    const int b = bh / HH;
    const int h = bh % HH;
    const int base = c * CLS_CHUNK;
    const int count = min(CLS_CHUNK, NN - base);
    const int tid = threadIdx.x;

    __shared__ float qs[DD];
    __shared__ float sc[CLS_CHUNK];
    __shared__ float red[256];
    __shared__ float part16[16][DD];

    if (tid < DD) qs[tid] = qkv[(size_t)(b * NN) * C3 + h * DD + tid];
    __syncthreads();

    float s = -1e30f;
    if (tid < count) {
        const float* kr = qkv + (size_t)(b * NN + base + tid) * C3 + CC + h * DD;
        float dot = 0.f;
        #pragma unroll
        for (int d = 0; d < DD; d += 4) {
            float4 k4 = *(const float4*)(kr + d);
            dot += qs[d] * k4.x + qs[d + 1] * k4.y + qs[d + 2] * k4.z + qs[d + 3] * k4.w;
        }
        s = dot * SCALE;
        sc[tid] = s;
    }
    red[tid] = s; __syncthreads();
    for (int o = 128; o; o >>= 1) { if (tid < o) red[tid] = fmaxf(red[tid], red[tid + o]); __syncthreads(); }
    const float m = red[0];
    __syncthreads();

    float e = 0.f;
    if (tid < count) { e = __expf(sc[tid] - m); sc[tid] = e; }
    red[tid] = e; __syncthreads();
    for (int o = 128; o; o >>= 1) { if (tid < o) red[tid] += red[tid + o]; __syncthreads(); }
    const float z = red[0];
    __syncthreads();

    const int part = tid >> 4;           // 0..15
    const int d4 = (tid & 15) << 2;      // 0,4,..,60
    float4 facc = make_float4(0.f, 0.f, 0.f, 0.f);
    for (int i = part; i < count; i += 16) {
        float4 v = *(const float4*)(qkv + (size_t)(b * NN + base + i) * C3 + 2 * CC + h * DD + d4);
        float sv = sc[i];
        facc.x += sv * v.x; facc.y += sv * v.y; facc.z += sv * v.z; facc.w += sv * v.w;
    }
    part16[part][d4 + 0] = facc.x;
    part16[part][d4 + 1] = facc.y;
    part16[part][d4 + 2] = facc.z;
    part16[part][d4 + 3] = facc.w;
    __syncthreads();

    float* out = P + (size_t)(bh * CLS_CH + c) * (DD + 2);
    if (tid < DD) {
        float a = 0.f;
        #pragma unroll
        for (int p = 0; p < 16; p++) a += part16[p][tid];
        out[tid] = a;
    }
    if (tid == DD)     out[DD] = m;
    if (tid == DD + 1) out[DD + 1] = z;
}

// ---------------- cls attention phase B: combine -> Y row 0 -------------
__global__ void cls_combine_kernel(const float* __restrict__ P, float* __restrict__ Y)
{
    const int bh = blockIdx.x;
    const int b = bh / HH;
    const int h = bh % HH;
    const int tid = threadIdx.x;   // 0..63

    const float* base = P + (size_t)bh * CLS_CH * (DD + 2);
    float m = -1e30f;
    #pragma unroll
    for (int c = 0; c < CLS_CH; c++) m = fmaxf(m, base[c * (DD + 2) + DD]);
    float z = 0.f, acc = 0.f;
    #pragma unroll
    for (int c = 0; c < CLS_CH; c++) {
        float sc = __expf(base[c * (DD + 2) + DD] - m);
        z += base[c * (DD + 2) + DD + 1] * sc;
        acc += base[c * (DD + 2) + tid] * sc;
    }
    Y[(size_t)(b * NN) * CC + h * DD + tid] = to_tf32(acc / z);
}

// ---------------- tensor-core space attention -> traj -------------------
// SQT=32 queries/block, 256 threads, grid = B*H*49, ~107KB smem -> 2 blocks/SM.
// Softmax is 2-pass; P stored as unnormalized tf32 exp values, 1/z fused into PV.
// inv[query] lives in dead Sc row 200.
#define SQT 32
#define BUF_LD 76
#define SC_LD 40
#define QT_LD 40
#define BUF_OFF 0
#define SC_OFF (208 * BUF_LD)                     // 15808
#define QT_OFF (SC_OFF + 208 * SC_LD)             // 24128
#define SPACE_SMEM_FLOATS (QT_OFF + 64 * QT_LD)   // 26688
#define SPACE_SMEM_BYTES (SPACE_SMEM_FLOATS * 4)  // 106752
#define INV_ROW 200

__global__ void space_attn_kernel(const float* __restrict__ qkv, float* __restrict__ traj)
{
    extern __shared__ float smem[];
    float* Buf = smem + BUF_OFF;  // [208][76] K then V, natural [n][d]
    float* Sc  = smem + SC_OFF;   // [208][40] scores^T [n][q]; row 200 = inv
    float* Qt  = smem + QT_OFF;   // [64][40]  Q^T [d][q]
    const uint32_t sBuf = (uint32_t)__cvta_generic_to_shared(Buf);

    const int nt_blocks = SS / SQT;    // 49
    const int bh = blockIdx.x / nt_blocks;
    const int st = blockIdx.x % nt_blocks;
    const int b = bh / HH;
    const int h = bh % HH;
    const int s0 = st * SQT;
    const int tid = threadIdx.x;
    const int warp = tid >> 5;
    const int lane = tid & 31;
    const int g = lane >> 2;
    const int q = lane & 3;

    for (int idx = tid; idx < SQT * 16; idx += 256) {
        int row = idx >> 4, d4 = (idx & 15) << 2;
        float4 qv = *(const float4*)(qkv + (size_t)(b * NN + 1 + s0 + row) * C3 + h * DD + d4);
        Qt[(d4 + 0) * QT_LD + row] = qv.x;
        Qt[(d4 + 1) * QT_LD + row] = qv.y;
        Qt[(d4 + 2) * QT_LD + row] = qv.z;
        Qt[(d4 + 3) * QT_LD + row] = qv.w;
    }
    // zero Buf pad rows 196..199 once; K/V loads never touch them again,
    // so QK emits exact zeros into Sc pad rows each frame (no re-zeroing needed).
    {
        int n = 196 + (tid >> 6), d = tid & 63;
        Buf[n * BUF_LD + d] = 0.f;
    }

    for (int f = 0; f < FF; f++) {
        __syncthreads();

        const size_t frameRow = (size_t)(b * NN + 1 + f * PP);
        for (int idx = tid; idx < PP * 16; idx += 256) {
            int n = idx >> 4, d4 = (idx & 15) << 2;
            cp16(sBuf + (uint32_t)(n * BUF_LD + d4) * 4u,
                 qkv + (frameRow + n) * C3 + CC + h * DD + d4);
        }
        CP_COMMIT();
        CP_WAIT0();
        __syncthreads();

        // ---- QK: warp handles m-tiles {warp, warp+8}; b-frags hoisted ----
        {
            const int mt0 = warp;
            const int mt1 = warp + 8;
            const int m0 = mt0 * 16;
            const int m1 = mt1 * 16;
            const bool has1 = (mt1 < 13);
            float acc0[4][4], acc1[4][4];
            #pragma unroll
            for (int i = 0; i < 4; i++)
                #pragma unroll
                for (int j = 0; j < 4; j++) { acc0[i][j] = 0.f; acc1[i][j] = 0.f; }
            #pragma unroll
            for (int kb = 0; kb < 8; kb++) {
                const int k0 = kb * 8;
                uint32_t bfr[4][2];
                #pragma unroll
                for (int nt = 0; nt < 4; nt++) {
                    bfr[nt][0] = __float_as_uint(Qt[(k0 + q) * QT_LD + nt * 8 + g]);
                    bfr[nt][1] = __float_as_uint(Qt[(k0 + q + 4) * QT_LD + nt * 8 + g]);
                }
                uint32_t a[4];
                a[0] = __float_as_uint(Buf[(m0 + g) * BUF_LD + k0 + q]);
                a[1] = __float_as_uint(Buf[(m0 + 8 + g) * BUF_LD + k0 + q]);
                a[2] = __float_as_uint(Buf[(m0 + g) * BUF_LD + k0 + q + 4]);
                a[3] = __float_as_uint(Buf[(m0 + 8 + g) * BUF_LD + k0 + q + 4]);
                #pragma unroll
                for (int nt = 0; nt < 4; nt++) mma_tf32(acc0[nt], a, bfr[nt]);
                if (has1) {
                    uint32_t a1[4];
                    a1[0] = __float_as_uint(Buf[(m1 + g) * BUF_LD + k0 + q]);
                    a1[1] = __float_as_uint(Buf[(m1 + 8 + g) * BUF_LD + k0 + q]);
                    a1[2] = __float_as_uint(Buf[(m1 + g) * BUF_LD + k0 + q + 4]);
                    a1[3] = __float_as_uint(Buf[(m1 + 8 + g) * BUF_LD + k0 + q + 4]);
                    #pragma unroll
                    for (int nt = 0; nt < 4; nt++) mma_tf32(acc1[nt], a1, bfr[nt]);
                }
            }
            #pragma unroll
            for (int nt = 0; nt < 4; nt++) {
                int c0 = nt * 8 + 2 * q;
                *(float2*)&Sc[(m0 + g) * SC_LD + c0] =
                    make_float2(acc0[nt][0] * SCALE, acc0[nt][1] * SCALE);
                *(float2*)&Sc[(m0 + 8 + g) * SC_LD + c0] =
                    make_float2(acc0[nt][2] * SCALE, acc0[nt][3] * SCALE);
            }
            if (has1) {
                #pragma unroll
                for (int nt = 0; nt < 4; nt++) {
                    int c0 = nt * 8 + 2 * q;
                    *(float2*)&Sc[(m1 + g) * SC_LD + c0] =
                        make_float2(acc1[nt][0] * SCALE, acc1[nt][1] * SCALE);
                    *(float2*)&Sc[(m1 + 8 + g) * SC_LD + c0] =
                        make_float2(acc1[nt][2] * SCALE, acc1[nt][3] * SCALE);
                }
            }
        }
        __syncthreads();

        // ---- V via cp.async (overlaps softmax) ----
        for (int idx = tid; idx < PP * 16; idx += 256) {
            int n = idx >> 4, d4 = (idx & 15) << 2;
            cp16(sBuf + (uint32_t)(n * BUF_LD + d4) * 4u,
                 qkv + (frameRow + n) * C3 + 2 * CC + h * DD + d4);
        }
        CP_COMMIT();

        // ---- 2-pass softmax: pass2 writes tf32 exp values; inv stored in row 200
        {
            const int col = tid >> 3, r = tid & 7;
            float m = -1e30f;
            for (int n = r; n < PP; n += 8) m = fmaxf(m, Sc[n * SC_LD + col]);
            #pragma unroll
            for (int o = 4; o; o >>= 1) m = fmaxf(m, __shfl_xor_sync(0xffffffffu, m, o));
            float z = 0.f;
            for (int n = r; n < PP; n += 8) {
                float e = to_tf32(__expf(Sc[n * SC_LD + col] - m));
                Sc[n * SC_LD + col] = e;
                z += e;
            }
            #pragma unroll
            for (int o = 4; o; o >>= 1) z += __shfl_xor_sync(0xffffffffu, z, o);
            if (r == 0) Sc[INV_ROW * SC_LD + col] = 1.f / z;
        }
        CP_WAIT0();
        __syncthreads();

        // ---- PV: 4 warps, 1 m-tile x 4 d-tiles; scale by inv at epilogue ----
        if (warp < 4) {
            const int mt = warp & 1;
            const int dgrp = warp >> 1;
            const int m0 = mt * 16;
            float acc[4][4];
            #pragma unroll
            for (int j = 0; j < 4; j++)
                #pragma unroll
                for (int l = 0; l < 4; l++) acc[j][l] = 0.f;
            for (int kb = 0; kb < 25; kb++) {
                const int k0 = kb * 8;
                uint32_t a[4];
                a[0] = __float_as_uint(Sc[(k0 + q) * SC_LD + m0 + g]);
                a[1] = __float_as_uint(Sc[(k0 + q) * SC_LD + m0 + 8 + g]);
                a[2] = __float_as_uint(Sc[(k0 + q + 4) * SC_LD + m0 + g]);
                a[3] = __float_as_uint(Sc[(k0 + q + 4) * SC_LD + m0 + 8 + g]);
                #pragma unroll
                for (int j = 0; j < 4; j++) {
                    const int d0 = dgrp * 32 + j * 8;
                    uint32_t bfr[2];
                    bfr[0] = __float_as_uint(Buf[(k0 + q) * BUF_LD + d0 + g]);
                    bfr[1] = __float_as_uint(Buf[(k0 + q + 4) * BUF_LD + d0 + g]);
                    mma_tf32(acc[j], a, bfr);
                }
            }
            const float inv0 = Sc[INV_ROW * SC_LD + m0 + g];
            const float inv1 = Sc[INV_ROW * SC_LD + m0 + 8 + g];
            #pragma unroll
            for (int j = 0; j < 4; j++) {
                const int d0 = dgrp * 32 + j * 8;
                const int col = h * DD + d0 + 2 * q;
                const int row0 = s0 + m0 + g;
                *(float2*)(traj + ((size_t)(b * SS + row0) * FF + f) * CC + col) =
                    make_float2(to_tf32(acc[j][0] * inv0), to_tf32(acc[j][1] * inv0));
                *(float2*)(traj + ((size_t)(b * SS + row0 + 8) * FF + f) * CC + col) =
                    make_float2(to_tf32(acc[j][2] * inv1), to_tf32(acc[j][3] * inv1));
            }
        }
    }
}

// ---------------- frame attention (fused logits) ----------------
__global__ void frame_attn_kernel(const float* __restrict__ w, const float* __restrict__ traj,
                                  float* __restrict__ Y, float* __restrict__ attn_out)
{
    const int bs = blockIdx.x;
    const int b = bs / SS;
    const int s = bs % SS;
    const int tid = threadIdx.x;
    const int h = tid >> 5;      // warp = head
    const int lane = tid & 31;

    __shared__ float ts[FF][CC];
    __shared__ float a_sm[HH][FF];

    for (int idx = tid; idx < FF * CC / 4; idx += 384) {
        int f = idx / 192, j = idx % 192;
        float4 v = *(const float4*)(traj + ((size_t)bs * FF + f) * CC + j * 4);
        *(float4*)&ts[f][j * 4] = v;
    }
    __syncthreads();

    const float* wrow = w + (size_t)bs * W12 + h * CC;
    float wreg[24];
    #pragma unroll
    for (int j = 0; j < 24; j++) wreg[j] = wrow[lane + 32 * j];

    float lg[FF];
    #pragma unroll
    for (int f = 0; f < FF; f++) {
        float dsum = 0.f;
        #pragma unroll
        for (int j = 0; j < 24; j++) dsum += wreg[j] * ts[f][lane + 32 * j];
        #pragma unroll
        for (int o = 16; o; o >>= 1) dsum += __shfl_xor_sync(0xffffffffu, dsum, o);
        lg[f] = dsum * SCALE;
    }
    float m = -1e30f;
    #pragma unroll
    for (int f = 0; f < FF; f++) m = fmaxf(m, lg[f]);
    float z = 0.f;
    #pragma unroll
    for (int f = 0; f < FF; f++) { lg[f] = __expf(lg[f] - m); z += lg[f]; }
    float inv = 1.f / z;
    #pragma unroll
    for (int f = 0; f < FF; f++) lg[f] *= inv;

    if (lane < FF) {
        a_sm[h][lane] = lg[lane];
        attn_out[(((size_t)b * HH + h) * SS + s) * FF + lane] = lg[lane];
    }
    __syncthreads();

    #pragma unroll
    for (int rep = 0; rep < 2; rep++) {
        int c = tid + rep * 384;
        int h2 = c >> 6;
        float o = 0.f;
        #pragma unroll
        for (int f = 0; f < FF; f++) o += a_sm[h2][f] * ts[f][c];
        Y[(size_t)(b * NN + 1 + s) * CC + c] = to_tf32(o);
    }
}

// ---------------- launcher ----------------
extern "C" void kernel_launch(void* const* d_in, const int* in_sizes, int n_in,
                              void* d_out, int out_size)
{
    const float* x      = (const float*)d_in[0];
    const float* W_qkv  = (const float*)d_in[1];
    const float* W_pq   = (const float*)d_in[2];
    const float* W_pkv  = (const float*)d_in[3];
    const float* W_proj = (const float*)d_in[4];
    const float* b_proj = (const float*)d_in[5];
    (void)in_sizes; (void)n_in;

    float *qkv, *traj, *q2, *w, *wT, *Y, *rx, *rwq, *rwpq, *rwproj, *clsP;
    cudaGetSymbolAddress((void**)&qkv,    g_qkv);
    cudaGetSymbolAddress((void**)&traj,   g_traj);
    cudaGetSymbolAddress((void**)&q2,     g_q2);
    cudaGetSymbolAddress((void**)&w,      g_w);
    cudaGetSymbolAddress((void**)&wT,     g_wT);
    cudaGetSymbolAddress((void**)&Y,      g_Y);
    cudaGetSymbolAddress((void**)&rx,     g_x);
    cudaGetSymbolAddress((void**)&rwq,    g_wq);
    cudaGetSymbolAddress((void**)&rwpq,   g_wpq);
    cudaGetSymbolAddress((void**)&rwproj, g_wproj);
    cudaGetSymbolAddress((void**)&clsP,   g_clsP);

    float* out_main = (float*)d_out;                                   // (B,N,C)
    float* out_attn = out_main + (size_t)BB * NN * CC;                 // (B,h,S,F)

    static int smem_set = 0;
    if (!smem_set) {
        cudaFuncSetAttribute(space_attn_kernel,
                             cudaFuncAttributeMaxDynamicSharedMemorySize, SPACE_SMEM_BYTES);
        smem_set = 1;
    }

    const int M1 = BB * NN;   // 3138
    const int M2 = BB * SS;   // 3136

    // 0) round inputs to tf32 + transpose W_pkv K-half
    {
        int t4 = (XSZ + WQSZ + 2 * WPSZ) / 4;
        round_inputs_kernel<<<(t4 + 255) / 256, 256>>>(x, W_qkv, W_pq, W_proj,
                                                       rx, rwq, rwpq, rwproj);
        transpose_wpkv_kernel<<<(CC * CC + 255) / 256, 256>>>(W_pkv, wT);
    }
    // 1) qkv = x @ W_qkv (tf32-rounded output)
    {
        dim3 grid(C3 / GBN, (M1 + GBM - 1) / GBM);
        tf32_gemm_kernel<<<grid, 256>>>(rx, rwq, qkv, M1, C3, CC, CC, C3, C3,
                                        nullptr, 0, 1, 0, 0, 0);
    }
    // 2) cls attention (split-softmax, 16 chunks) -> Y row 0 per batch
    {
        dim3 gridA(BB * HH, CLS_CH);
        cls_partial_kernel<<<gridA, 256>>>(qkv, clsP);
        cls_combine_kernel<<<BB * HH, 64>>>(clsP, Y);
    }
    // 3) space attention -> traj (256 threads, 2 blocks/SM — proven config)
    space_attn_kernel<<<BB * HH * (SS / SQT), 256, SPACE_SMEM_BYTES>>>(qkv, traj);
    // 4) q2 = xdiag @ W_pq with fused diagonal gather (tf32-rounded output)
    {
        dim3 grid(CC / GBN, (M2 + GBM - 1) / GBM);
        tf32_gemm_kernel<<<grid, 256>>>(traj, rwpq, q2, M2, CC, CC, CC, CC, CC,
                                        nullptr, 1, 1, 0, 0, 0);
    }
    // 5) w[bs,h,:] = q2[bs,h-block] @ W_pkv_h^T   (batched over z = head)
    {
        dim3 grid(CC / GBN, (M2 + GBM - 1) / GBM, HH);
        tf32_gemm_kernel<<<grid, 256>>>(q2, wT, w, M2, CC, DD, CC, CC, W12,
                                        nullptr, 0, 0, DD, DD * CC, CC);
    }
    // 6) frame attention (fused logits) -> attn output + Y rows 1..S
    frame_attn_kernel<<<BB * SS, 384>>>(w, traj, Y, out_attn);
    // 7) out = Y @ W_proj + b_proj (final, unrounded)
    {
        dim3 grid(CC / GBN, (M1 + GBM - 1) / GBM);
        tf32_gemm_kernel<<<grid, 256>>>(Y, rwproj, out_main, M1, CC, CC, CC, CC, CC,
                                        b_proj, 0, 0, 0, 0, 0);
    }
}

// round 17
// speedup vs baseline: 4.6418x; 1.0071x over previous
#include <cuda_runtime.h>
#include <cuda_bf16.h>
#include <math.h>
#include <stdint.h>

// Problem constants
#define BB 2
#define NN 1569          // tokens incl cls
#define CC 768
#define HH 12
#define DD 64
#define PP 196
#define FF 8
#define SS 1568          // F*P
#define C3 2304          // 3*C
#define W12 9216         // 12*768
#define SCALE 0.125f
#define CLS_CH 16        // cls split-softmax chunks
#define CLS_CHUNK 99     // ceil(NN/CLS_CH)

// ---------------- device scratch (no allocations allowed) ----------------
__device__ float g_qkv[(size_t)BB * NN * C3];          // (B*N, 3C)
__device__ float g_traj[(size_t)BB * SS * FF * CC];    // (B,S,F,C)
__device__ float g_q2[(size_t)BB * SS * CC];           // (B*S, C)
__device__ float g_w[(size_t)BB * SS * W12];           // (B*S, H, C) fused k2 weights
__device__ float g_wT[(size_t)CC * CC];                // W_pkv[:, :CC]^T (tf32)
__device__ float g_Y[(size_t)BB * NN * CC];            // (B*N, C) concat[cls,out]
__device__ float g_x[(size_t)BB * NN * CC];            // tf32-rounded x
__device__ float g_wq[(size_t)CC * C3];                // tf32-rounded W_qkv
__device__ float g_wpq[(size_t)CC * CC];               // tf32-rounded W_pq
__device__ float g_wproj[(size_t)CC * CC];             // tf32-rounded W_proj
__device__ float g_clsP[(size_t)BB * HH * CLS_CH * (DD + 2)];  // cls partials

__device__ __forceinline__ float to_tf32(float x) {
    uint32_t u;
    asm("cvt.rna.tf32.f32 %0, %1;" : "=r"(u) : "f"(x));
    return __uint_as_float(u);
}

__device__ __forceinline__ void mma_tf32(float (&c)[4], const uint32_t (&a)[4], const uint32_t (&b)[2]) {
    asm volatile(
        "mma.sync.aligned.m16n8k8.row.col.f32.tf32.tf32.f32 "
        "{%0,%1,%2,%3}, {%4,%5,%6,%7}, {%8,%9}, {%0,%1,%2,%3};"
        : "+f"(c[0]), "+f"(c[1]), "+f"(c[2]), "+f"(c[3])
        : "r"(a[0]), "r"(a[1]), "r"(a[2]), "r"(a[3]), "r"(b[0]), "r"(b[1]));
}

__device__ __forceinline__ void cp16(uint32_t dst, const void* src) {
    asm volatile("cp.async.cg.shared.global [%0], [%1], 16;" :: "r"(dst), "l"(src));
}
__device__ __forceinline__ void cp16z(uint32_t dst, const void* src, int sz) {
    asm volatile("cp.async.cg.shared.global [%0], [%1], 16, %2;" :: "r"(dst), "l"(src), "r"(sz));
}
#define CP_COMMIT() asm volatile("cp.async.commit_group;")
#define CP_WAIT0()  asm volatile("cp.async.wait_group 0;")

// ---------------- input prep: tf32 rounding + W_pkv K-half transpose -----
#define XSZ  (BB * NN * CC)    // 2409984
#define WQSZ (CC * C3)         // 1769472
#define WPSZ (CC * CC)         // 589824
#define RND_T4 ((XSZ + WQSZ + 2 * WPSZ) / 4)
#define PREP_TOT (RND_T4 + WPSZ)
__global__ void prep_inputs_kernel(const float* __restrict__ x, const float* __restrict__ Wq,
                                   const float* __restrict__ Wpq, const float* __restrict__ Wpr,
                                   const float* __restrict__ W_pkv,
                                   float* __restrict__ rx, float* __restrict__ rwq,
                                   float* __restrict__ rwpq, float* __restrict__ rwpr,
                                   float* __restrict__ wT)
{
    int idx4 = blockIdx.x * 256 + threadIdx.x;
    if (idx4 >= PREP_TOT) return;
    if (idx4 < RND_T4) {
        int i = idx4 * 4;
        const float* s; float* d; int off;
        if (i < XSZ)                    { s = x;   d = rx;   off = i; }
        else if (i < XSZ + WQSZ)        { s = Wq;  d = rwq;  off = i - XSZ; }
        else if (i < XSZ + WQSZ + WPSZ) { s = Wpq; d = rwpq; off = i - XSZ - WQSZ; }
        else                            { s = Wpr; d = rwpr; off = i - XSZ - WQSZ - WPSZ; }
        float4 v = *(const float4*)(s + off);
        v.x = to_tf32(v.x); v.y = to_tf32(v.y); v.z = to_tf32(v.z); v.w = to_tf32(v.w);
        *(float4*)(d + off) = v;
    } else {
        int t = idx4 - RND_T4;          // 0 .. WPSZ-1
        int hd = t / CC, c = t % CC;
        wT[(size_t)hd * CC + c] = to_tf32(W_pkv[(size_t)c * (2 * CC) + hd]);
    }
}

// ---------------- TF32 tensor-core GEMM, cp.async double-buffered ----------
#define GBM 128
#define GBN 128
#define GBK 16
#define A_LD 20
#define B_LD 136

__device__ __forceinline__ size_t a_row_off(int gr, int lda, int gather) {
    if (gather) {
        int s = gr % SS;
        gr = gr * FF + s / PP;
    }
    return (size_t)gr * lda;
}

__global__ void __launch_bounds__(256, 2)
tf32_gemm_kernel(const float* __restrict__ A, const float* __restrict__ B,
                 float* __restrict__ C, int M, int N, int K,
                 int lda, int ldb, int ldc,
                 const float* __restrict__ bias, int gather, int round_out,
                 int zAcol, int zBoff, int zCcol)
{
    __shared__ float As[2][GBM][A_LD];   // row-major
    __shared__ float Bs[2][GBK][B_LD];   // k-major

    const int z = blockIdx.z;
    A += (size_t)z * zAcol;
    B += (size_t)z * zBoff;
    C += (size_t)z * zCcol;

    const int tid  = threadIdx.x;
    const int warp = tid >> 5;
    const int lane = tid & 31;
    const int g = lane >> 2;
    const int q = lane & 3;
    const int warpM = (warp & 3) * 32;
    const int warpN = (warp >> 2) * 64;
    const int by = blockIdx.y * GBM;
    const int bx = blockIdx.x * GBN;

    float acc[2][8][4];
    #pragma unroll
    for (int i = 0; i < 2; i++)
        #pragma unroll
        for (int j = 0; j < 8; j++)
            #pragma unroll
            for (int l = 0; l < 4; l++) acc[i][j][l] = 0.f;

    const int ar = tid & 127;
    const int cg0 = tid >> 7;          // 0 or 1
    const int gr = by + ar;
    const int asz = (gr < M) ? 16 : 0;
    const float* ap = A + a_row_off(gr < M ? gr : M - 1, lda, gather);
    const int br = tid >> 4;
    const int bc = (tid & 15) << 2;
    const float* bp = B + (size_t)br * ldb + bx + bc;

    uint32_t sA = (uint32_t)__cvta_generic_to_shared(&As[0][ar][0]);
    uint32_t sB = (uint32_t)__cvta_generic_to_shared(&Bs[0][br][bc]);
    const uint32_t stA = sizeof(float) * GBM * A_LD;
    const uint32_t stB = sizeof(float) * GBK * B_LD;

    cp16z(sA + (cg0 * 4) * 4, ap + cg0 * 4, asz);
    cp16z(sA + ((cg0 + 2) * 4) * 4, ap + (cg0 + 2) * 4, asz);
    cp16(sB, bp);
    cp16(sB + 64 * 4, bp + 64);
    CP_COMMIT();

    int cur = 0;
    for (int k0 = 0; k0 < K; k0 += GBK) {
        CP_WAIT0();
        __syncthreads();
        if (k0 + GBK < K) {
            uint32_t oA = (cur ^ 1) * stA, oB = (cur ^ 1) * stB;
            cp16z(sA + oA + (cg0 * 4) * 4, ap + k0 + GBK + cg0 * 4, asz);
            cp16z(sA + oA + ((cg0 + 2) * 4) * 4, ap + k0 + GBK + (cg0 + 2) * 4, asz);
            cp16(sB + oB, bp + (size_t)(k0 + GBK) * ldb);
            cp16(sB + oB + 64 * 4, bp + (size_t)(k0 + GBK) * ldb + 64);
            CP_COMMIT();
        }

        #pragma unroll
        for (int kk = 0; kk < GBK; kk += 8) {
            uint32_t afr[2][4];
            #pragma unroll
            for (int mt = 0; mt < 2; mt++) {
                int r = warpM + mt * 16 + g;
                afr[mt][0] = __float_as_uint(As[cur][r][kk + q]);
                afr[mt][1] = __float_as_uint(As[cur][r + 8][kk + q]);
                afr[mt][2] = __float_as_uint(As[cur][r][kk + q + 4]);
                afr[mt][3] = __float_as_uint(As[cur][r + 8][kk + q + 4]);
            }
            uint32_t bfr[8][2];
            #pragma unroll
            for (int nt = 0; nt < 8; nt++) {
                int c = warpN + nt * 8 + g;
                bfr[nt][0] = __float_as_uint(Bs[cur][kk + q][c]);
                bfr[nt][1] = __float_as_uint(Bs[cur][kk + q + 4][c]);
            }
            #pragma unroll
            for (int mt = 0; mt < 2; mt++)
                #pragma unroll
                for (int nt = 0; nt < 8; nt++)
                    mma_tf32(acc[mt][nt], afr[mt], bfr[nt]);
        }
        cur ^= 1;
    }

    #pragma unroll
    for (int mt = 0; mt < 2; mt++) {
        #pragma unroll
        for (int nt = 0; nt < 8; nt++) {
            int col = bx + warpN + nt * 8 + 2 * q;
            float bx0 = 0.f, bx1 = 0.f;
            if (bias) { bx0 = bias[col]; bx1 = bias[col + 1]; }
            int r0 = by + warpM + mt * 16 + g;
            float v0 = acc[mt][nt][0] + bx0, v1 = acc[mt][nt][1] + bx1;
            float v2 = acc[mt][nt][2] + bx0, v3 = acc[mt][nt][3] + bx1;
            if (round_out) {
                v0 = to_tf32(v0); v1 = to_tf32(v1); v2 = to_tf32(v2); v3 = to_tf32(v3);
            }
            if (r0 < M)     *(float2*)(C + (size_t)r0 * ldc + col) = make_float2(v0, v1);
            if (r0 + 8 < M) *(float2*)(C + (size_t)(r0 + 8) * ldc + col) = make_float2(v2, v3);
        }
    }
}

// ---------------- cls attention phase A: split-softmax partials ----------
// grid (BB*HH, CLS_CH), 256 threads. Scalar shared stores only.
__global__ void cls_partial_kernel(const float* __restrict__ qkv, float* __restrict__ P)
{
    const int bh = blockIdx.x;
    const int c  = blockIdx.y;
    const int b = bh / HH;
    const int h = bh % HH;
    const int base = c * CLS_CHUNK;
    const int count = min(CLS_CHUNK, NN - base);
    const int tid = threadIdx.x;

    __shared__ float qs[DD];
    __shared__ float sc[CLS_CHUNK];
    __shared__ float red[256];
    __shared__ float part16[16][DD];

    if (tid < DD) qs[tid] = qkv[(size_t)(b * NN) * C3 + h * DD + tid];
    __syncthreads();

    float s = -1e30f;
    if (tid < count) {
        const float* kr = qkv + (size_t)(b * NN + base + tid) * C3 + CC + h * DD;
        float dot = 0.f;
        #pragma unroll
        for (int d = 0; d < DD; d += 4) {
            float4 k4 = *(const float4*)(kr + d);
            dot += qs[d] * k4.x + qs[d + 1] * k4.y + qs[d + 2] * k4.z + qs[d + 3] * k4.w;
        }
        s = dot * SCALE;
        sc[tid] = s;
    }
    red[tid] = s; __syncthreads();
    for (int o = 128; o; o >>= 1) { if (tid < o) red[tid] = fmaxf(red[tid], red[tid + o]); __syncthreads(); }
    const float m = red[0];
    __syncthreads();

    float e = 0.f;
    if (tid < count) { e = __expf(sc[tid] - m); sc[tid] = e; }
    red[tid] = e; __syncthreads();
    for (int o = 128; o; o >>= 1) { if (tid < o) red[tid] += red[tid + o]; __syncthreads(); }
    const float z = red[0];
    __syncthreads();

    const int part = tid >> 4;           // 0..15
    const int d4 = (tid & 15) << 2;      // 0,4,..,60
    float4 facc = make_float4(0.f, 0.f, 0.f, 0.f);
    for (int i = part; i < count; i += 16) {
        float4 v = *(const float4*)(qkv + (size_t)(b * NN + base + i) * C3 + 2 * CC + h * DD + d4);
        float sv = sc[i];
        facc.x += sv * v.x; facc.y += sv * v.y; facc.z += sv * v.z; facc.w += sv * v.w;
    }
    part16[part][d4 + 0] = facc.x;
    part16[part][d4 + 1] = facc.y;
    part16[part][d4 + 2] = facc.z;
    part16[part][d4 + 3] = facc.w;
    __syncthreads();

    float* out = P + (size_t)(bh * CLS_CH + c) * (DD + 2);
    if (tid < DD) {
        float a = 0.f;
        #pragma unroll
        for (int p = 0; p < 16; p++) a += part16[p][tid];
        out[tid] = a;
    }
    if (tid == DD)     out[DD] = m;
    if (tid == DD + 1) out[DD + 1] = z;
}

// ---------------- cls attention phase B: combine -> Y row 0 -------------
__global__ void cls_combine_kernel(const float* __restrict__ P, float* __restrict__ Y)
{
    const int bh = blockIdx.x;
    const int b = bh / HH;
    const int h = bh % HH;
    const int tid = threadIdx.x;   // 0..63

    const float* base = P + (size_t)bh * CLS_CH * (DD + 2);
    float m = -1e30f;
    #pragma unroll
    for (int c = 0; c < CLS_CH; c++) m = fmaxf(m, base[c * (DD + 2) + DD]);
    float z = 0.f, acc = 0.f;
    #pragma unroll
    for (int c = 0; c < CLS_CH; c++) {
        float sc = __expf(base[c * (DD + 2) + DD] - m);
        z += base[c * (DD + 2) + DD + 1] * sc;
        acc += base[c * (DD + 2) + tid] * sc;
    }
    Y[(size_t)(b * NN) * CC + h * DD + tid] = to_tf32(acc / z);
}

// ---------------- tensor-core space attention -> traj -------------------
// SQT=32 queries/block, 256 threads, grid = B*H*49, ~107KB smem -> 2 blocks/SM.
// 2-pass softmax; P stored unnormalized tf32, 1/z fused into PV epilogue.
#define SQT 32
#define BUF_LD 76
#define SC_LD 40
#define QT_LD 40
#define BUF_OFF 0
#define SC_OFF (208 * BUF_LD)                     // 15808
#define QT_OFF (SC_OFF + 208 * SC_LD)             // 24128
#define SPACE_SMEM_FLOATS (QT_OFF + 64 * QT_LD)   // 26688
#define SPACE_SMEM_BYTES (SPACE_SMEM_FLOATS * 4)  // 106752
#define INV_ROW 200

__global__ void space_attn_kernel(const float* __restrict__ qkv, float* __restrict__ traj)
{
    extern __shared__ float smem[];
    float* Buf = smem + BUF_OFF;  // [208][76] K then V, natural [n][d]
    float* Sc  = smem + SC_OFF;   // [208][40] scores^T [n][q]; row 200 = inv
    float* Qt  = smem + QT_OFF;   // [64][40]  Q^T [d][q]
    const uint32_t sBuf = (uint32_t)__cvta_generic_to_shared(Buf);

    const int nt_blocks = SS / SQT;    // 49
    const int bh = blockIdx.x / nt_blocks;
    const int st = blockIdx.x % nt_blocks;
    const int b = bh / HH;
    const int h = bh % HH;
    const int s0 = st * SQT;
    const int tid = threadIdx.x;
    const int warp = tid >> 5;
    const int lane = tid & 31;
    const int g = lane >> 2;
    const int q = lane & 3;

    for (int idx = tid; idx < SQT * 16; idx += 256) {
        int row = idx >> 4, d4 = (idx & 15) << 2;
        float4 qv = *(const float4*)(qkv + (size_t)(b * NN + 1 + s0 + row) * C3 + h * DD + d4);
        Qt[(d4 + 0) * QT_LD + row] = qv.x;
        Qt[(d4 + 1) * QT_LD + row] = qv.y;
        Qt[(d4 + 2) * QT_LD + row] = qv.z;
        Qt[(d4 + 3) * QT_LD + row] = qv.w;
    }
    {
        int n = 196 + (tid >> 6), d = tid & 63;
        Buf[n * BUF_LD + d] = 0.f;
    }

    for (int f = 0; f < FF; f++) {
        __syncthreads();

        const size_t frameRow = (size_t)(b * NN + 1 + f * PP);
        for (int idx = tid; idx < PP * 16; idx += 256) {
            int n = idx >> 4, d4 = (idx & 15) << 2;
            cp16(sBuf + (uint32_t)(n * BUF_LD + d4) * 4u,
                 qkv + (frameRow + n) * C3 + CC + h * DD + d4);
        }
        CP_COMMIT();
        CP_WAIT0();
        __syncthreads();

        // ---- QK: warp handles m-tiles {warp, warp+8}; b-frags hoisted ----
        {
            const int mt0 = warp;
            const int mt1 = warp + 8;
            const int m0 = mt0 * 16;
            const int m1 = mt1 * 16;
            const bool has1 = (mt1 < 13);
            float acc0[4][4], acc1[4][4];
            #pragma unroll
            for (int i = 0; i < 4; i++)
                #pragma unroll
                for (int j = 0; j < 4; j++) { acc0[i][j] = 0.f; acc1[i][j] = 0.f; }
            #pragma unroll
            for (int kb = 0; kb < 8; kb++) {
                const int k0 = kb * 8;
                uint32_t bfr[4][2];
                #pragma unroll
                for (int nt = 0; nt < 4; nt++) {
                    bfr[nt][0] = __float_as_uint(Qt[(k0 + q) * QT_LD + nt * 8 + g]);
                    bfr[nt][1] = __float_as_uint(Qt[(k0 + q + 4) * QT_LD + nt * 8 + g]);
                }
                uint32_t a[4];
                a[0] = __float_as_uint(Buf[(m0 + g) * BUF_LD + k0 + q]);
                a[1] = __float_as_uint(Buf[(m0 + 8 + g) * BUF_LD + k0 + q]);
                a[2] = __float_as_uint(Buf[(m0 + g) * BUF_LD + k0 + q + 4]);
                a[3] = __float_as_uint(Buf[(m0 + 8 + g) * BUF_LD + k0 + q + 4]);
                #pragma unroll
                for (int nt = 0; nt < 4; nt++) mma_tf32(acc0[nt], a, bfr[nt]);
                if (has1) {
                    uint32_t a1[4];
                    a1[0] = __float_as_uint(Buf[(m1 + g) * BUF_LD + k0 + q]);
                    a1[1] = __float_as_uint(Buf[(m1 + 8 + g) * BUF_LD + k0 + q]);
                    a1[2] = __float_as_uint(Buf[(m1 + g) * BUF_LD + k0 + q + 4]);
                    a1[3] = __float_as_uint(Buf[(m1 + 8 + g) * BUF_LD + k0 + q + 4]);
                    #pragma unroll
                    for (int nt = 0; nt < 4; nt++) mma_tf32(acc1[nt], a1, bfr[nt]);
                }
            }
            #pragma unroll
            for (int nt = 0; nt < 4; nt++) {
                int c0 = nt * 8 + 2 * q;
                *(float2*)&Sc[(m0 + g) * SC_LD + c0] =
                    make_float2(acc0[nt][0] * SCALE, acc0[nt][1] * SCALE);
                *(float2*)&Sc[(m0 + 8 + g) * SC_LD + c0] =
                    make_float2(acc0[nt][2] * SCALE, acc0[nt][3] * SCALE);
            }
            if (has1) {
                #pragma unroll
                for (int nt = 0; nt < 4; nt++) {
                    int c0 = nt * 8 + 2 * q;
                    *(float2*)&Sc[(m1 + g) * SC_LD + c0] =
                        make_float2(acc1[nt][0] * SCALE, acc1[nt][1] * SCALE);
                    *(float2*)&Sc[(m1 + 8 + g) * SC_LD + c0] =
                        make_float2(acc1[nt][2] * SCALE, acc1[nt][3] * SCALE);
                }
            }
        }
        __syncthreads();

        // ---- V via cp.async (overlaps softmax) ----
        for (int idx = tid; idx < PP * 16; idx += 256) {
            int n = idx >> 4, d4 = (idx & 15) << 2;
            cp16(sBuf + (uint32_t)(n * BUF_LD + d4) * 4u,
                 qkv + (frameRow + n) * C3 + 2 * CC + h * DD + d4);
        }
        CP_COMMIT();

        // ---- 2-pass softmax: writes tf32 exp values; inv in row 200 ----
        {
            const int col = tid >> 3, r = tid & 7;
            float m = -1e30f;
            for (int n = r; n < PP; n += 8) m = fmaxf(m, Sc[n * SC_LD + col]);
            #pragma unroll
            for (int o = 4; o; o >>= 1) m = fmaxf(m, __shfl_xor_sync(0xffffffffu, m, o));
            float z = 0.f;
            for (int n = r; n < PP; n += 8) {
                float e = to_tf32(__expf(Sc[n * SC_LD + col] - m));
                Sc[n * SC_LD + col] = e;
                z += e;
            }
            #pragma unroll
            for (int o = 4; o; o >>= 1) z += __shfl_xor_sync(0xffffffffu, z, o);
            if (r == 0) Sc[INV_ROW * SC_LD + col] = 1.f / z;
        }
        CP_WAIT0();
        __syncthreads();

        // ---- PV: 4 warps, 1 m-tile x 4 d-tiles; scale by inv at epilogue ----
        if (warp < 4) {
            const int mt = warp & 1;
            const int dgrp = warp >> 1;
            const int m0 = mt * 16;
            float acc[4][4];
            #pragma unroll
            for (int j = 0; j < 4; j++)
                #pragma unroll
                for (int l = 0; l < 4; l++) acc[j][l] = 0.f;
            for (int kb = 0; kb < 25; kb++) {
                const int k0 = kb * 8;
                uint32_t a[4];
                a[0] = __float_as_uint(Sc[(k0 + q) * SC_LD + m0 + g]);
                a[1] = __float_as_uint(Sc[(k0 + q) * SC_LD + m0 + 8 + g]);
                a[2] = __float_as_uint(Sc[(k0 + q + 4) * SC_LD + m0 + g]);
                a[3] = __float_as_uint(Sc[(k0 + q + 4) * SC_LD + m0 + 8 + g]);
                #pragma unroll
                for (int j = 0; j < 4; j++) {
                    const int d0 = dgrp * 32 + j * 8;
                    uint32_t bfr[2];
                    bfr[0] = __float_as_uint(Buf[(k0 + q) * BUF_LD + d0 + g]);
                    bfr[1] = __float_as_uint(Buf[(k0 + q + 4) * BUF_LD + d0 + g]);
                    mma_tf32(acc[j], a, bfr);
                }
            }
            const float inv0 = Sc[INV_ROW * SC_LD + m0 + g];
            const float inv1 = Sc[INV_ROW * SC_LD + m0 + 8 + g];
            #pragma unroll
            for (int j = 0; j < 4; j++) {
                const int d0 = dgrp * 32 + j * 8;
                const int col = h * DD + d0 + 2 * q;
                const int row0 = s0 + m0 + g;
                *(float2*)(traj + ((size_t)(b * SS + row0) * FF + f) * CC + col) =
                    make_float2(to_tf32(acc[j][0] * inv0), to_tf32(acc[j][1] * inv0));
                *(float2*)(traj + ((size_t)(b * SS + row0 + 8) * FF + f) * CC + col) =
                    make_float2(to_tf32(acc[j][2] * inv1), to_tf32(acc[j][3] * inv1));
            }
        }
    }
}

// ---------------- frame attention (fused logits) ----------------
__global__ void frame_attn_kernel(const float* __restrict__ w, const float* __restrict__ traj,
                                  float* __restrict__ Y, float* __restrict__ attn_out)
{
    const int bs = blockIdx.x;
    const int b = bs / SS;
    const int s = bs % SS;
    const int tid = threadIdx.x;
    const int h = tid >> 5;      // warp = head
    const int lane = tid & 31;

    __shared__ float ts[FF][CC];
    __shared__ float a_sm[HH][FF];

    for (int idx = tid; idx < FF * CC / 4; idx += 384) {
        int f = idx / 192, j = idx % 192;
        float4 v = *(const float4*)(traj + ((size_t)bs * FF + f) * CC + j * 4);
        *(float4*)&ts[f][j * 4] = v;
    }
    __syncthreads();

    const float* wrow = w + (size_t)bs * W12 + h * CC;
    float wreg[24];
    #pragma unroll
    for (int j = 0; j < 24; j++) wreg[j] = wrow[lane + 32 * j];

    float lg[FF];
    #pragma unroll
    for (int f = 0; f < FF; f++) {
        float dsum = 0.f;
        #pragma unroll
        for (int j = 0; j < 24; j++) dsum += wreg[j] * ts[f][lane + 32 * j];
        #pragma unroll
        for (int o = 16; o; o >>= 1) dsum += __shfl_xor_sync(0xffffffffu, dsum, o);
        lg[f] = dsum * SCALE;
    }
    float m = -1e30f;
    #pragma unroll
    for (int f = 0; f < FF; f++) m = fmaxf(m, lg[f]);
    float z = 0.f;
    #pragma unroll
    for (int f = 0; f < FF; f++) { lg[f] = __expf(lg[f] - m); z += lg[f]; }
    float inv = 1.f / z;
    #pragma unroll
    for (int f = 0; f < FF; f++) lg[f] *= inv;

    if (lane < FF) {
        a_sm[h][lane] = lg[lane];
        attn_out[(((size_t)b * HH + h) * SS + s) * FF + lane] = lg[lane];
    }
    __syncthreads();

    #pragma unroll
    for (int rep = 0; rep < 2; rep++) {
        int c = tid + rep * 384;
        int h2 = c >> 6;
        float o = 0.f;
        #pragma unroll
        for (int f = 0; f < FF; f++) o += a_sm[h2][f] * ts[f][c];
        Y[(size_t)(b * NN + 1 + s) * CC + c] = to_tf32(o);
    }
}

// ---------------- launcher ----------------
extern "C" void kernel_launch(void* const* d_in, const int* in_sizes, int n_in,
                              void* d_out, int out_size)
{
    const float* x      = (const float*)d_in[0];
    const float* W_qkv  = (const float*)d_in[1];
    const float* W_pq   = (const float*)d_in[2];
    const float* W_pkv  = (const float*)d_in[3];
    const float* W_proj = (const float*)d_in[4];
    const float* b_proj = (const float*)d_in[5];
    (void)in_sizes; (void)n_in;

    float *qkv, *traj, *q2, *w, *wT, *Y, *rx, *rwq, *rwpq, *rwproj, *clsP;
    cudaGetSymbolAddress((void**)&qkv,    g_qkv);
    cudaGetSymbolAddress((void**)&traj,   g_traj);
    cudaGetSymbolAddress((void**)&q2,     g_q2);
    cudaGetSymbolAddress((void**)&w,      g_w);
    cudaGetSymbolAddress((void**)&wT,     g_wT);
    cudaGetSymbolAddress((void**)&Y,      g_Y);
    cudaGetSymbolAddress((void**)&rx,     g_x);
    cudaGetSymbolAddress((void**)&rwq,    g_wq);
    cudaGetSymbolAddress((void**)&rwpq,   g_wpq);
    cudaGetSymbolAddress((void**)&rwproj, g_wproj);
    cudaGetSymbolAddress((void**)&clsP,   g_clsP);

    float* out_main = (float*)d_out;                                   // (B,N,C)
    float* out_attn = out_main + (size_t)BB * NN * CC;                 // (B,h,S,F)

    static int smem_set = 0;
    if (!smem_set) {
        cudaFuncSetAttribute(space_attn_kernel,
                             cudaFuncAttributeMaxDynamicSharedMemorySize, SPACE_SMEM_BYTES);
        smem_set = 1;
    }

    const int M1 = BB * NN;   // 3138
    const int M2 = BB * SS;   // 3136

    // 0) prep: tf32 rounding + W_pkv K-half transpose (single kernel)
    prep_inputs_kernel<<<(PREP_TOT + 255) / 256, 256>>>(x, W_qkv, W_pq, W_proj, W_pkv,
                                                        rx, rwq, rwpq, rwproj, wT);
    // 1) qkv = x @ W_qkv (tf32-rounded output)
    {
        dim3 grid(C3 / GBN, (M1 + GBM - 1) / GBM);
        tf32_gemm_kernel<<<grid, 256>>>(rx, rwq, qkv, M1, C3, CC, CC, C3, C3,
                                        nullptr, 0, 1, 0, 0, 0);
    }
    // 2) cls attention (split-softmax, 16 chunks) -> Y row 0 per batch
    {
        dim3 gridA(BB * HH, CLS_CH);
        cls_partial_kernel<<<gridA, 256>>>(qkv, clsP);
        cls_combine_kernel<<<BB * HH, 64>>>(clsP, Y);
    }
    // 3) space attention -> traj (256 threads, 2 blocks/SM — proven config)
    space_attn_kernel<<<BB * HH * (SS / SQT), 256, SPACE_SMEM_BYTES>>>(qkv, traj);
    // 4) q2 = xdiag @ W_pq with fused diagonal gather (tf32-rounded output)
    {
        dim3 grid(CC / GBN, (M2 + GBM - 1) / GBM);
        tf32_gemm_kernel<<<grid, 256>>>(traj, rwpq, q2, M2, CC, CC, CC, CC, CC,
                                        nullptr, 1, 1, 0, 0, 0);
    }
    // 5) w[bs,h,:] = q2[bs,h-block] @ W_pkv_h^T   (batched over z = head)
    {
        dim3 grid(CC / GBN, (M2 + GBM - 1) / GBM, HH);
        tf32_gemm_kernel<<<grid, 256>>>(q2, wT, w, M2, CC, DD, CC, CC, W12,
                                        nullptr, 0, 0, DD, DD * CC, CC);
    }
    // 6) frame attention (fused logits) -> attn output + Y rows 1..S
    frame_attn_kernel<<<BB * SS, 384>>>(w, traj, Y, out_attn);
    // 7) out = Y @ W_proj + b_proj (final, unrounded)
    {
        dim3 grid(CC / GBN, (M1 + GBM - 1) / GBM);
        tf32_gemm_kernel<<<grid, 256>>>(Y, rwproj, out_main, M1, CC, CC, CC, CC, CC,
                                        b_proj, 0, 0, 0, 0, 0);
    }
}